// round 1
// baseline (speedup 1.0000x reference)
#include <cuda_runtime.h>
#include <math.h>

#define BB 4
#define TT 2048
#define CC 1024
#define HH 16
#define HD 64
#define BT (BB*TT)
#define C3 (3*CC)

// Scratch (device globals: allocation-guard safe)
__device__ float g_q[BB*HH*TT*HD];
__device__ float g_k[BB*HH*TT*HD];
__device__ float g_v[BB*HH*TT*HD];
__device__ float g_y[BT*CC];

// ---------------- SGEMM tiles ----------------
#define BM 128
#define BN 128
#define BK 8
#define TM 8
#define TN 8

// QKV GEMM: A[BT,CC] @ W[CC,C3] + bias, scatter to q/k/v in [B,H,T,hd]
__global__ __launch_bounds__(256) void qkv_kernel(const float* __restrict__ A,
                                                  const float* __restrict__ W,
                                                  const float* __restrict__ bias) {
    __shared__ float As[BK][BM];
    __shared__ float Bs[BK][BN];
    int tid = threadIdx.x;
    int bn0 = blockIdx.x * BN;
    int bm0 = blockIdx.y * BM;
    int tx = tid & 15, ty = tid >> 4;
    float acc[TM][TN] = {};
    int arow = tid >> 1;
    int acol = (tid & 1) * 4;
    int brow = tid >> 5;
    int bcol = (tid & 31) * 4;
    for (int k0 = 0; k0 < CC; k0 += BK) {
        float4 a4 = *(const float4*)&A[(size_t)(bm0 + arow) * CC + k0 + acol];
        As[acol + 0][arow] = a4.x;
        As[acol + 1][arow] = a4.y;
        As[acol + 2][arow] = a4.z;
        As[acol + 3][arow] = a4.w;
        *(float4*)&Bs[brow][bcol] =
            *(const float4*)&W[(size_t)(k0 + brow) * C3 + bn0 + bcol];
        __syncthreads();
#pragma unroll
        for (int k = 0; k < BK; k++) {
            float ra[TM], rb[TN];
#pragma unroll
            for (int i = 0; i < TM; i++) ra[i] = As[k][ty * TM + i];
#pragma unroll
            for (int j = 0; j < TN; j++) rb[j] = Bs[k][tx * TN + j];
#pragma unroll
            for (int i = 0; i < TM; i++)
#pragma unroll
                for (int j = 0; j < TN; j++) acc[i][j] += ra[i] * rb[j];
        }
        __syncthreads();
    }
    // Epilogue: bias + scatter into head-major layout. The 8-col span per
    // thread stays inside one head (8 | 64) and one of q/k/v (128 | 1024).
    int n0 = bn0 + tx * TN;
    int which = n0 / CC;
    int nl0 = n0 % CC;
    int h = nl0 / HD;
    int d0 = nl0 % HD;
    float* dst = (which == 0) ? g_q : ((which == 1) ? g_k : g_v);
    float bv[TN];
#pragma unroll
    for (int j = 0; j < TN; j++) bv[j] = bias[n0 + j];
#pragma unroll
    for (int i = 0; i < TM; i++) {
        int m = bm0 + ty * TM + i;
        int b_ = m / TT, t = m % TT;
        float* drow = &dst[(((size_t)(b_ * HH + h)) * TT + t) * HD + d0];
        float4 v0 = make_float4(acc[i][0] + bv[0], acc[i][1] + bv[1],
                                acc[i][2] + bv[2], acc[i][3] + bv[3]);
        float4 v1 = make_float4(acc[i][4] + bv[4], acc[i][5] + bv[5],
                                acc[i][6] + bv[6], acc[i][7] + bv[7]);
        *(float4*)&drow[0] = v0;
        *(float4*)&drow[4] = v1;
    }
}

// Proj GEMM: g_y[BT,CC] @ W[CC,CC] + bias -> out
__global__ __launch_bounds__(256) void proj_kernel(const float* __restrict__ W,
                                                   const float* __restrict__ bias,
                                                   float* __restrict__ out) {
    __shared__ float As[BK][BM];
    __shared__ float Bs[BK][BN];
    const float* A = g_y;
    int tid = threadIdx.x;
    int bn0 = blockIdx.x * BN;
    int bm0 = blockIdx.y * BM;
    int tx = tid & 15, ty = tid >> 4;
    float acc[TM][TN] = {};
    int arow = tid >> 1;
    int acol = (tid & 1) * 4;
    int brow = tid >> 5;
    int bcol = (tid & 31) * 4;
    for (int k0 = 0; k0 < CC; k0 += BK) {
        float4 a4 = *(const float4*)&A[(size_t)(bm0 + arow) * CC + k0 + acol];
        As[acol + 0][arow] = a4.x;
        As[acol + 1][arow] = a4.y;
        As[acol + 2][arow] = a4.z;
        As[acol + 3][arow] = a4.w;
        *(float4*)&Bs[brow][bcol] =
            *(const float4*)&W[(size_t)(k0 + brow) * CC + bn0 + bcol];
        __syncthreads();
#pragma unroll
        for (int k = 0; k < BK; k++) {
            float ra[TM], rb[TN];
#pragma unroll
            for (int i = 0; i < TM; i++) ra[i] = As[k][ty * TM + i];
#pragma unroll
            for (int j = 0; j < TN; j++) rb[j] = Bs[k][tx * TN + j];
#pragma unroll
            for (int i = 0; i < TM; i++)
#pragma unroll
                for (int j = 0; j < TN; j++) acc[i][j] += ra[i] * rb[j];
        }
        __syncthreads();
    }
    int n0 = bn0 + tx * TN;
    float bv[TN];
#pragma unroll
    for (int j = 0; j < TN; j++) bv[j] = bias[n0 + j];
#pragma unroll
    for (int i = 0; i < TM; i++) {
        int m = bm0 + ty * TM + i;
        float4 v0 = make_float4(acc[i][0] + bv[0], acc[i][1] + bv[1],
                                acc[i][2] + bv[2], acc[i][3] + bv[3]);
        float4 v1 = make_float4(acc[i][4] + bv[4], acc[i][5] + bv[5],
                                acc[i][6] + bv[6], acc[i][7] + bv[7]);
        *(float4*)&out[(size_t)m * CC + n0] = v0;
        *(float4*)&out[(size_t)m * CC + n0 + 4] = v1;
    }
}

// ---------------- Flash-style attention ----------------
// One thread = one query row. q (16 x float4) and o (16 x float4) in regs.
// K/V tiles of 32 keys staged in smem; all lanes read the same smem address
// during the dot products -> broadcast LDS.128, 4 FFMA per load.
#define KTILE 32
#define QROWS 128

__global__ __launch_bounds__(QROWS) void attn_kernel() {
    __shared__ float4 Ks[KTILE][HD / 4];
    __shared__ float4 Vs[KTILE][HD / 4];
    int bh = blockIdx.y;                      // b*H + h
    int tid = threadIdx.x;
    int row = blockIdx.x * QROWS + tid;       // query index t
    const float* qb = g_q + (size_t)bh * TT * HD;
    const float* kb = g_k + (size_t)bh * TT * HD;
    const float* vb = g_v + (size_t)bh * TT * HD;

    const float scale = 0.125f;               // 1/sqrt(64)
    float4 q[HD / 4];
#pragma unroll
    for (int i = 0; i < HD / 4; i++) {
        float4 t4 = *(const float4*)&qb[(size_t)row * HD + i * 4];
        q[i] = make_float4(t4.x * scale, t4.y * scale, t4.z * scale, t4.w * scale);
    }
    float4 o[HD / 4];
#pragma unroll
    for (int i = 0; i < HD / 4; i++) o[i] = make_float4(0.f, 0.f, 0.f, 0.f);
    float m = -1e30f, l = 0.f;

    for (int kt = 0; kt < TT; kt += KTILE) {
        __syncthreads();  // previous tile fully consumed
#pragma unroll
        for (int i = 0; i < (KTILE * HD / 4) / QROWS; i++) {
            int idx = i * QROWS + tid;  // 0..511, flat float4 index
            ((float4*)Ks)[idx] = *(const float4*)&kb[(size_t)kt * HD + idx * 4];
            ((float4*)Vs)[idx] = *(const float4*)&vb[(size_t)kt * HD + idx * 4];
        }
        __syncthreads();

        float s[KTILE];
#pragma unroll
        for (int j = 0; j < KTILE; j++) {
            float sj = 0.f;
#pragma unroll
            for (int i = 0; i < HD / 4; i++) {
                float4 kk = Ks[j][i];
                sj += q[i].x * kk.x + q[i].y * kk.y + q[i].z * kk.z + q[i].w * kk.w;
            }
            s[j] = sj;
        }
        float tmax = m;
#pragma unroll
        for (int j = 0; j < KTILE; j++) tmax = fmaxf(tmax, s[j]);
        float corr = __expf(m - tmax);
        m = tmax;
        l *= corr;
#pragma unroll
        for (int i = 0; i < HD / 4; i++) {
            o[i].x *= corr; o[i].y *= corr; o[i].z *= corr; o[i].w *= corr;
        }
#pragma unroll
        for (int j = 0; j < KTILE; j++) {
            float p = __expf(s[j] - m);
            l += p;
#pragma unroll
            for (int i = 0; i < HD / 4; i++) {
                float4 vv = Vs[j][i];
                o[i].x += p * vv.x; o[i].y += p * vv.y;
                o[i].z += p * vv.z; o[i].w += p * vv.w;
            }
        }
    }
    float inv = 1.f / l;
    int b_ = bh / HH, h = bh % HH;
    float* yrow = g_y + ((size_t)(b_ * TT + row)) * CC + h * HD;
#pragma unroll
    for (int i = 0; i < HD / 4; i++) {
        float4 r4 = make_float4(o[i].x * inv, o[i].y * inv, o[i].z * inv, o[i].w * inv);
        *(float4*)&yrow[i * 4] = r4;
    }
}

extern "C" void kernel_launch(void* const* d_in, const int* in_sizes, int n_in,
                              void* d_out, int out_size) {
    const float* seq    = (const float*)d_in[0];
    const float* w_attn = (const float*)d_in[1];
    const float* b_attn = (const float*)d_in[2];
    const float* w_proj = (const float*)d_in[3];
    const float* b_proj = (const float*)d_in[4];
    float* out = (float*)d_out;

    dim3 g1(C3 / BN, BT / BM);          // 24 x 64
    qkv_kernel<<<g1, 256>>>(seq, w_attn, b_attn);

    dim3 g2(TT / QROWS, BB * HH);       // 16 x 64
    attn_kernel<<<g2, QROWS>>>();

    dim3 g3(CC / BN, BT / BM);          // 8 x 64
    proj_kernel<<<g3, 256>>>(w_proj, b_proj, out);
}

// round 2
// speedup vs baseline: 1.3447x; 1.3447x over previous
#include <cuda_runtime.h>
#include <math.h>

#define BB 4
#define TT 2048
#define CC 1024
#define HH 16
#define HD 64
#define BT (BB*TT)
#define C3 (3*CC)

// Scratch (device globals: allocation-guard safe)
__device__ float g_q[BB*HH*TT*HD];
__device__ float g_k[BB*HH*TT*HD];
__device__ float g_v[BB*HH*TT*HD];
__device__ float g_y[BT*CC];

// ---------------- tf32 tensor-core GEMM ----------------
// Block tile 128x128, k-stage 16. 8 warps = 4(M) x 2(N); warp tile 32x64.
// mma.sync m16n8k8 tf32, fp32 accumulate.
#define GBM 128
#define GBN 128
#define GBK 16
#define AS_STRIDE 20    // 128 rows x 20 (16 + 4 pad) -> conflict-free frag loads
#define BS_STRIDE 136   // 16 rows x 136 (128 + 8 pad) -> conflict-free frag loads

__device__ __forceinline__ unsigned f2tf32(float x) {
    unsigned r;
    asm("cvt.rna.tf32.f32 %0, %1;" : "=r"(r) : "f"(x));
    return r;
}

__device__ __forceinline__ void mma_tf32(float* c, const unsigned* a, const unsigned* b) {
    asm volatile(
        "mma.sync.aligned.m16n8k8.row.col.f32.tf32.tf32.f32 "
        "{%0,%1,%2,%3}, {%4,%5,%6,%7}, {%8,%9}, {%0,%1,%2,%3};"
        : "+f"(c[0]), "+f"(c[1]), "+f"(c[2]), "+f"(c[3])
        : "r"(a[0]), "r"(a[1]), "r"(a[2]), "r"(a[3]), "r"(b[0]), "r"(b[1]));
}

// Computes the 128x128 block tile of A[MT x K] @ W[K x N] into acc.
// A row-major (lda = K), W row-major (ldw = N). K = CC = 1024.
__device__ __forceinline__ void gemm_tile_tf32(
    const float* __restrict__ A, int lda,
    const float* __restrict__ W, int ldw,
    int bm0, int bn0,
    unsigned* Asu, unsigned* Bsu,
    float acc[2][8][4])
{
    int tid = threadIdx.x;
    int wid = tid >> 5, lane = tid & 31;
    int wm = wid & 3, wn = wid >> 2;          // 4 x 2 warp grid
    int g = lane >> 2, tig = lane & 3;

    for (int k0 = 0; k0 < CC; k0 += GBK) {
        // ---- fill stage: A 128x16, B 16x128, tf32-rounded ----
#pragma unroll
        for (int it = 0; it < 2; it++) {
            int fi = it * 256 + tid;
            // A: m = fi>>2, 4-float chunk c4 = (fi&3)*4
            int m = fi >> 2;
            int c4 = (fi & 3) * 4;
            float4 av = *(const float4*)&A[(size_t)(bm0 + m) * lda + k0 + c4];
            uint4 at;
            at.x = f2tf32(av.x); at.y = f2tf32(av.y);
            at.z = f2tf32(av.z); at.w = f2tf32(av.w);
            *(uint4*)&Asu[m * AS_STRIDE + c4] = at;
            // B: k = fi>>5, n chunk n4 = (fi&31)*4
            int kk = fi >> 5;
            int n4 = (fi & 31) * 4;
            float4 bv = *(const float4*)&W[(size_t)(k0 + kk) * ldw + bn0 + n4];
            uint4 bt;
            bt.x = f2tf32(bv.x); bt.y = f2tf32(bv.y);
            bt.z = f2tf32(bv.z); bt.w = f2tf32(bv.w);
            *(uint4*)&Bsu[kk * BS_STRIDE + n4] = bt;
        }
        __syncthreads();

        // ---- compute: two k8 sub-steps ----
#pragma unroll
        for (int kc = 0; kc < GBK; kc += 8) {
            unsigned a_frag[2][4];
#pragma unroll
            for (int im = 0; im < 2; im++) {
                int rm = wm * 32 + im * 16 + g;
                a_frag[im][0] = Asu[rm * AS_STRIDE + kc + tig];
                a_frag[im][1] = Asu[(rm + 8) * AS_STRIDE + kc + tig];
                a_frag[im][2] = Asu[rm * AS_STRIDE + kc + tig + 4];
                a_frag[im][3] = Asu[(rm + 8) * AS_STRIDE + kc + tig + 4];
            }
            unsigned b_frag[8][2];
#pragma unroll
            for (int jn = 0; jn < 8; jn++) {
                int n = wn * 64 + jn * 8 + g;
                b_frag[jn][0] = Bsu[(kc + tig) * BS_STRIDE + n];
                b_frag[jn][1] = Bsu[(kc + tig + 4) * BS_STRIDE + n];
            }
#pragma unroll
            for (int im = 0; im < 2; im++)
#pragma unroll
                for (int jn = 0; jn < 8; jn++)
                    mma_tf32(acc[im][jn], a_frag[im], b_frag[jn]);
        }
        __syncthreads();
    }
}

// QKV GEMM: seq[BT,CC] @ w_attn[CC,C3] + bias, scatter into head-major q/k/v.
__global__ __launch_bounds__(256) void qkv_kernel(const float* __restrict__ A,
                                                  const float* __restrict__ W,
                                                  const float* __restrict__ bias) {
    __shared__ unsigned Asu[GBM * AS_STRIDE];
    __shared__ unsigned Bsu[GBK * BS_STRIDE];
    int bn0 = blockIdx.x * GBN;
    int bm0 = blockIdx.y * GBM;
    float acc[2][8][4] = {};
    gemm_tile_tf32(A, CC, W, C3, bm0, bn0, Asu, Bsu, acc);

    int tid = threadIdx.x;
    int wid = tid >> 5, lane = tid & 31;
    int wm = wid & 3, wn = wid >> 2;
    int g = lane >> 2, tig = lane & 3;
#pragma unroll
    for (int jn = 0; jn < 8; jn++) {
        int n0 = bn0 + wn * 64 + jn * 8 + 2 * tig;   // 8-col tile stays in one head
        int which = n0 / CC;
        int nl = n0 % CC;
        int h = nl / HD;
        int d0 = nl % HD;
        float* dst = (which == 0) ? g_q : ((which == 1) ? g_k : g_v);
        float b0v = bias[n0], b1v = bias[n0 + 1];
#pragma unroll
        for (int im = 0; im < 2; im++) {
            int r0 = bm0 + wm * 32 + im * 16 + g;
#pragma unroll
            for (int half = 0; half < 2; half++) {
                int r = r0 + half * 8;
                int b_ = r / TT, t = r % TT;
                float2 v2 = make_float2(acc[im][jn][half * 2 + 0] + b0v,
                                        acc[im][jn][half * 2 + 1] + b1v);
                *(float2*)&dst[(((size_t)(b_ * HH + h)) * TT + t) * HD + d0] = v2;
            }
        }
    }
}

// Proj GEMM: g_y[BT,CC] @ w_proj[CC,CC] + bias -> out.
__global__ __launch_bounds__(256) void proj_kernel(const float* __restrict__ W,
                                                   const float* __restrict__ bias,
                                                   float* __restrict__ out) {
    __shared__ unsigned Asu[GBM * AS_STRIDE];
    __shared__ unsigned Bsu[GBK * BS_STRIDE];
    int bn0 = blockIdx.x * GBN;
    int bm0 = blockIdx.y * GBM;
    float acc[2][8][4] = {};
    gemm_tile_tf32(g_y, CC, W, CC, bm0, bn0, Asu, Bsu, acc);

    int tid = threadIdx.x;
    int wid = tid >> 5, lane = tid & 31;
    int wm = wid & 3, wn = wid >> 2;
    int g = lane >> 2, tig = lane & 3;
#pragma unroll
    for (int jn = 0; jn < 8; jn++) {
        int n0 = bn0 + wn * 64 + jn * 8 + 2 * tig;
        float b0v = bias[n0], b1v = bias[n0 + 1];
#pragma unroll
        for (int im = 0; im < 2; im++) {
            int r0 = bm0 + wm * 32 + im * 16 + g;
#pragma unroll
            for (int half = 0; half < 2; half++) {
                int r = r0 + half * 8;
                float2 v2 = make_float2(acc[im][jn][half * 2 + 0] + b0v,
                                        acc[im][jn][half * 2 + 1] + b1v);
                *(float2*)&out[(size_t)r * CC + n0] = v2;
            }
        }
    }
}

// ---------------- Flash-style attention (fp32, unchanged) ----------------
#define KTILE 32
#define QROWS 128

__global__ __launch_bounds__(QROWS) void attn_kernel() {
    __shared__ float4 Ks[KTILE][HD / 4];
    __shared__ float4 Vs[KTILE][HD / 4];
    int bh = blockIdx.y;
    int tid = threadIdx.x;
    int row = blockIdx.x * QROWS + tid;
    const float* qb = g_q + (size_t)bh * TT * HD;
    const float* kb = g_k + (size_t)bh * TT * HD;
    const float* vb = g_v + (size_t)bh * TT * HD;

    const float scale = 0.125f;
    float4 q[HD / 4];
#pragma unroll
    for (int i = 0; i < HD / 4; i++) {
        float4 t4 = *(const float4*)&qb[(size_t)row * HD + i * 4];
        q[i] = make_float4(t4.x * scale, t4.y * scale, t4.z * scale, t4.w * scale);
    }
    float4 o[HD / 4];
#pragma unroll
    for (int i = 0; i < HD / 4; i++) o[i] = make_float4(0.f, 0.f, 0.f, 0.f);
    float m = -1e30f, l = 0.f;

    for (int kt = 0; kt < TT; kt += KTILE) {
        __syncthreads();
#pragma unroll
        for (int i = 0; i < (KTILE * HD / 4) / QROWS; i++) {
            int idx = i * QROWS + tid;
            ((float4*)Ks)[idx] = *(const float4*)&kb[(size_t)kt * HD + idx * 4];
            ((float4*)Vs)[idx] = *(const float4*)&vb[(size_t)kt * HD + idx * 4];
        }
        __syncthreads();

        float s[KTILE];
#pragma unroll
        for (int j = 0; j < KTILE; j++) {
            float sj = 0.f;
#pragma unroll
            for (int i = 0; i < HD / 4; i++) {
                float4 kk = Ks[j][i];
                sj += q[i].x * kk.x + q[i].y * kk.y + q[i].z * kk.z + q[i].w * kk.w;
            }
            s[j] = sj;
        }
        float tmax = m;
#pragma unroll
        for (int j = 0; j < KTILE; j++) tmax = fmaxf(tmax, s[j]);
        float corr = __expf(m - tmax);
        m = tmax;
        l *= corr;
#pragma unroll
        for (int i = 0; i < HD / 4; i++) {
            o[i].x *= corr; o[i].y *= corr; o[i].z *= corr; o[i].w *= corr;
        }
#pragma unroll
        for (int j = 0; j < KTILE; j++) {
            float p = __expf(s[j] - m);
            l += p;
#pragma unroll
            for (int i = 0; i < HD / 4; i++) {
                float4 vv = Vs[j][i];
                o[i].x += p * vv.x; o[i].y += p * vv.y;
                o[i].z += p * vv.z; o[i].w += p * vv.w;
            }
        }
    }
    float inv = 1.f / l;
    int b_ = bh / HH, h = bh % HH;
    float* yrow = g_y + ((size_t)(b_ * TT + row)) * CC + h * HD;
#pragma unroll
    for (int i = 0; i < HD / 4; i++) {
        float4 r4 = make_float4(o[i].x * inv, o[i].y * inv, o[i].z * inv, o[i].w * inv);
        *(float4*)&yrow[i * 4] = r4;
    }
}

extern "C" void kernel_launch(void* const* d_in, const int* in_sizes, int n_in,
                              void* d_out, int out_size) {
    const float* seq    = (const float*)d_in[0];
    const float* w_attn = (const float*)d_in[1];
    const float* b_attn = (const float*)d_in[2];
    const float* w_proj = (const float*)d_in[3];
    const float* b_proj = (const float*)d_in[4];
    float* out = (float*)d_out;

    dim3 g1(C3 / GBN, BT / GBM);        // 24 x 64
    qkv_kernel<<<g1, 256>>>(seq, w_attn, b_attn);

    dim3 g2(TT / QROWS, BB * HH);       // 16 x 64
    attn_kernel<<<g2, QROWS>>>();

    dim3 g3(CC / GBN, BT / GBM);        // 8 x 64
    proj_kernel<<<g3, 256>>>(w_proj, b_proj, out);
}

// round 3
// speedup vs baseline: 3.0918x; 2.2992x over previous
#include <cuda_runtime.h>
#include <cuda_bf16.h>
#include <math.h>

#define BB 4
#define TT 2048
#define CC 1024
#define HH 16
#define HD 64
#define BT (BB*TT)
#define C3 (3*CC)

// Scratch (device globals: allocation-guard safe)
__device__ float g_q[BB*HH*TT*HD];
__device__ float g_k[BB*HH*TT*HD];
__device__ float g_v[BB*HH*TT*HD];
__device__ float g_y[BT*CC];

// ---------------- common helpers ----------------
__device__ __forceinline__ unsigned f2tf32(float x) {
    unsigned r;
    asm("cvt.rna.tf32.f32 %0, %1;" : "=r"(r) : "f"(x));
    return r;
}

__device__ __forceinline__ void mma_tf32(float* c, const unsigned* a, const unsigned* b) {
    asm volatile(
        "mma.sync.aligned.m16n8k8.row.col.f32.tf32.tf32.f32 "
        "{%0,%1,%2,%3}, {%4,%5,%6,%7}, {%8,%9}, {%0,%1,%2,%3};"
        : "+f"(c[0]), "+f"(c[1]), "+f"(c[2]), "+f"(c[3])
        : "r"(a[0]), "r"(a[1]), "r"(a[2]), "r"(a[3]), "r"(b[0]), "r"(b[1]));
}

__device__ __forceinline__ void mma_bf16(float* c, const unsigned* a, const unsigned* b) {
    asm volatile(
        "mma.sync.aligned.m16n8k16.row.col.f32.bf16.bf16.f32 "
        "{%0,%1,%2,%3}, {%4,%5,%6,%7}, {%8,%9}, {%0,%1,%2,%3};"
        : "+f"(c[0]), "+f"(c[1]), "+f"(c[2]), "+f"(c[3])
        : "r"(a[0]), "r"(a[1]), "r"(a[2]), "r"(a[3]), "r"(b[0]), "r"(b[1]));
}

// Split (a0,a1) into packed bf16x2 hi and lo parts: hi ~ bf16(a), lo ~ bf16(a-hi).
// Packed layout: low 16 bits = a0, high 16 bits = a1.
__device__ __forceinline__ void split2(float a0, float a1, unsigned& hi, unsigned& lo) {
    unsigned h;
    asm("cvt.rn.bf16x2.f32 %0, %1, %2;" : "=r"(h) : "f"(a1), "f"(a0));
    float h0 = __uint_as_float(h << 16);
    float h1 = __uint_as_float(h & 0xffff0000u);
    unsigned l;
    float r0 = a0 - h0, r1 = a1 - h1;
    asm("cvt.rn.bf16x2.f32 %0, %1, %2;" : "=r"(l) : "f"(r1), "f"(r0));
    hi = h; lo = l;
}

__device__ __forceinline__ unsigned saddr(const void* p) {
    return (unsigned)__cvta_generic_to_shared(p);
}

__device__ __forceinline__ void ldsm4(unsigned& r0, unsigned& r1, unsigned& r2,
                                      unsigned& r3, unsigned a) {
    asm volatile("ldmatrix.sync.aligned.m8n8.x4.shared.b16 {%0,%1,%2,%3}, [%4];"
                 : "=r"(r0), "=r"(r1), "=r"(r2), "=r"(r3) : "r"(a));
}

// ---------------- tf32 tensor-core GEMM (unchanged from R2) ----------------
#define GBM 128
#define GBN 128
#define GBK 16
#define AS_STRIDE 20
#define BS_STRIDE 136

__device__ __forceinline__ void gemm_tile_tf32(
    const float* __restrict__ A, int lda,
    const float* __restrict__ W, int ldw,
    int bm0, int bn0,
    unsigned* Asu, unsigned* Bsu,
    float acc[2][8][4])
{
    int tid = threadIdx.x;
    int wid = tid >> 5, lane = tid & 31;
    int wm = wid & 3, wn = wid >> 2;
    int g = lane >> 2, tig = lane & 3;

    for (int k0 = 0; k0 < CC; k0 += GBK) {
#pragma unroll
        for (int it = 0; it < 2; it++) {
            int fi = it * 256 + tid;
            int m = fi >> 2;
            int c4 = (fi & 3) * 4;
            float4 av = *(const float4*)&A[(size_t)(bm0 + m) * lda + k0 + c4];
            uint4 at;
            at.x = f2tf32(av.x); at.y = f2tf32(av.y);
            at.z = f2tf32(av.z); at.w = f2tf32(av.w);
            *(uint4*)&Asu[m * AS_STRIDE + c4] = at;
            int kk = fi >> 5;
            int n4 = (fi & 31) * 4;
            float4 bv = *(const float4*)&W[(size_t)(k0 + kk) * ldw + bn0 + n4];
            uint4 bt;
            bt.x = f2tf32(bv.x); bt.y = f2tf32(bv.y);
            bt.z = f2tf32(bv.z); bt.w = f2tf32(bv.w);
            *(uint4*)&Bsu[kk * BS_STRIDE + n4] = bt;
        }
        __syncthreads();
#pragma unroll
        for (int kc = 0; kc < GBK; kc += 8) {
            unsigned a_frag[2][4];
#pragma unroll
            for (int im = 0; im < 2; im++) {
                int rm = wm * 32 + im * 16 + g;
                a_frag[im][0] = Asu[rm * AS_STRIDE + kc + tig];
                a_frag[im][1] = Asu[(rm + 8) * AS_STRIDE + kc + tig];
                a_frag[im][2] = Asu[rm * AS_STRIDE + kc + tig + 4];
                a_frag[im][3] = Asu[(rm + 8) * AS_STRIDE + kc + tig + 4];
            }
            unsigned b_frag[8][2];
#pragma unroll
            for (int jn = 0; jn < 8; jn++) {
                int n = wn * 64 + jn * 8 + g;
                b_frag[jn][0] = Bsu[(kc + tig) * BS_STRIDE + n];
                b_frag[jn][1] = Bsu[(kc + tig + 4) * BS_STRIDE + n];
            }
#pragma unroll
            for (int im = 0; im < 2; im++)
#pragma unroll
                for (int jn = 0; jn < 8; jn++)
                    mma_tf32(acc[im][jn], a_frag[im], b_frag[jn]);
        }
        __syncthreads();
    }
}

__global__ __launch_bounds__(256) void qkv_kernel(const float* __restrict__ A,
                                                  const float* __restrict__ W,
                                                  const float* __restrict__ bias) {
    __shared__ unsigned Asu[GBM * AS_STRIDE];
    __shared__ unsigned Bsu[GBK * BS_STRIDE];
    int bn0 = blockIdx.x * GBN;
    int bm0 = blockIdx.y * GBM;
    float acc[2][8][4] = {};
    gemm_tile_tf32(A, CC, W, C3, bm0, bn0, Asu, Bsu, acc);

    int tid = threadIdx.x;
    int wid = tid >> 5, lane = tid & 31;
    int wm = wid & 3, wn = wid >> 2;
    int g = lane >> 2, tig = lane & 3;
#pragma unroll
    for (int jn = 0; jn < 8; jn++) {
        int n0 = bn0 + wn * 64 + jn * 8 + 2 * tig;
        int which = n0 / CC;
        int nl = n0 % CC;
        int h = nl / HD;
        int d0 = nl % HD;
        float* dst = (which == 0) ? g_q : ((which == 1) ? g_k : g_v);
        float b0v = bias[n0], b1v = bias[n0 + 1];
#pragma unroll
        for (int im = 0; im < 2; im++) {
            int r0 = bm0 + wm * 32 + im * 16 + g;
#pragma unroll
            for (int half = 0; half < 2; half++) {
                int r = r0 + half * 8;
                int b_ = r / TT, t = r % TT;
                float2 v2 = make_float2(acc[im][jn][half * 2 + 0] + b0v,
                                        acc[im][jn][half * 2 + 1] + b1v);
                *(float2*)&dst[(((size_t)(b_ * HH + h)) * TT + t) * HD + d0] = v2;
            }
        }
    }
}

__global__ __launch_bounds__(256) void proj_kernel(const float* __restrict__ W,
                                                   const float* __restrict__ bias,
                                                   float* __restrict__ out) {
    __shared__ unsigned Asu[GBM * AS_STRIDE];
    __shared__ unsigned Bsu[GBK * BS_STRIDE];
    int bn0 = blockIdx.x * GBN;
    int bm0 = blockIdx.y * GBM;
    float acc[2][8][4] = {};
    gemm_tile_tf32(g_y, CC, W, CC, bm0, bn0, Asu, Bsu, acc);

    int tid = threadIdx.x;
    int wid = tid >> 5, lane = tid & 31;
    int wm = wid & 3, wn = wid >> 2;
    int g = lane >> 2, tig = lane & 3;
#pragma unroll
    for (int jn = 0; jn < 8; jn++) {
        int n0 = bn0 + wn * 64 + jn * 8 + 2 * tig;
        float b0v = bias[n0], b1v = bias[n0 + 1];
#pragma unroll
        for (int im = 0; im < 2; im++) {
            int r0 = bm0 + wm * 32 + im * 16 + g;
#pragma unroll
            for (int half = 0; half < 2; half++) {
                int r = r0 + half * 8;
                float2 v2 = make_float2(acc[im][jn][half * 2 + 0] + b0v,
                                        acc[im][jn][half * 2 + 1] + b1v);
                *(float2*)&out[(size_t)r * CC + n0] = v2;
            }
        }
    }
}

// ---------------- bf16x2 tensor-core flash attention ----------------
// 8 warps x 16 q-rows = 128 q-rows per CTA. 64-key tiles.
// K smem: [key][d] bf16 hi/lo, row stride 36 words (72 bf16) -> conflict-free.
// V smem: transposed [d][keypair] bf16x2, stride 36, col swizzled kp^(4*(d>>2&7)).
// 3-pass bf16 emulation: hi*hi + hi*lo + lo*hi (error ~2^-18, negligible).
#define AKT 64

__global__ __launch_bounds__(256, 2) void attn_kernel() {
    __shared__ __align__(128) unsigned Khi[AKT * 36];
    __shared__ __align__(128) unsigned Klo[AKT * 36];
    __shared__ __align__(128) unsigned Vthi[HD * 36];
    __shared__ __align__(128) unsigned Vtlo[HD * 36];

    const int tid = threadIdx.x;
    const int warp = tid >> 5, lane = tid & 31;
    const int g = lane >> 2, tig = lane & 3;
    const int l7 = lane & 7, l3h = lane >> 3;
    const int bh = blockIdx.y;
    const int q0 = blockIdx.x * 128;
    const float* qb = g_q + (size_t)bh * TT * HD;
    const float* kb = g_k + (size_t)bh * TT * HD;
    const float* vb = g_v + (size_t)bh * TT * HD;
    const int qrow = q0 + warp * 16 + g;

    // Q fragments in registers (scaled by 1/8), bf16 hi/lo, 4 k-steps.
    unsigned aqh[4][4], aql[4][4];
#pragma unroll
    for (int kc = 0; kc < 4; kc++) {
        int c0 = kc * 16 + 2 * tig;
        float2 x0 = *(const float2*)&qb[(size_t)qrow * HD + c0];
        float2 x1 = *(const float2*)&qb[(size_t)(qrow + 8) * HD + c0];
        float2 x2 = *(const float2*)&qb[(size_t)qrow * HD + c0 + 8];
        float2 x3 = *(const float2*)&qb[(size_t)(qrow + 8) * HD + c0 + 8];
        split2(x0.x * 0.125f, x0.y * 0.125f, aqh[kc][0], aql[kc][0]);
        split2(x1.x * 0.125f, x1.y * 0.125f, aqh[kc][1], aql[kc][1]);
        split2(x2.x * 0.125f, x2.y * 0.125f, aqh[kc][2], aql[kc][2]);
        split2(x3.x * 0.125f, x3.y * 0.125f, aqh[kc][3], aql[kc][3]);
    }

    float o[8][4];
#pragma unroll
    for (int j = 0; j < 8; j++)
#pragma unroll
        for (int i = 0; i < 4; i++) o[j][i] = 0.f;
    float m0 = -1e30f, m1 = -1e30f, l0 = 0.f, l1 = 0.f;

    for (int kt = 0; kt < TT; kt += AKT) {
        __syncthreads();
        // ---- fill K (hi/lo bf16, row stride 36 words) ----
#pragma unroll
        for (int it = 0; it < 4; it++) {
            int task = it * 256 + tid;
            int key = task >> 4, d4 = task & 15;
            float4 kv = *(const float4*)&kb[(size_t)(kt + key) * HD + d4 * 4];
            unsigned h0, lo0, h1, lo1;
            split2(kv.x, kv.y, h0, lo0);
            split2(kv.z, kv.w, h1, lo1);
            int w = key * 36 + d4 * 2;
            Khi[w] = h0; Khi[w + 1] = h1;
            Klo[w] = lo0; Klo[w + 1] = lo1;
        }
        // ---- fill V transposed (keypair-packed bf16x2, swizzled) ----
#pragma unroll
        for (int it = 0; it < 2; it++) {
            int kp = (tid & 3) + 4 * (tid >> 5);
            int d4 = ((tid >> 2) & 7) + 8 * it;
            float4 v0 = *(const float4*)&vb[(size_t)(kt + 2 * kp) * HD + d4 * 4];
            float4 v1 = *(const float4*)&vb[(size_t)(kt + 2 * kp + 1) * HD + d4 * 4];
            int col = kp ^ (4 * (d4 & 7));
            unsigned h, lo_;
            split2(v0.x, v1.x, h, lo_);
            Vthi[(4 * d4 + 0) * 36 + col] = h; Vtlo[(4 * d4 + 0) * 36 + col] = lo_;
            split2(v0.y, v1.y, h, lo_);
            Vthi[(4 * d4 + 1) * 36 + col] = h; Vtlo[(4 * d4 + 1) * 36 + col] = lo_;
            split2(v0.z, v1.z, h, lo_);
            Vthi[(4 * d4 + 2) * 36 + col] = h; Vtlo[(4 * d4 + 2) * 36 + col] = lo_;
            split2(v0.w, v1.w, h, lo_);
            Vthi[(4 * d4 + 3) * 36 + col] = h; Vtlo[(4 * d4 + 3) * 36 + col] = lo_;
        }
        __syncthreads();

        // ---- S = Q K^T (3-pass bf16) ----
        float sacc[8][4];
#pragma unroll
        for (int j = 0; j < 8; j++) {
#pragma unroll
            for (int i = 0; i < 4; i++) sacc[j][i] = 0.f;
            int rw = (8 * j + l7) * 36 + 4 * l3h;
            unsigned kh[4][2], kl[4][2];
            ldsm4(kh[0][0], kh[0][1], kh[1][0], kh[1][1], saddr(&Khi[rw]));
            ldsm4(kh[2][0], kh[2][1], kh[3][0], kh[3][1], saddr(&Khi[rw + 16]));
            ldsm4(kl[0][0], kl[0][1], kl[1][0], kl[1][1], saddr(&Klo[rw]));
            ldsm4(kl[2][0], kl[2][1], kl[3][0], kl[3][1], saddr(&Klo[rw + 16]));
#pragma unroll
            for (int kc = 0; kc < 4; kc++) {
                mma_bf16(sacc[j], aqh[kc], kh[kc]);
                mma_bf16(sacc[j], aqh[kc], kl[kc]);
                mma_bf16(sacc[j], aql[kc], kh[kc]);
            }
        }

        // ---- online softmax ----
        float rm0 = -1e30f, rm1 = -1e30f;
#pragma unroll
        for (int j = 0; j < 8; j++) {
            rm0 = fmaxf(rm0, fmaxf(sacc[j][0], sacc[j][1]));
            rm1 = fmaxf(rm1, fmaxf(sacc[j][2], sacc[j][3]));
        }
        rm0 = fmaxf(rm0, __shfl_xor_sync(0xffffffffu, rm0, 1));
        rm0 = fmaxf(rm0, __shfl_xor_sync(0xffffffffu, rm0, 2));
        rm1 = fmaxf(rm1, __shfl_xor_sync(0xffffffffu, rm1, 1));
        rm1 = fmaxf(rm1, __shfl_xor_sync(0xffffffffu, rm1, 2));
        float nm0 = fmaxf(m0, rm0), nm1 = fmaxf(m1, rm1);
        float cr0 = __expf(m0 - nm0), cr1 = __expf(m1 - nm1);
        m0 = nm0; m1 = nm1;

        unsigned ph[4][4], pl[4][4];
        float sum0 = 0.f, sum1 = 0.f;
#pragma unroll
        for (int u = 0; u < 4; u++) {
            float p00 = __expf(sacc[2 * u][0] - m0);
            float p01 = __expf(sacc[2 * u][1] - m0);
            float p10 = __expf(sacc[2 * u][2] - m1);
            float p11 = __expf(sacc[2 * u][3] - m1);
            float p20 = __expf(sacc[2 * u + 1][0] - m0);
            float p21 = __expf(sacc[2 * u + 1][1] - m0);
            float p30 = __expf(sacc[2 * u + 1][2] - m1);
            float p31 = __expf(sacc[2 * u + 1][3] - m1);
            sum0 += p00 + p01 + p20 + p21;
            sum1 += p10 + p11 + p30 + p31;
            split2(p00, p01, ph[u][0], pl[u][0]);
            split2(p10, p11, ph[u][1], pl[u][1]);
            split2(p20, p21, ph[u][2], pl[u][2]);
            split2(p30, p31, ph[u][3], pl[u][3]);
        }
        sum0 += __shfl_xor_sync(0xffffffffu, sum0, 1);
        sum0 += __shfl_xor_sync(0xffffffffu, sum0, 2);
        sum1 += __shfl_xor_sync(0xffffffffu, sum1, 1);
        sum1 += __shfl_xor_sync(0xffffffffu, sum1, 2);
        l0 = l0 * cr0 + sum0;
        l1 = l1 * cr1 + sum1;
#pragma unroll
        for (int j = 0; j < 8; j++) {
            o[j][0] *= cr0; o[j][1] *= cr0;
            o[j][2] *= cr1; o[j][3] *= cr1;
        }

        // ---- O += P V (3-pass bf16) ----
#pragma unroll
        for (int j = 0; j < 8; j++) {
            int drow = 8 * j + l7;
            int f = 4 * ((drow >> 2) & 7);
            int rb = drow * 36;
            unsigned vh[4][2], vl[4][2];
            ldsm4(vh[0][0], vh[0][1], vh[1][0], vh[1][1],
                  saddr(&Vthi[rb + ((4 * l3h) ^ f)]));
            ldsm4(vh[2][0], vh[2][1], vh[3][0], vh[3][1],
                  saddr(&Vthi[rb + ((16 + 4 * l3h) ^ f)]));
            ldsm4(vl[0][0], vl[0][1], vl[1][0], vl[1][1],
                  saddr(&Vtlo[rb + ((4 * l3h) ^ f)]));
            ldsm4(vl[2][0], vl[2][1], vl[3][0], vl[3][1],
                  saddr(&Vtlo[rb + ((16 + 4 * l3h) ^ f)]));
#pragma unroll
            for (int u = 0; u < 4; u++) {
                mma_bf16(o[j], ph[u], vh[u]);
                mma_bf16(o[j], ph[u], vl[u]);
                mma_bf16(o[j], pl[u], vh[u]);
            }
        }
    }

    // ---- epilogue ----
    float inv0 = 1.f / l0, inv1 = 1.f / l1;
    int b_ = bh >> 4, h = bh & 15;
    float* y0 = g_y + ((size_t)(b_ * TT + qrow)) * CC + h * HD;
    float* y1 = g_y + ((size_t)(b_ * TT + qrow + 8)) * CC + h * HD;
#pragma unroll
    for (int j = 0; j < 8; j++) {
        *(float2*)&y0[8 * j + 2 * tig] = make_float2(o[j][0] * inv0, o[j][1] * inv0);
        *(float2*)&y1[8 * j + 2 * tig] = make_float2(o[j][2] * inv1, o[j][3] * inv1);
    }
}

extern "C" void kernel_launch(void* const* d_in, const int* in_sizes, int n_in,
                              void* d_out, int out_size) {
    const float* seq    = (const float*)d_in[0];
    const float* w_attn = (const float*)d_in[1];
    const float* b_attn = (const float*)d_in[2];
    const float* w_proj = (const float*)d_in[3];
    const float* b_proj = (const float*)d_in[4];
    float* out = (float*)d_out;

    dim3 g1(C3 / GBN, BT / GBM);        // 24 x 64
    qkv_kernel<<<g1, 256>>>(seq, w_attn, b_attn);

    dim3 g2(TT / 128, BB * HH);         // 16 x 64
    attn_kernel<<<g2, 256>>>();

    dim3 g3(CC / GBN, BT / GBM);        // 8 x 64
    proj_kernel<<<g3, 256>>>(w_proj, b_proj, out);
}

// round 5
// speedup vs baseline: 3.3156x; 1.0724x over previous
#include <cuda_runtime.h>
#include <cuda_bf16.h>
#include <math.h>

#define BB 4
#define TT 2048
#define CC 1024
#define HH 16
#define HD 64
#define BT (BB*TT)
#define C3 (3*CC)

// Scratch (device globals: allocation-guard safe)
__device__ float g_q[BB*HH*TT*HD];
__device__ float g_k[BB*HH*TT*HD];
__device__ float g_v[BB*HH*TT*HD];
__device__ float g_y[BT*CC];

// ---------------- common helpers ----------------
__device__ __forceinline__ unsigned f2tf32(float x) {
    unsigned r;
    asm("cvt.rna.tf32.f32 %0, %1;" : "=r"(r) : "f"(x));
    return r;
}

__device__ __forceinline__ void mma_tf32(float* c, const unsigned* a, const unsigned* b) {
    asm volatile(
        "mma.sync.aligned.m16n8k8.row.col.f32.tf32.tf32.f32 "
        "{%0,%1,%2,%3}, {%4,%5,%6,%7}, {%8,%9}, {%0,%1,%2,%3};"
        : "+f"(c[0]), "+f"(c[1]), "+f"(c[2]), "+f"(c[3])
        : "r"(a[0]), "r"(a[1]), "r"(a[2]), "r"(a[3]), "r"(b[0]), "r"(b[1]));
}

__device__ __forceinline__ void mma_bf16(float* c, const unsigned* a, const unsigned* b) {
    asm volatile(
        "mma.sync.aligned.m16n8k16.row.col.f32.bf16.bf16.f32 "
        "{%0,%1,%2,%3}, {%4,%5,%6,%7}, {%8,%9}, {%0,%1,%2,%3};"
        : "+f"(c[0]), "+f"(c[1]), "+f"(c[2]), "+f"(c[3])
        : "r"(a[0]), "r"(a[1]), "r"(a[2]), "r"(a[3]), "r"(b[0]), "r"(b[1]));
}

// Split (a0,a1) into packed bf16x2 hi and lo: hi ~ bf16(a), lo ~ bf16(a-hi).
__device__ __forceinline__ void split2(float a0, float a1, unsigned& hi, unsigned& lo) {
    unsigned h;
    asm("cvt.rn.bf16x2.f32 %0, %1, %2;" : "=r"(h) : "f"(a1), "f"(a0));
    float h0 = __uint_as_float(h << 16);
    float h1 = __uint_as_float(h & 0xffff0000u);
    unsigned l;
    float r0 = a0 - h0, r1 = a1 - h1;
    asm("cvt.rn.bf16x2.f32 %0, %1, %2;" : "=r"(l) : "f"(r1), "f"(r0));
    hi = h; lo = l;
}

__device__ __forceinline__ unsigned saddr(const void* p) {
    return (unsigned)__cvta_generic_to_shared(p);
}

__device__ __forceinline__ void ldsm4(unsigned& r0, unsigned& r1, unsigned& r2,
                                      unsigned& r3, unsigned a) {
    asm volatile("ldmatrix.sync.aligned.m8n8.x4.shared.b16 {%0,%1,%2,%3}, [%4];"
                 : "=r"(r0), "=r"(r1), "=r"(r2), "=r"(r3) : "r"(a));
}

// ---------------- tf32 tensor-core GEMM, software-pipelined ----------------
// Block 128x128, k-stage 16, 2-stage smem double buffer + register prefetch.
#define GBM 128
#define GBN 128
#define GBK 16
#define AS_STRIDE 20
#define BS_STRIDE 136
#define ASZ (GBM * AS_STRIDE)   // words per A stage
#define BSZ (GBK * BS_STRIDE)   // words per B stage
#define NSTG (CC / GBK)         // 64

__device__ __forceinline__ void gemm_sts(unsigned* Asu, unsigned* Bsu, int buf,
                                         const float4* pa, const float4* pb,
                                         const int* m_, const int* c4_,
                                         const int* kk_, const int* n4_) {
#pragma unroll
    for (int it = 0; it < 2; it++) {
        uint4 at;
        at.x = f2tf32(pa[it].x); at.y = f2tf32(pa[it].y);
        at.z = f2tf32(pa[it].z); at.w = f2tf32(pa[it].w);
        *(uint4*)&Asu[buf * ASZ + m_[it] * AS_STRIDE + c4_[it]] = at;
        uint4 bt;
        bt.x = f2tf32(pb[it].x); bt.y = f2tf32(pb[it].y);
        bt.z = f2tf32(pb[it].z); bt.w = f2tf32(pb[it].w);
        *(uint4*)&Bsu[buf * BSZ + kk_[it] * BS_STRIDE + n4_[it]] = bt;
    }
}

__device__ __forceinline__ void gemm_tile_tf32(
    const float* __restrict__ A, int lda,
    const float* __restrict__ W, int ldw,
    int bm0, int bn0,
    unsigned* Asu, unsigned* Bsu,
    float acc[2][8][4])
{
    int tid = threadIdx.x;
    int wid = tid >> 5, lane = tid & 31;
    int wm = wid & 3, wn = wid >> 2;
    int g = lane >> 2, tig = lane & 3;

    // Per-thread fill coordinates
    int m_[2], c4_[2], kk_[2], n4_[2];
#pragma unroll
    for (int it = 0; it < 2; it++) {
        int fi = it * 256 + tid;
        m_[it] = fi >> 2;
        c4_[it] = (fi & 3) * 4;
        kk_[it] = fi >> 5;
        n4_[it] = (fi & 31) * 4;
    }

    float4 pa[2], pb[2];
    // Prologue: load + store stage 0
#pragma unroll
    for (int it = 0; it < 2; it++) {
        pa[it] = *(const float4*)&A[(size_t)(bm0 + m_[it]) * lda + c4_[it]];
        pb[it] = *(const float4*)&W[(size_t)kk_[it] * ldw + bn0 + n4_[it]];
    }
    gemm_sts(Asu, Bsu, 0, pa, pb, m_, c4_, kk_, n4_);
    __syncthreads();

#pragma unroll 2
    for (int s = 0; s < NSTG; s++) {
        int cur = s & 1;
        // Prefetch next stage into registers (latency hidden by compute below)
        if (s + 1 < NSTG) {
            int k0 = (s + 1) * GBK;
#pragma unroll
            for (int it = 0; it < 2; it++) {
                pa[it] = *(const float4*)&A[(size_t)(bm0 + m_[it]) * lda + k0 + c4_[it]];
                pb[it] = *(const float4*)&W[(size_t)(k0 + kk_[it]) * ldw + bn0 + n4_[it]];
            }
        }
        // Compute current stage
        const unsigned* Ac = Asu + cur * ASZ;
        const unsigned* Bc = Bsu + cur * BSZ;
#pragma unroll
        for (int kc = 0; kc < GBK; kc += 8) {
            unsigned a_frag[2][4];
#pragma unroll
            for (int im = 0; im < 2; im++) {
                int rm = wm * 32 + im * 16 + g;
                a_frag[im][0] = Ac[rm * AS_STRIDE + kc + tig];
                a_frag[im][1] = Ac[(rm + 8) * AS_STRIDE + kc + tig];
                a_frag[im][2] = Ac[rm * AS_STRIDE + kc + tig + 4];
                a_frag[im][3] = Ac[(rm + 8) * AS_STRIDE + kc + tig + 4];
            }
            unsigned b_frag[8][2];
#pragma unroll
            for (int jn = 0; jn < 8; jn++) {
                int n = wn * 64 + jn * 8 + g;
                b_frag[jn][0] = Bc[(kc + tig) * BS_STRIDE + n];
                b_frag[jn][1] = Bc[(kc + tig + 4) * BS_STRIDE + n];
            }
#pragma unroll
            for (int im = 0; im < 2; im++)
#pragma unroll
                for (int jn = 0; jn < 8; jn++)
                    mma_tf32(acc[im][jn], a_frag[im], b_frag[jn]);
        }
        // Store next stage into the other buffer
        if (s + 1 < NSTG)
            gemm_sts(Asu, Bsu, cur ^ 1, pa, pb, m_, c4_, kk_, n4_);
        __syncthreads();
    }
}

__global__ __launch_bounds__(256, 2) void qkv_kernel(const float* __restrict__ A,
                                                     const float* __restrict__ W,
                                                     const float* __restrict__ bias) {
    __shared__ unsigned Asu[2 * ASZ];
    __shared__ unsigned Bsu[2 * BSZ];
    int bn0 = blockIdx.x * GBN;
    int bm0 = blockIdx.y * GBM;
    float acc[2][8][4] = {};
    gemm_tile_tf32(A, CC, W, C3, bm0, bn0, Asu, Bsu, acc);

    int tid = threadIdx.x;
    int wid = tid >> 5, lane = tid & 31;
    int wm = wid & 3, wn = wid >> 2;
    int g = lane >> 2, tig = lane & 3;
#pragma unroll
    for (int jn = 0; jn < 8; jn++) {
        int n0 = bn0 + wn * 64 + jn * 8 + 2 * tig;
        int which = n0 / CC;
        int nl = n0 % CC;
        int h = nl / HD;
        int d0 = nl % HD;
        float* dst = (which == 0) ? g_q : ((which == 1) ? g_k : g_v);
        float b0v = bias[n0], b1v = bias[n0 + 1];
#pragma unroll
        for (int im = 0; im < 2; im++) {
            int r0 = bm0 + wm * 32 + im * 16 + g;
#pragma unroll
            for (int half = 0; half < 2; half++) {
                int r = r0 + half * 8;
                int b_ = r / TT, t = r % TT;
                float2 v2 = make_float2(acc[im][jn][half * 2 + 0] + b0v,
                                        acc[im][jn][half * 2 + 1] + b1v);
                *(float2*)&dst[(((size_t)(b_ * HH + h)) * TT + t) * HD + d0] = v2;
            }
        }
    }
}

__global__ __launch_bounds__(256, 2) void proj_kernel(const float* __restrict__ W,
                                                      const float* __restrict__ bias,
                                                      float* __restrict__ out) {
    __shared__ unsigned Asu[2 * ASZ];
    __shared__ unsigned Bsu[2 * BSZ];
    int bn0 = blockIdx.x * GBN;
    int bm0 = blockIdx.y * GBM;
    float acc[2][8][4] = {};
    gemm_tile_tf32(g_y, CC, W, CC, bm0, bn0, Asu, Bsu, acc);

    int tid = threadIdx.x;
    int wid = tid >> 5, lane = tid & 31;
    int wm = wid & 3, wn = wid >> 2;
    int g = lane >> 2, tig = lane & 3;
#pragma unroll
    for (int jn = 0; jn < 8; jn++) {
        int n0 = bn0 + wn * 64 + jn * 8 + 2 * tig;
        float b0v = bias[n0], b1v = bias[n0 + 1];
#pragma unroll
        for (int im = 0; im < 2; im++) {
            int r0 = bm0 + wm * 32 + im * 16 + g;
#pragma unroll
            for (int half = 0; half < 2; half++) {
                int r = r0 + half * 8;
                float2 v2 = make_float2(acc[im][jn][half * 2 + 0] + b0v,
                                        acc[im][jn][half * 2 + 1] + b1v);
                *(float2*)&out[(size_t)r * CC + n0] = v2;
            }
        }
    }
}

// ---------------- bf16x2 tensor-core flash attention (unchanged) ----------------
#define AKT 64

__global__ __launch_bounds__(256, 2) void attn_kernel() {
    __shared__ __align__(128) unsigned Khi[AKT * 36];
    __shared__ __align__(128) unsigned Klo[AKT * 36];
    __shared__ __align__(128) unsigned Vthi[HD * 36];
    __shared__ __align__(128) unsigned Vtlo[HD * 36];

    const int tid = threadIdx.x;
    const int warp = tid >> 5, lane = tid & 31;
    const int g = lane >> 2, tig = lane & 3;
    const int l7 = lane & 7, l3h = lane >> 3;
    const int bh = blockIdx.y;
    const int q0 = blockIdx.x * 128;
    const float* qb = g_q + (size_t)bh * TT * HD;
    const float* kb = g_k + (size_t)bh * TT * HD;
    const float* vb = g_v + (size_t)bh * TT * HD;
    const int qrow = q0 + warp * 16 + g;

    unsigned aqh[4][4], aql[4][4];
#pragma unroll
    for (int kc = 0; kc < 4; kc++) {
        int c0 = kc * 16 + 2 * tig;
        float2 x0 = *(const float2*)&qb[(size_t)qrow * HD + c0];
        float2 x1 = *(const float2*)&qb[(size_t)(qrow + 8) * HD + c0];
        float2 x2 = *(const float2*)&qb[(size_t)qrow * HD + c0 + 8];
        float2 x3 = *(const float2*)&qb[(size_t)(qrow + 8) * HD + c0 + 8];
        split2(x0.x * 0.125f, x0.y * 0.125f, aqh[kc][0], aql[kc][0]);
        split2(x1.x * 0.125f, x1.y * 0.125f, aqh[kc][1], aql[kc][1]);
        split2(x2.x * 0.125f, x2.y * 0.125f, aqh[kc][2], aql[kc][2]);
        split2(x3.x * 0.125f, x3.y * 0.125f, aqh[kc][3], aql[kc][3]);
    }

    float o[8][4];
#pragma unroll
    for (int j = 0; j < 8; j++)
#pragma unroll
        for (int i = 0; i < 4; i++) o[j][i] = 0.f;
    float m0 = -1e30f, m1 = -1e30f, l0 = 0.f, l1 = 0.f;

    for (int kt = 0; kt < TT; kt += AKT) {
        __syncthreads();
#pragma unroll
        for (int it = 0; it < 4; it++) {
            int task = it * 256 + tid;
            int key = task >> 4, d4 = task & 15;
            float4 kv = *(const float4*)&kb[(size_t)(kt + key) * HD + d4 * 4];
            unsigned h0, lo0, h1, lo1;
            split2(kv.x, kv.y, h0, lo0);
            split2(kv.z, kv.w, h1, lo1);
            int w = key * 36 + d4 * 2;
            Khi[w] = h0; Khi[w + 1] = h1;
            Klo[w] = lo0; Klo[w + 1] = lo1;
        }
#pragma unroll
        for (int it = 0; it < 2; it++) {
            int kp = (tid & 3) + 4 * (tid >> 5);
            int d4 = ((tid >> 2) & 7) + 8 * it;
            float4 v0 = *(const float4*)&vb[(size_t)(kt + 2 * kp) * HD + d4 * 4];
            float4 v1 = *(const float4*)&vb[(size_t)(kt + 2 * kp + 1) * HD + d4 * 4];
            int col = kp ^ (4 * (d4 & 7));
            unsigned h, lo_;
            split2(v0.x, v1.x, h, lo_);
            Vthi[(4 * d4 + 0) * 36 + col] = h; Vtlo[(4 * d4 + 0) * 36 + col] = lo_;
            split2(v0.y, v1.y, h, lo_);
            Vthi[(4 * d4 + 1) * 36 + col] = h; Vtlo[(4 * d4 + 1) * 36 + col] = lo_;
            split2(v0.z, v1.z, h, lo_);
            Vthi[(4 * d4 + 2) * 36 + col] = h; Vtlo[(4 * d4 + 2) * 36 + col] = lo_;
            split2(v0.w, v1.w, h, lo_);
            Vthi[(4 * d4 + 3) * 36 + col] = h; Vtlo[(4 * d4 + 3) * 36 + col] = lo_;
        }
        __syncthreads();

        float sacc[8][4];
#pragma unroll
        for (int j = 0; j < 8; j++) {
#pragma unroll
            for (int i = 0; i < 4; i++) sacc[j][i] = 0.f;
            int rw = (8 * j + l7) * 36 + 4 * l3h;
            unsigned kh[4][2], kl[4][2];
            ldsm4(kh[0][0], kh[0][1], kh[1][0], kh[1][1], saddr(&Khi[rw]));
            ldsm4(kh[2][0], kh[2][1], kh[3][0], kh[3][1], saddr(&Khi[rw + 16]));
            ldsm4(kl[0][0], kl[0][1], kl[1][0], kl[1][1], saddr(&Klo[rw]));
            ldsm4(kl[2][0], kl[2][1], kl[3][0], kl[3][1], saddr(&Klo[rw + 16]));
#pragma unroll
            for (int kc = 0; kc < 4; kc++) {
                mma_bf16(sacc[j], aqh[kc], kh[kc]);
                mma_bf16(sacc[j], aqh[kc], kl[kc]);
                mma_bf16(sacc[j], aql[kc], kh[kc]);
            }
        }

        float rm0 = -1e30f, rm1 = -1e30f;
#pragma unroll
        for (int j = 0; j < 8; j++) {
            rm0 = fmaxf(rm0, fmaxf(sacc[j][0], sacc[j][1]));
            rm1 = fmaxf(rm1, fmaxf(sacc[j][2], sacc[j][3]));
        }
        rm0 = fmaxf(rm0, __shfl_xor_sync(0xffffffffu, rm0, 1));
        rm0 = fmaxf(rm0, __shfl_xor_sync(0xffffffffu, rm0, 2));
        rm1 = fmaxf(rm1, __shfl_xor_sync(0xffffffffu, rm1, 1));
        rm1 = fmaxf(rm1, __shfl_xor_sync(0xffffffffu, rm1, 2));
        float nm0 = fmaxf(m0, rm0), nm1 = fmaxf(m1, rm1);
        float cr0 = __expf(m0 - nm0), cr1 = __expf(m1 - nm1);
        m0 = nm0; m1 = nm1;

        unsigned ph[4][4], pl[4][4];
        float sum0 = 0.f, sum1 = 0.f;
#pragma unroll
        for (int u = 0; u < 4; u++) {
            float p00 = __expf(sacc[2 * u][0] - m0);
            float p01 = __expf(sacc[2 * u][1] - m0);
            float p10 = __expf(sacc[2 * u][2] - m1);
            float p11 = __expf(sacc[2 * u][3] - m1);
            float p20 = __expf(sacc[2 * u + 1][0] - m0);
            float p21 = __expf(sacc[2 * u + 1][1] - m0);
            float p30 = __expf(sacc[2 * u + 1][2] - m1);
            float p31 = __expf(sacc[2 * u + 1][3] - m1);
            sum0 += p00 + p01 + p20 + p21;
            sum1 += p10 + p11 + p30 + p31;
            split2(p00, p01, ph[u][0], pl[u][0]);
            split2(p10, p11, ph[u][1], pl[u][1]);
            split2(p20, p21, ph[u][2], pl[u][2]);
            split2(p30, p31, ph[u][3], pl[u][3]);
        }
        sum0 += __shfl_xor_sync(0xffffffffu, sum0, 1);
        sum0 += __shfl_xor_sync(0xffffffffu, sum0, 2);
        sum1 += __shfl_xor_sync(0xffffffffu, sum1, 1);
        sum1 += __shfl_xor_sync(0xffffffffu, sum1, 2);
        l0 = l0 * cr0 + sum0;
        l1 = l1 * cr1 + sum1;
#pragma unroll
        for (int j = 0; j < 8; j++) {
            o[j][0] *= cr0; o[j][1] *= cr0;
            o[j][2] *= cr1; o[j][3] *= cr1;
        }

#pragma unroll
        for (int j = 0; j < 8; j++) {
            int drow = 8 * j + l7;
            int f = 4 * ((drow >> 2) & 7);
            int rb = drow * 36;
            unsigned vh[4][2], vl[4][2];
            ldsm4(vh[0][0], vh[0][1], vh[1][0], vh[1][1],
                  saddr(&Vthi[rb + ((4 * l3h) ^ f)]));
            ldsm4(vh[2][0], vh[2][1], vh[3][0], vh[3][1],
                  saddr(&Vthi[rb + ((16 + 4 * l3h) ^ f)]));
            ldsm4(vl[0][0], vl[0][1], vl[1][0], vl[1][1],
                  saddr(&Vtlo[rb + ((4 * l3h) ^ f)]));
            ldsm4(vl[2][0], vl[2][1], vl[3][0], vl[3][1],
                  saddr(&Vtlo[rb + ((16 + 4 * l3h) ^ f)]));
#pragma unroll
            for (int u = 0; u < 4; u++) {
                mma_bf16(o[j], ph[u], vh[u]);
                mma_bf16(o[j], ph[u], vl[u]);
                mma_bf16(o[j], pl[u], vh[u]);
            }
        }
    }

    float inv0 = 1.f / l0, inv1 = 1.f / l1;
    int b_ = bh >> 4, h = bh & 15;
    float* y0 = g_y + ((size_t)(b_ * TT + qrow)) * CC + h * HD;
    float* y1 = g_y + ((size_t)(b_ * TT + qrow + 8)) * CC + h * HD;
#pragma unroll
    for (int j = 0; j < 8; j++) {
        *(float2*)&y0[8 * j + 2 * tig] = make_float2(o[j][0] * inv0, o[j][1] * inv0);
        *(float2*)&y1[8 * j + 2 * tig] = make_float2(o[j][2] * inv1, o[j][3] * inv1);
    }
}

extern "C" void kernel_launch(void* const* d_in, const int* in_sizes, int n_in,
                              void* d_out, int out_size) {
    const float* seq    = (const float*)d_in[0];
    const float* w_attn = (const float*)d_in[1];
    const float* b_attn = (const float*)d_in[2];
    const float* w_proj = (const float*)d_in[3];
    const float* b_proj = (const float*)d_in[4];
    float* out = (float*)d_out;

    dim3 g1(C3 / GBN, BT / GBM);        // 24 x 64
    qkv_kernel<<<g1, 256>>>(seq, w_attn, b_attn);

    dim3 g2(TT / 128, BB * HH);         // 16 x 64
    attn_kernel<<<g2, 256>>>();

    dim3 g3(CC / GBN, BT / GBM);        // 8 x 64
    proj_kernel<<<g3, 256>>>(w_proj, b_proj, out);
}

// round 8
// speedup vs baseline: 3.3616x; 1.0139x over previous
#include <cuda_runtime.h>
#include <cuda_bf16.h>
#include <math.h>

#define BB 4
#define TT 2048
#define CC 1024
#define HH 16
#define HD 64
#define BT (BB*TT)
#define C3 (3*CC)

// q pre-scale: (1/sqrt(64)) * log2(e), folded in at qkv epilogue
#define QSCALE 0.18033688011112042f

// Scratch (device globals: allocation-guard safe).
// q/k/v stored as pre-split bf16 hi/lo planes, packed d-pairs: [b*H+h][t][32 words]
__device__ unsigned g_qhi[BB*HH*TT*32];
__device__ unsigned g_qlo[BB*HH*TT*32];
__device__ unsigned g_khi[BB*HH*TT*32];
__device__ unsigned g_klo[BB*HH*TT*32];
__device__ unsigned g_vhi[BB*HH*TT*32];
__device__ unsigned g_vlo[BB*HH*TT*32];
__device__ float g_y[BT*CC];

// ---------------- common helpers ----------------
__device__ __forceinline__ unsigned f2tf32(float x) {
    unsigned r;
    asm("cvt.rna.tf32.f32 %0, %1;" : "=r"(r) : "f"(x));
    return r;
}

__device__ __forceinline__ void mma_tf32(float* c, const unsigned* a, const unsigned* b) {
    asm volatile(
        "mma.sync.aligned.m16n8k8.row.col.f32.tf32.tf32.f32 "
        "{%0,%1,%2,%3}, {%4,%5,%6,%7}, {%8,%9}, {%0,%1,%2,%3};"
        : "+f"(c[0]), "+f"(c[1]), "+f"(c[2]), "+f"(c[3])
        : "r"(a[0]), "r"(a[1]), "r"(a[2]), "r"(a[3]), "r"(b[0]), "r"(b[1]));
}

__device__ __forceinline__ void mma_bf16(float* c, const unsigned* a, const unsigned* b) {
    asm volatile(
        "mma.sync.aligned.m16n8k16.row.col.f32.bf16.bf16.f32 "
        "{%0,%1,%2,%3}, {%4,%5,%6,%7}, {%8,%9}, {%0,%1,%2,%3};"
        : "+f"(c[0]), "+f"(c[1]), "+f"(c[2]), "+f"(c[3])
        : "r"(a[0]), "r"(a[1]), "r"(a[2]), "r"(a[3]), "r"(b[0]), "r"(b[1]));
}

// Split (a0,a1) into packed bf16x2 hi and lo: hi ~ bf16(a), lo ~ bf16(a-hi).
__device__ __forceinline__ void split2(float a0, float a1, unsigned& hi, unsigned& lo) {
    unsigned h;
    asm("cvt.rn.bf16x2.f32 %0, %1, %2;" : "=r"(h) : "f"(a1), "f"(a0));
    float h0 = __uint_as_float(h << 16);
    float h1 = __uint_as_float(h & 0xffff0000u);
    unsigned l;
    float r0 = a0 - h0, r1 = a1 - h1;
    asm("cvt.rn.bf16x2.f32 %0, %1, %2;" : "=r"(l) : "f"(r1), "f"(r0));
    hi = h; lo = l;
}

__device__ __forceinline__ unsigned saddr(const void* p) {
    return (unsigned)__cvta_generic_to_shared(p);
}

__device__ __forceinline__ void ldsm4(unsigned& r0, unsigned& r1, unsigned& r2,
                                      unsigned& r3, unsigned a) {
    asm volatile("ldmatrix.sync.aligned.m8n8.x4.shared.b16 {%0,%1,%2,%3}, [%4];"
                 : "=r"(r0), "=r"(r1), "=r"(r2), "=r"(r3) : "r"(a));
}

__device__ __forceinline__ unsigned prmt(unsigned a, unsigned b, unsigned sel) {
    unsigned r;
    asm("prmt.b32 %0, %1, %2, %3;" : "=r"(r) : "r"(a), "r"(b), "r"(sel));
    return r;
}

__device__ __forceinline__ float ex2(float x) {
    float r;
    asm("ex2.approx.f32 %0, %1;" : "=f"(r) : "f"(x));
    return r;
}

// ---------------- tf32 tensor-core GEMM, software-pipelined (R5) ----------------
#define GBM 128
#define GBN 128
#define GBK 16
#define AS_STRIDE 20
#define BS_STRIDE 136
#define ASZ (GBM * AS_STRIDE)
#define BSZ (GBK * BS_STRIDE)
#define NSTG (CC / GBK)

__device__ __forceinline__ void gemm_sts(unsigned* Asu, unsigned* Bsu, int buf,
                                         const float4* pa, const float4* pb,
                                         const int* m_, const int* c4_,
                                         const int* kk_, const int* n4_) {
#pragma unroll
    for (int it = 0; it < 2; it++) {
        uint4 at;
        at.x = f2tf32(pa[it].x); at.y = f2tf32(pa[it].y);
        at.z = f2tf32(pa[it].z); at.w = f2tf32(pa[it].w);
        *(uint4*)&Asu[buf * ASZ + m_[it] * AS_STRIDE + c4_[it]] = at;
        uint4 bt;
        bt.x = f2tf32(pb[it].x); bt.y = f2tf32(pb[it].y);
        bt.z = f2tf32(pb[it].z); bt.w = f2tf32(pb[it].w);
        *(uint4*)&Bsu[buf * BSZ + kk_[it] * BS_STRIDE + n4_[it]] = bt;
    }
}

__device__ __forceinline__ void gemm_tile_tf32(
    const float* __restrict__ A, int lda,
    const float* __restrict__ W, int ldw,
    int bm0, int bn0,
    unsigned* Asu, unsigned* Bsu,
    float acc[2][8][4])
{
    int tid = threadIdx.x;
    int wid = tid >> 5, lane = tid & 31;
    int wm = wid & 3, wn = wid >> 2;
    int g = lane >> 2, tig = lane & 3;

    int m_[2], c4_[2], kk_[2], n4_[2];
#pragma unroll
    for (int it = 0; it < 2; it++) {
        int fi = it * 256 + tid;
        m_[it] = fi >> 2;
        c4_[it] = (fi & 3) * 4;
        kk_[it] = fi >> 5;
        n4_[it] = (fi & 31) * 4;
    }

    float4 pa[2], pb[2];
#pragma unroll
    for (int it = 0; it < 2; it++) {
        pa[it] = *(const float4*)&A[(size_t)(bm0 + m_[it]) * lda + c4_[it]];
        pb[it] = *(const float4*)&W[(size_t)kk_[it] * ldw + bn0 + n4_[it]];
    }
    gemm_sts(Asu, Bsu, 0, pa, pb, m_, c4_, kk_, n4_);
    __syncthreads();

#pragma unroll 2
    for (int s = 0; s < NSTG; s++) {
        int cur = s & 1;
        if (s + 1 < NSTG) {
            int k0 = (s + 1) * GBK;
#pragma unroll
            for (int it = 0; it < 2; it++) {
                pa[it] = *(const float4*)&A[(size_t)(bm0 + m_[it]) * lda + k0 + c4_[it]];
                pb[it] = *(const float4*)&W[(size_t)(k0 + kk_[it]) * ldw + bn0 + n4_[it]];
            }
        }
        const unsigned* Ac = Asu + cur * ASZ;
        const unsigned* Bc = Bsu + cur * BSZ;
#pragma unroll
        for (int kc = 0; kc < GBK; kc += 8) {
            unsigned a_frag[2][4];
#pragma unroll
            for (int im = 0; im < 2; im++) {
                int rm = wm * 32 + im * 16 + g;
                a_frag[im][0] = Ac[rm * AS_STRIDE + kc + tig];
                a_frag[im][1] = Ac[(rm + 8) * AS_STRIDE + kc + tig];
                a_frag[im][2] = Ac[rm * AS_STRIDE + kc + tig + 4];
                a_frag[im][3] = Ac[(rm + 8) * AS_STRIDE + kc + tig + 4];
            }
            unsigned b_frag[8][2];
#pragma unroll
            for (int jn = 0; jn < 8; jn++) {
                int n = wn * 64 + jn * 8 + g;
                b_frag[jn][0] = Bc[(kc + tig) * BS_STRIDE + n];
                b_frag[jn][1] = Bc[(kc + tig + 4) * BS_STRIDE + n];
            }
#pragma unroll
            for (int im = 0; im < 2; im++)
#pragma unroll
                for (int jn = 0; jn < 8; jn++)
                    mma_tf32(acc[im][jn], a_frag[im], b_frag[jn]);
        }
        if (s + 1 < NSTG)
            gemm_sts(Asu, Bsu, cur ^ 1, pa, pb, m_, c4_, kk_, n4_);
        __syncthreads();
    }
}

// QKV: seq @ w_attn + bias -> pre-split bf16 hi/lo q/k/v planes (q pre-scaled)
__global__ __launch_bounds__(256, 2) void qkv_kernel(const float* __restrict__ A,
                                                     const float* __restrict__ W,
                                                     const float* __restrict__ bias) {
    __shared__ unsigned Asu[2 * ASZ];
    __shared__ unsigned Bsu[2 * BSZ];
    int bn0 = blockIdx.x * GBN;
    int bm0 = blockIdx.y * GBM;
    float acc[2][8][4] = {};
    gemm_tile_tf32(A, CC, W, C3, bm0, bn0, Asu, Bsu, acc);

    int tid = threadIdx.x;
    int wid = tid >> 5, lane = tid & 31;
    int wm = wid & 3, wn = wid >> 2;
    int g = lane >> 2, tig = lane & 3;
#pragma unroll
    for (int jn = 0; jn < 8; jn++) {
        int n0 = bn0 + wn * 64 + jn * 8 + 2 * tig;    // even -> d-pair aligned
        int which = n0 / CC;
        int nl = n0 % CC;
        int h = nl / HD;
        int word = (nl % HD) >> 1;
        unsigned* dsthi = (which == 0) ? g_qhi : ((which == 1) ? g_khi : g_vhi);
        unsigned* dstlo = (which == 0) ? g_qlo : ((which == 1) ? g_klo : g_vlo);
        float b0v = bias[n0], b1v = bias[n0 + 1];
#pragma unroll
        for (int im = 0; im < 2; im++) {
            int r0 = bm0 + wm * 32 + im * 16 + g;
#pragma unroll
            for (int half = 0; half < 2; half++) {
                int r = r0 + half * 8;
                int b_ = r / TT, t = r % TT;
                float v0 = acc[im][jn][half * 2 + 0] + b0v;
                float v1 = acc[im][jn][half * 2 + 1] + b1v;
                if (which == 0) { v0 *= QSCALE; v1 *= QSCALE; }
                unsigned hi, lo;
                split2(v0, v1, hi, lo);
                size_t idx = ((size_t)(b_ * HH + h) * TT + t) * 32 + word;
                dsthi[idx] = hi;
                dstlo[idx] = lo;
            }
        }
    }
}

// Proj: g_y[BT,CC] @ w_proj[CC,CC] + bias -> out (unchanged from R5)
__global__ __launch_bounds__(256, 2) void proj_kernel(const float* __restrict__ W,
                                                      const float* __restrict__ bias,
                                                      float* __restrict__ out) {
    __shared__ unsigned Asu[2 * ASZ];
    __shared__ unsigned Bsu[2 * BSZ];
    int bn0 = blockIdx.x * GBN;
    int bm0 = blockIdx.y * GBM;
    float acc[2][8][4] = {};
    gemm_tile_tf32(g_y, CC, W, CC, bm0, bn0, Asu, Bsu, acc);

    int tid = threadIdx.x;
    int wid = tid >> 5, lane = tid & 31;
    int wm = wid & 3, wn = wid >> 2;
    int g = lane >> 2, tig = lane & 3;
#pragma unroll
    for (int jn = 0; jn < 8; jn++) {
        int n0 = bn0 + wn * 64 + jn * 8 + 2 * tig;
        float b0v = bias[n0], b1v = bias[n0 + 1];
#pragma unroll
        for (int im = 0; im < 2; im++) {
            int r0 = bm0 + wm * 32 + im * 16 + g;
#pragma unroll
            for (int half = 0; half < 2; half++) {
                int r = r0 + half * 8;
                float2 v2 = make_float2(acc[im][jn][half * 2 + 0] + b0v,
                                        acc[im][jn][half * 2 + 1] + b1v);
                *(float2*)&out[(size_t)r * CC + n0] = v2;
            }
        }
    }
}

// ---------------- bf16x2 tensor-core flash attention ----------------
// K/V/Q arrive pre-split in bf16 hi/lo planes; fills are pure data movement.
// Softmax in log2 domain (q pre-scaled by 0.125*log2e), ex2.approx for exps.
#define AKT 64

__global__ __launch_bounds__(256, 2) void attn_kernel() {
    __shared__ __align__(128) unsigned Khi[AKT * 36];
    __shared__ __align__(128) unsigned Klo[AKT * 36];
    __shared__ __align__(128) unsigned Vthi[HD * 36];
    __shared__ __align__(128) unsigned Vtlo[HD * 36];

    const int tid = threadIdx.x;
    const int warp = tid >> 5, lane = tid & 31;
    const int g = lane >> 2, tig = lane & 3;
    const int l7 = lane & 7, l3h = lane >> 3;
    const int bh = blockIdx.y;
    const int q0 = blockIdx.x * 128;
    const unsigned* qhg = g_qhi + (size_t)bh * TT * 32;
    const unsigned* qlg = g_qlo + (size_t)bh * TT * 32;
    const unsigned* khg = g_khi + (size_t)bh * TT * 32;
    const unsigned* klg = g_klo + (size_t)bh * TT * 32;
    const unsigned* vhg = g_vhi + (size_t)bh * TT * 32;
    const unsigned* vlg = g_vlo + (size_t)bh * TT * 32;
    const int qrow = q0 + warp * 16 + g;

    // Q fragments: direct word loads (pre-scaled, pre-split)
    unsigned aqh[4][4], aql[4][4];
#pragma unroll
    for (int kc = 0; kc < 4; kc++) {
        int w = kc * 8 + tig;
        aqh[kc][0] = qhg[(size_t)qrow * 32 + w];
        aqh[kc][1] = qhg[(size_t)(qrow + 8) * 32 + w];
        aqh[kc][2] = qhg[(size_t)qrow * 32 + w + 4];
        aqh[kc][3] = qhg[(size_t)(qrow + 8) * 32 + w + 4];
        aql[kc][0] = qlg[(size_t)qrow * 32 + w];
        aql[kc][1] = qlg[(size_t)(qrow + 8) * 32 + w];
        aql[kc][2] = qlg[(size_t)qrow * 32 + w + 4];
        aql[kc][3] = qlg[(size_t)(qrow + 8) * 32 + w + 4];
    }

    float o[8][4];
#pragma unroll
    for (int j = 0; j < 8; j++)
#pragma unroll
        for (int i = 0; i < 4; i++) o[j][i] = 0.f;
    float m0 = -1e30f, m1 = -1e30f, l0 = 0.f, l1 = 0.f;

    const int kp = (tid & 3) + 4 * (tid >> 5);
    const int d4b = (tid >> 2) & 7;

    for (int kt = 0; kt < TT; kt += AKT) {
        __syncthreads();
        // ---- K fill: straight uint4 copies (layout matches d-pair packing) ----
#pragma unroll
        for (int it = 0; it < 2; it++) {
            int fi = it * 256 + tid;
            int key = fi >> 3, grp = (fi & 7) * 4;
            *(uint4*)&Khi[key * 36 + grp] =
                *(const uint4*)&khg[(size_t)(kt + key) * 32 + grp];
            *(uint4*)&Klo[key * 36 + grp] =
                *(const uint4*)&klg[(size_t)(kt + key) * 32 + grp];
        }
        // ---- V fill: transpose to key-pair packing via PRMT ----
#pragma unroll
        for (int it = 0; it < 2; it++) {
            int d4 = d4b + 8 * it;
            uint2 h0 = *(const uint2*)&vhg[(size_t)(kt + 2 * kp) * 32 + 2 * d4];
            uint2 h1 = *(const uint2*)&vhg[(size_t)(kt + 2 * kp + 1) * 32 + 2 * d4];
            uint2 w0 = *(const uint2*)&vlg[(size_t)(kt + 2 * kp) * 32 + 2 * d4];
            uint2 w1 = *(const uint2*)&vlg[(size_t)(kt + 2 * kp + 1) * 32 + 2 * d4];
            int col = kp ^ (4 * (d4 & 7));
            Vthi[(4 * d4 + 0) * 36 + col] = prmt(h0.x, h1.x, 0x5410);
            Vthi[(4 * d4 + 1) * 36 + col] = prmt(h0.x, h1.x, 0x7632);
            Vthi[(4 * d4 + 2) * 36 + col] = prmt(h0.y, h1.y, 0x5410);
            Vthi[(4 * d4 + 3) * 36 + col] = prmt(h0.y, h1.y, 0x7632);
            Vtlo[(4 * d4 + 0) * 36 + col] = prmt(w0.x, w1.x, 0x5410);
            Vtlo[(4 * d4 + 1) * 36 + col] = prmt(w0.x, w1.x, 0x7632);
            Vtlo[(4 * d4 + 2) * 36 + col] = prmt(w0.y, w1.y, 0x5410);
            Vtlo[(4 * d4 + 3) * 36 + col] = prmt(w0.y, w1.y, 0x7632);
        }
        __syncthreads();

        // ---- S = Q K^T (3-pass bf16), in log2 units ----
        float sacc[8][4];
#pragma unroll
        for (int j = 0; j < 8; j++) {
#pragma unroll
            for (int i = 0; i < 4; i++) sacc[j][i] = 0.f;
            int rw = (8 * j + l7) * 36 + 4 * l3h;
            unsigned kh[4][2], kl[4][2];
            ldsm4(kh[0][0], kh[0][1], kh[1][0], kh[1][1], saddr(&Khi[rw]));
            ldsm4(kh[2][0], kh[2][1], kh[3][0], kh[3][1], saddr(&Khi[rw + 16]));
            ldsm4(kl[0][0], kl[0][1], kl[1][0], kl[1][1], saddr(&Klo[rw]));
            ldsm4(kl[2][0], kl[2][1], kl[3][0], kl[3][1], saddr(&Klo[rw + 16]));
#pragma unroll
            for (int kc = 0; kc < 4; kc++) {
                mma_bf16(sacc[j], aqh[kc], kh[kc]);
                mma_bf16(sacc[j], aqh[kc], kl[kc]);
                mma_bf16(sacc[j], aql[kc], kh[kc]);
            }
        }

        // ---- online softmax (log2 domain) ----
        float rm0 = -1e30f, rm1 = -1e30f;
#pragma unroll
        for (int j = 0; j < 8; j++) {
            rm0 = fmaxf(rm0, fmaxf(sacc[j][0], sacc[j][1]));
            rm1 = fmaxf(rm1, fmaxf(sacc[j][2], sacc[j][3]));
        }
        rm0 = fmaxf(rm0, __shfl_xor_sync(0xffffffffu, rm0, 1));
        rm0 = fmaxf(rm0, __shfl_xor_sync(0xffffffffu, rm0, 2));
        rm1 = fmaxf(rm1, __shfl_xor_sync(0xffffffffu, rm1, 1));
        rm1 = fmaxf(rm1, __shfl_xor_sync(0xffffffffu, rm1, 2));
        float nm0 = fmaxf(m0, rm0), nm1 = fmaxf(m1, rm1);
        float cr0 = ex2(m0 - nm0), cr1 = ex2(m1 - nm1);
        m0 = nm0; m1 = nm1;

        unsigned ph[4][4], pl[4][4];
        float sum0 = 0.f, sum1 = 0.f;
#pragma unroll
        for (int u = 0; u < 4; u++) {
            float p00 = ex2(sacc[2 * u][0] - m0);
            float p01 = ex2(sacc[2 * u][1] - m0);
            float p10 = ex2(sacc[2 * u][2] - m1);
            float p11 = ex2(sacc[2 * u][3] - m1);
            float p20 = ex2(sacc[2 * u + 1][0] - m0);
            float p21 = ex2(sacc[2 * u + 1][1] - m0);
            float p30 = ex2(sacc[2 * u + 1][2] - m1);
            float p31 = ex2(sacc[2 * u + 1][3] - m1);
            sum0 += p00 + p01 + p20 + p21;
            sum1 += p10 + p11 + p30 + p31;
            split2(p00, p01, ph[u][0], pl[u][0]);
            split2(p10, p11, ph[u][1], pl[u][1]);
            split2(p20, p21, ph[u][2], pl[u][2]);
            split2(p30, p31, ph[u][3], pl[u][3]);
        }
        sum0 += __shfl_xor_sync(0xffffffffu, sum0, 1);
        sum0 += __shfl_xor_sync(0xffffffffu, sum0, 2);
        sum1 += __shfl_xor_sync(0xffffffffu, sum1, 1);
        sum1 += __shfl_xor_sync(0xffffffffu, sum1, 2);
        l0 = l0 * cr0 + sum0;
        l1 = l1 * cr1 + sum1;
#pragma unroll
        for (int j = 0; j < 8; j++) {
            o[j][0] *= cr0; o[j][1] *= cr0;
            o[j][2] *= cr1; o[j][3] *= cr1;
        }

        // ---- O += P V (3-pass bf16) ----
#pragma unroll
        for (int j = 0; j < 8; j++) {
            int drow = 8 * j + l7;
            int f = 4 * ((drow >> 2) & 7);
            int rb = drow * 36;
            unsigned vh[4][2], vl[4][2];
            ldsm4(vh[0][0], vh[0][1], vh[1][0], vh[1][1],
                  saddr(&Vthi[rb + ((4 * l3h) ^ f)]));
            ldsm4(vh[2][0], vh[2][1], vh[3][0], vh[3][1],
                  saddr(&Vthi[rb + ((16 + 4 * l3h) ^ f)]));
            ldsm4(vl[0][0], vl[0][1], vl[1][0], vl[1][1],
                  saddr(&Vtlo[rb + ((4 * l3h) ^ f)]));
            ldsm4(vl[2][0], vl[2][1], vl[3][0], vl[3][1],
                  saddr(&Vtlo[rb + ((16 + 4 * l3h) ^ f)]));
#pragma unroll
            for (int u = 0; u < 4; u++) {
                mma_bf16(o[j], ph[u], vh[u]);
                mma_bf16(o[j], ph[u], vl[u]);
                mma_bf16(o[j], pl[u], vh[u]);
            }
        }
    }

    // ---- epilogue ----
    float inv0 = 1.f / l0, inv1 = 1.f / l1;
    int b_ = bh >> 4, h = bh & 15;
    float* y0 = g_y + ((size_t)(b_ * TT + qrow)) * CC + h * HD;
    float* y1 = g_y + ((size_t)(b_ * TT + qrow + 8)) * CC + h * HD;
#pragma unroll
    for (int j = 0; j < 8; j++) {
        *(float2*)&y0[8 * j + 2 * tig] = make_float2(o[j][0] * inv0, o[j][1] * inv0);
        *(float2*)&y1[8 * j + 2 * tig] = make_float2(o[j][2] * inv1, o[j][3] * inv1);
    }
}

extern "C" void kernel_launch(void* const* d_in, const int* in_sizes, int n_in,
                              void* d_out, int out_size) {
    const float* seq    = (const float*)d_in[0];
    const float* w_attn = (const float*)d_in[1];
    const float* b_attn = (const float*)d_in[2];
    const float* w_proj = (const float*)d_in[3];
    const float* b_proj = (const float*)d_in[4];
    float* out = (float*)d_out;

    dim3 g1(C3 / GBN, BT / GBM);        // 24 x 64
    qkv_kernel<<<g1, 256>>>(seq, w_attn, b_attn);

    dim3 g2(TT / 128, BB * HH);         // 16 x 64
    attn_kernel<<<g2, 256>>>();

    dim3 g3(CC / GBN, BT / GBM);        // 8 x 64
    proj_kernel<<<g3, 256>>>(w_proj, b_proj, out);
}

// round 9
// speedup vs baseline: 3.4084x; 1.0139x over previous
#include <cuda_runtime.h>
#include <cuda_bf16.h>
#include <cuda_fp16.h>
#include <math.h>

#define BB 4
#define TT 2048
#define CC 1024
#define HH 16
#define HD 64
#define BT (BB*TT)
#define C3 (3*CC)

// q pre-scale: (1/sqrt(64)) * log2(e), folded in at qkv epilogue
#define QSCALE 0.18033688011112042f

// Scratch (device globals: allocation-guard safe).
// q/k stored as pre-split bf16 hi/lo planes; v as pre-split fp16 hi/lo planes.
// Packed d-pairs: [b*H+h][t][32 words]
__device__ unsigned g_qhi[BB*HH*TT*32];
__device__ unsigned g_qlo[BB*HH*TT*32];
__device__ unsigned g_khi[BB*HH*TT*32];
__device__ unsigned g_klo[BB*HH*TT*32];
__device__ unsigned g_vhi[BB*HH*TT*32];   // fp16 content
__device__ unsigned g_vlo[BB*HH*TT*32];   // fp16 content
__device__ float g_y[BT*CC];

// ---------------- common helpers ----------------
__device__ __forceinline__ unsigned f2tf32(float x) {
    unsigned r;
    asm("cvt.rna.tf32.f32 %0, %1;" : "=r"(r) : "f"(x));
    return r;
}

__device__ __forceinline__ void mma_tf32(float* c, const unsigned* a, const unsigned* b) {
    asm volatile(
        "mma.sync.aligned.m16n8k8.row.col.f32.tf32.tf32.f32 "
        "{%0,%1,%2,%3}, {%4,%5,%6,%7}, {%8,%9}, {%0,%1,%2,%3};"
        : "+f"(c[0]), "+f"(c[1]), "+f"(c[2]), "+f"(c[3])
        : "r"(a[0]), "r"(a[1]), "r"(a[2]), "r"(a[3]), "r"(b[0]), "r"(b[1]));
}

__device__ __forceinline__ void mma_bf16(float* c, const unsigned* a, const unsigned* b) {
    asm volatile(
        "mma.sync.aligned.m16n8k16.row.col.f32.bf16.bf16.f32 "
        "{%0,%1,%2,%3}, {%4,%5,%6,%7}, {%8,%9}, {%0,%1,%2,%3};"
        : "+f"(c[0]), "+f"(c[1]), "+f"(c[2]), "+f"(c[3])
        : "r"(a[0]), "r"(a[1]), "r"(a[2]), "r"(a[3]), "r"(b[0]), "r"(b[1]));
}

__device__ __forceinline__ void mma_f16(float* c, const unsigned* a, const unsigned* b) {
    asm volatile(
        "mma.sync.aligned.m16n8k16.row.col.f32.f16.f16.f32 "
        "{%0,%1,%2,%3}, {%4,%5,%6,%7}, {%8,%9}, {%0,%1,%2,%3};"
        : "+f"(c[0]), "+f"(c[1]), "+f"(c[2]), "+f"(c[3])
        : "r"(a[0]), "r"(a[1]), "r"(a[2]), "r"(a[3]), "r"(b[0]), "r"(b[1]));
}

// Split (a0,a1) into packed bf16x2 hi and lo: hi ~ bf16(a), lo ~ bf16(a-hi).
__device__ __forceinline__ void split2(float a0, float a1, unsigned& hi, unsigned& lo) {
    unsigned h;
    asm("cvt.rn.bf16x2.f32 %0, %1, %2;" : "=r"(h) : "f"(a1), "f"(a0));
    float h0 = __uint_as_float(h << 16);
    float h1 = __uint_as_float(h & 0xffff0000u);
    unsigned l;
    float r0 = a0 - h0, r1 = a1 - h1;
    asm("cvt.rn.bf16x2.f32 %0, %1, %2;" : "=r"(l) : "f"(r1), "f"(r0));
    hi = h; lo = l;
}

// fp16 variant: hi ~ fp16(a), lo ~ fp16(a-hi). Packed low16=a0, high16=a1.
__device__ __forceinline__ void split2h(float a0, float a1, unsigned& hi, unsigned& lo) {
    unsigned h;
    asm("cvt.rn.f16x2.f32 %0, %1, %2;" : "=r"(h) : "f"(a1), "f"(a0));
    __half2 hh = *reinterpret_cast<__half2*>(&h);
    float h0 = __low2float(hh), h1 = __high2float(hh);
    unsigned l;
    float r0 = a0 - h0, r1 = a1 - h1;
    asm("cvt.rn.f16x2.f32 %0, %1, %2;" : "=r"(l) : "f"(r1), "f"(r0));
    hi = h; lo = l;
}

__device__ __forceinline__ unsigned packh2(float a0, float a1) {
    unsigned r;
    asm("cvt.rn.f16x2.f32 %0, %1, %2;" : "=r"(r) : "f"(a1), "f"(a0));
    return r;
}

__device__ __forceinline__ unsigned saddr(const void* p) {
    return (unsigned)__cvta_generic_to_shared(p);
}

__device__ __forceinline__ void ldsm4(unsigned& r0, unsigned& r1, unsigned& r2,
                                      unsigned& r3, unsigned a) {
    asm volatile("ldmatrix.sync.aligned.m8n8.x4.shared.b16 {%0,%1,%2,%3}, [%4];"
                 : "=r"(r0), "=r"(r1), "=r"(r2), "=r"(r3) : "r"(a));
}

__device__ __forceinline__ unsigned prmt(unsigned a, unsigned b, unsigned sel) {
    unsigned r;
    asm("prmt.b32 %0, %1, %2, %3;" : "=r"(r) : "r"(a), "r"(b), "r"(sel));
    return r;
}

__device__ __forceinline__ float ex2(float x) {
    float r;
    asm("ex2.approx.f32 %0, %1;" : "=f"(r) : "f"(x));
    return r;
}

// ---------------- tf32 tensor-core GEMM, software-pipelined (R5) ----------------
#define GBM 128
#define GBN 128
#define GBK 16
#define AS_STRIDE 20
#define BS_STRIDE 136
#define ASZ (GBM * AS_STRIDE)
#define BSZ (GBK * BS_STRIDE)
#define NSTG (CC / GBK)

__device__ __forceinline__ void gemm_sts(unsigned* Asu, unsigned* Bsu, int buf,
                                         const float4* pa, const float4* pb,
                                         const int* m_, const int* c4_,
                                         const int* kk_, const int* n4_) {
#pragma unroll
    for (int it = 0; it < 2; it++) {
        uint4 at;
        at.x = f2tf32(pa[it].x); at.y = f2tf32(pa[it].y);
        at.z = f2tf32(pa[it].z); at.w = f2tf32(pa[it].w);
        *(uint4*)&Asu[buf * ASZ + m_[it] * AS_STRIDE + c4_[it]] = at;
        uint4 bt;
        bt.x = f2tf32(pb[it].x); bt.y = f2tf32(pb[it].y);
        bt.z = f2tf32(pb[it].z); bt.w = f2tf32(pb[it].w);
        *(uint4*)&Bsu[buf * BSZ + kk_[it] * BS_STRIDE + n4_[it]] = bt;
    }
}

__device__ __forceinline__ void gemm_tile_tf32(
    const float* __restrict__ A, int lda,
    const float* __restrict__ W, int ldw,
    int bm0, int bn0,
    unsigned* Asu, unsigned* Bsu,
    float acc[2][8][4])
{
    int tid = threadIdx.x;
    int wid = tid >> 5, lane = tid & 31;
    int wm = wid & 3, wn = wid >> 2;
    int g = lane >> 2, tig = lane & 3;

    int m_[2], c4_[2], kk_[2], n4_[2];
#pragma unroll
    for (int it = 0; it < 2; it++) {
        int fi = it * 256 + tid;
        m_[it] = fi >> 2;
        c4_[it] = (fi & 3) * 4;
        kk_[it] = fi >> 5;
        n4_[it] = (fi & 31) * 4;
    }

    float4 pa[2], pb[2];
#pragma unroll
    for (int it = 0; it < 2; it++) {
        pa[it] = *(const float4*)&A[(size_t)(bm0 + m_[it]) * lda + c4_[it]];
        pb[it] = *(const float4*)&W[(size_t)kk_[it] * ldw + bn0 + n4_[it]];
    }
    gemm_sts(Asu, Bsu, 0, pa, pb, m_, c4_, kk_, n4_);
    __syncthreads();

#pragma unroll 2
    for (int s = 0; s < NSTG; s++) {
        int cur = s & 1;
        if (s + 1 < NSTG) {
            int k0 = (s + 1) * GBK;
#pragma unroll
            for (int it = 0; it < 2; it++) {
                pa[it] = *(const float4*)&A[(size_t)(bm0 + m_[it]) * lda + k0 + c4_[it]];
                pb[it] = *(const float4*)&W[(size_t)(k0 + kk_[it]) * ldw + bn0 + n4_[it]];
            }
        }
        const unsigned* Ac = Asu + cur * ASZ;
        const unsigned* Bc = Bsu + cur * BSZ;
#pragma unroll
        for (int kc = 0; kc < GBK; kc += 8) {
            unsigned a_frag[2][4];
#pragma unroll
            for (int im = 0; im < 2; im++) {
                int rm = wm * 32 + im * 16 + g;
                a_frag[im][0] = Ac[rm * AS_STRIDE + kc + tig];
                a_frag[im][1] = Ac[(rm + 8) * AS_STRIDE + kc + tig];
                a_frag[im][2] = Ac[rm * AS_STRIDE + kc + tig + 4];
                a_frag[im][3] = Ac[(rm + 8) * AS_STRIDE + kc + tig + 4];
            }
            unsigned b_frag[8][2];
#pragma unroll
            for (int jn = 0; jn < 8; jn++) {
                int n = wn * 64 + jn * 8 + g;
                b_frag[jn][0] = Bc[(kc + tig) * BS_STRIDE + n];
                b_frag[jn][1] = Bc[(kc + tig + 4) * BS_STRIDE + n];
            }
#pragma unroll
            for (int im = 0; im < 2; im++)
#pragma unroll
                for (int jn = 0; jn < 8; jn++)
                    mma_tf32(acc[im][jn], a_frag[im], b_frag[jn]);
        }
        if (s + 1 < NSTG)
            gemm_sts(Asu, Bsu, cur ^ 1, pa, pb, m_, c4_, kk_, n4_);
        __syncthreads();
    }
}

// QKV: seq @ w_attn + bias -> pre-split planes (q/k bf16, v fp16; q pre-scaled)
__global__ __launch_bounds__(256, 2) void qkv_kernel(const float* __restrict__ A,
                                                     const float* __restrict__ W,
                                                     const float* __restrict__ bias) {
    __shared__ unsigned Asu[2 * ASZ];
    __shared__ unsigned Bsu[2 * BSZ];
    int bn0 = blockIdx.x * GBN;
    int bm0 = blockIdx.y * GBM;
    float acc[2][8][4] = {};
    gemm_tile_tf32(A, CC, W, C3, bm0, bn0, Asu, Bsu, acc);

    int tid = threadIdx.x;
    int wid = tid >> 5, lane = tid & 31;
    int wm = wid & 3, wn = wid >> 2;
    int g = lane >> 2, tig = lane & 3;
#pragma unroll
    for (int jn = 0; jn < 8; jn++) {
        int n0 = bn0 + wn * 64 + jn * 8 + 2 * tig;    // even -> d-pair aligned
        int which = n0 / CC;
        int nl = n0 % CC;
        int h = nl / HD;
        int word = (nl % HD) >> 1;
        unsigned* dsthi = (which == 0) ? g_qhi : ((which == 1) ? g_khi : g_vhi);
        unsigned* dstlo = (which == 0) ? g_qlo : ((which == 1) ? g_klo : g_vlo);
        float b0v = bias[n0], b1v = bias[n0 + 1];
#pragma unroll
        for (int im = 0; im < 2; im++) {
            int r0 = bm0 + wm * 32 + im * 16 + g;
#pragma unroll
            for (int half = 0; half < 2; half++) {
                int r = r0 + half * 8;
                int b_ = r / TT, t = r % TT;
                float v0 = acc[im][jn][half * 2 + 0] + b0v;
                float v1 = acc[im][jn][half * 2 + 1] + b1v;
                if (which == 0) { v0 *= QSCALE; v1 *= QSCALE; }
                unsigned hi, lo;
                if (which == 2) split2h(v0, v1, hi, lo);   // v -> fp16 planes
                else            split2(v0, v1, hi, lo);    // q/k -> bf16 planes
                size_t idx = ((size_t)(b_ * HH + h) * TT + t) * 32 + word;
                dsthi[idx] = hi;
                dstlo[idx] = lo;
            }
        }
    }
}

// Proj: g_y[BT,CC] @ w_proj[CC,CC] + bias -> out (unchanged from R5)
__global__ __launch_bounds__(256, 2) void proj_kernel(const float* __restrict__ W,
                                                      const float* __restrict__ bias,
                                                      float* __restrict__ out) {
    __shared__ unsigned Asu[2 * ASZ];
    __shared__ unsigned Bsu[2 * BSZ];
    int bn0 = blockIdx.x * GBN;
    int bm0 = blockIdx.y * GBM;
    float acc[2][8][4] = {};
    gemm_tile_tf32(g_y, CC, W, CC, bm0, bn0, Asu, Bsu, acc);

    int tid = threadIdx.x;
    int wid = tid >> 5, lane = tid & 31;
    int wm = wid & 3, wn = wid >> 2;
    int g = lane >> 2, tig = lane & 3;
#pragma unroll
    for (int jn = 0; jn < 8; jn++) {
        int n0 = bn0 + wn * 64 + jn * 8 + 2 * tig;
        float b0v = bias[n0], b1v = bias[n0 + 1];
#pragma unroll
        for (int im = 0; im < 2; im++) {
            int r0 = bm0 + wm * 32 + im * 16 + g;
#pragma unroll
            for (int half = 0; half < 2; half++) {
                int r = r0 + half * 8;
                float2 v2 = make_float2(acc[im][jn][half * 2 + 0] + b0v,
                                        acc[im][jn][half * 2 + 1] + b1v);
                *(float2*)&out[(size_t)r * CC + n0] = v2;
            }
        }
    }
}

// ---------------- tensor-core flash attention ----------------
// QK: bf16 3-pass. PV: fp16 2-pass (P single fp16, V pre-split fp16 hi/lo).
// Softmax in log2 domain (q pre-scaled by 0.125*log2e), ex2.approx.
#define AKT 64

__global__ __launch_bounds__(256, 2) void attn_kernel() {
    __shared__ __align__(128) unsigned Khi[AKT * 36];
    __shared__ __align__(128) unsigned Klo[AKT * 36];
    __shared__ __align__(128) unsigned Vthi[HD * 36];
    __shared__ __align__(128) unsigned Vtlo[HD * 36];

    const int tid = threadIdx.x;
    const int warp = tid >> 5, lane = tid & 31;
    const int g = lane >> 2, tig = lane & 3;
    const int l7 = lane & 7, l3h = lane >> 3;
    const int bh = blockIdx.y;
    const int q0 = blockIdx.x * 128;
    const unsigned* qhg = g_qhi + (size_t)bh * TT * 32;
    const unsigned* qlg = g_qlo + (size_t)bh * TT * 32;
    const unsigned* khg = g_khi + (size_t)bh * TT * 32;
    const unsigned* klg = g_klo + (size_t)bh * TT * 32;
    const unsigned* vhg = g_vhi + (size_t)bh * TT * 32;
    const unsigned* vlg = g_vlo + (size_t)bh * TT * 32;
    const int qrow = q0 + warp * 16 + g;

    // Q fragments: direct word loads (pre-scaled, pre-split)
    unsigned aqh[4][4], aql[4][4];
#pragma unroll
    for (int kc = 0; kc < 4; kc++) {
        int w = kc * 8 + tig;
        aqh[kc][0] = qhg[(size_t)qrow * 32 + w];
        aqh[kc][1] = qhg[(size_t)(qrow + 8) * 32 + w];
        aqh[kc][2] = qhg[(size_t)qrow * 32 + w + 4];
        aqh[kc][3] = qhg[(size_t)(qrow + 8) * 32 + w + 4];
        aql[kc][0] = qlg[(size_t)qrow * 32 + w];
        aql[kc][1] = qlg[(size_t)(qrow + 8) * 32 + w];
        aql[kc][2] = qlg[(size_t)qrow * 32 + w + 4];
        aql[kc][3] = qlg[(size_t)(qrow + 8) * 32 + w + 4];
    }

    float o[8][4];
#pragma unroll
    for (int j = 0; j < 8; j++)
#pragma unroll
        for (int i = 0; i < 4; i++) o[j][i] = 0.f;
    float m0 = -1e30f, m1 = -1e30f, l0 = 0.f, l1 = 0.f;

    const int kp = (tid & 3) + 4 * (tid >> 5);
    const int d4b = (tid >> 2) & 7;

    for (int kt = 0; kt < TT; kt += AKT) {
        __syncthreads();
        // ---- K fill: straight uint4 copies ----
#pragma unroll
        for (int it = 0; it < 2; it++) {
            int fi = it * 256 + tid;
            int key = fi >> 3, grp = (fi & 7) * 4;
            *(uint4*)&Khi[key * 36 + grp] =
                *(const uint4*)&khg[(size_t)(kt + key) * 32 + grp];
            *(uint4*)&Klo[key * 36 + grp] =
                *(const uint4*)&klg[(size_t)(kt + key) * 32 + grp];
        }
        // ---- V fill: transpose to key-pair packing via PRMT (fp16 bytes) ----
#pragma unroll
        for (int it = 0; it < 2; it++) {
            int d4 = d4b + 8 * it;
            uint2 h0 = *(const uint2*)&vhg[(size_t)(kt + 2 * kp) * 32 + 2 * d4];
            uint2 h1 = *(const uint2*)&vhg[(size_t)(kt + 2 * kp + 1) * 32 + 2 * d4];
            uint2 w0 = *(const uint2*)&vlg[(size_t)(kt + 2 * kp) * 32 + 2 * d4];
            uint2 w1 = *(const uint2*)&vlg[(size_t)(kt + 2 * kp + 1) * 32 + 2 * d4];
            int col = kp ^ (4 * (d4 & 7));
            Vthi[(4 * d4 + 0) * 36 + col] = prmt(h0.x, h1.x, 0x5410);
            Vthi[(4 * d4 + 1) * 36 + col] = prmt(h0.x, h1.x, 0x7632);
            Vthi[(4 * d4 + 2) * 36 + col] = prmt(h0.y, h1.y, 0x5410);
            Vthi[(4 * d4 + 3) * 36 + col] = prmt(h0.y, h1.y, 0x7632);
            Vtlo[(4 * d4 + 0) * 36 + col] = prmt(w0.x, w1.x, 0x5410);
            Vtlo[(4 * d4 + 1) * 36 + col] = prmt(w0.x, w1.x, 0x7632);
            Vtlo[(4 * d4 + 2) * 36 + col] = prmt(w0.y, w1.y, 0x5410);
            Vtlo[(4 * d4 + 3) * 36 + col] = prmt(w0.y, w1.y, 0x7632);
        }
        __syncthreads();

        // ---- S = Q K^T (3-pass bf16), in log2 units ----
        float sacc[8][4];
#pragma unroll
        for (int j = 0; j < 8; j++) {
#pragma unroll
            for (int i = 0; i < 4; i++) sacc[j][i] = 0.f;
            int rw = (8 * j + l7) * 36 + 4 * l3h;
            unsigned kh[4][2], kl[4][2];
            ldsm4(kh[0][0], kh[0][1], kh[1][0], kh[1][1], saddr(&Khi[rw]));
            ldsm4(kh[2][0], kh[2][1], kh[3][0], kh[3][1], saddr(&Khi[rw + 16]));
            ldsm4(kl[0][0], kl[0][1], kl[1][0], kl[1][1], saddr(&Klo[rw]));
            ldsm4(kl[2][0], kl[2][1], kl[3][0], kl[3][1], saddr(&Klo[rw + 16]));
#pragma unroll
            for (int kc = 0; kc < 4; kc++) {
                mma_bf16(sacc[j], aqh[kc], kh[kc]);
                mma_bf16(sacc[j], aqh[kc], kl[kc]);
                mma_bf16(sacc[j], aql[kc], kh[kc]);
            }
        }

        // ---- online softmax (log2 domain) ----
        float rm0 = -1e30f, rm1 = -1e30f;
#pragma unroll
        for (int j = 0; j < 8; j++) {
            rm0 = fmaxf(rm0, fmaxf(sacc[j][0], sacc[j][1]));
            rm1 = fmaxf(rm1, fmaxf(sacc[j][2], sacc[j][3]));
        }
        rm0 = fmaxf(rm0, __shfl_xor_sync(0xffffffffu, rm0, 1));
        rm0 = fmaxf(rm0, __shfl_xor_sync(0xffffffffu, rm0, 2));
        rm1 = fmaxf(rm1, __shfl_xor_sync(0xffffffffu, rm1, 1));
        rm1 = fmaxf(rm1, __shfl_xor_sync(0xffffffffu, rm1, 2));
        float nm0 = fmaxf(m0, rm0), nm1 = fmaxf(m1, rm1);
        float cr0 = ex2(m0 - nm0), cr1 = ex2(m1 - nm1);
        m0 = nm0; m1 = nm1;

        unsigned p[4][4];
        float sum0 = 0.f, sum1 = 0.f;
#pragma unroll
        for (int u = 0; u < 4; u++) {
            float p00 = ex2(sacc[2 * u][0] - m0);
            float p01 = ex2(sacc[2 * u][1] - m0);
            float p10 = ex2(sacc[2 * u][2] - m1);
            float p11 = ex2(sacc[2 * u][3] - m1);
            float p20 = ex2(sacc[2 * u + 1][0] - m0);
            float p21 = ex2(sacc[2 * u + 1][1] - m0);
            float p30 = ex2(sacc[2 * u + 1][2] - m1);
            float p31 = ex2(sacc[2 * u + 1][3] - m1);
            sum0 += p00 + p01 + p20 + p21;
            sum1 += p10 + p11 + p30 + p31;
            p[u][0] = packh2(p00, p01);
            p[u][1] = packh2(p10, p11);
            p[u][2] = packh2(p20, p21);
            p[u][3] = packh2(p30, p31);
        }
        sum0 += __shfl_xor_sync(0xffffffffu, sum0, 1);
        sum0 += __shfl_xor_sync(0xffffffffu, sum0, 2);
        sum1 += __shfl_xor_sync(0xffffffffu, sum1, 1);
        sum1 += __shfl_xor_sync(0xffffffffu, sum1, 2);
        l0 = l0 * cr0 + sum0;
        l1 = l1 * cr1 + sum1;
#pragma unroll
        for (int j = 0; j < 8; j++) {
            o[j][0] *= cr0; o[j][1] *= cr0;
            o[j][2] *= cr1; o[j][3] *= cr1;
        }

        // ---- O += P V (2-pass fp16: P*(vh + vl)) ----
#pragma unroll
        for (int j = 0; j < 8; j++) {
            int drow = 8 * j + l7;
            int f = 4 * ((drow >> 2) & 7);
            int rb = drow * 36;
            unsigned vh[4][2], vl[4][2];
            ldsm4(vh[0][0], vh[0][1], vh[1][0], vh[1][1],
                  saddr(&Vthi[rb + ((4 * l3h) ^ f)]));
            ldsm4(vh[2][0], vh[2][1], vh[3][0], vh[3][1],
                  saddr(&Vthi[rb + ((16 + 4 * l3h) ^ f)]));
            ldsm4(vl[0][0], vl[0][1], vl[1][0], vl[1][1],
                  saddr(&Vtlo[rb + ((4 * l3h) ^ f)]));
            ldsm4(vl[2][0], vl[2][1], vl[3][0], vl[3][1],
                  saddr(&Vtlo[rb + ((16 + 4 * l3h) ^ f)]));
#pragma unroll
            for (int u = 0; u < 4; u++) {
                mma_f16(o[j], p[u], vh[u]);
                mma_f16(o[j], p[u], vl[u]);
            }
        }
    }

    // ---- epilogue ----
    float inv0 = 1.f / l0, inv1 = 1.f / l1;
    int b_ = bh >> 4, h = bh & 15;
    float* y0 = g_y + ((size_t)(b_ * TT + qrow)) * CC + h * HD;
    float* y1 = g_y + ((size_t)(b_ * TT + qrow + 8)) * CC + h * HD;
#pragma unroll
    for (int j = 0; j < 8; j++) {
        *(float2*)&y0[8 * j + 2 * tig] = make_float2(o[j][0] * inv0, o[j][1] * inv0);
        *(float2*)&y1[8 * j + 2 * tig] = make_float2(o[j][2] * inv1, o[j][3] * inv1);
    }
}

extern "C" void kernel_launch(void* const* d_in, const int* in_sizes, int n_in,
                              void* d_out, int out_size) {
    const float* seq    = (const float*)d_in[0];
    const float* w_attn = (const float*)d_in[1];
    const float* b_attn = (const float*)d_in[2];
    const float* w_proj = (const float*)d_in[3];
    const float* b_proj = (const float*)d_in[4];
    float* out = (float*)d_out;

    dim3 g1(C3 / GBN, BT / GBM);        // 24 x 64
    qkv_kernel<<<g1, 256>>>(seq, w_attn, b_attn);

    dim3 g2(TT / 128, BB * HH);         // 16 x 64
    attn_kernel<<<g2, 256>>>();

    dim3 g3(CC / GBN, BT / GBM);        // 8 x 64
    proj_kernel<<<g3, 256>>>(w_proj, b_proj, out);
}

// round 11
// speedup vs baseline: 3.8101x; 1.1179x over previous
#include <cuda_runtime.h>
#include <cuda_bf16.h>
#include <cuda_fp16.h>
#include <math.h>

#define BB 4
#define TT 2048
#define CC 1024
#define HH 16
#define HD 64
#define BT (BB*TT)
#define C3 (3*CC)

// q pre-scale: (1/sqrt(64)) * log2(e), folded in at qkv epilogue
#define QSCALE 0.18033688011112042f

// Scratch (device globals: allocation-guard safe).
// q/k: pre-split bf16 hi/lo planes, packed d-pairs [bh][t][32 words].
// v:   pre-split fp16 hi/lo planes in per-64-key-tile TRANSPOSED layout
//      [bh][tile][d(64)][colkey(32)] where colkey = kp ^ (4*((d>>2)&7)),
//      word = (key 2kp low16, key 2kp+1 high16) for dim d.
__device__ unsigned g_qhi[BB*HH*TT*32];
__device__ unsigned g_qlo[BB*HH*TT*32];
__device__ unsigned g_khi[BB*HH*TT*32];
__device__ unsigned g_klo[BB*HH*TT*32];
__device__ unsigned g_vhi[BB*HH*TT*32];   // fp16, tile-transposed
__device__ unsigned g_vlo[BB*HH*TT*32];   // fp16, tile-transposed
__device__ float g_y[BT*CC];

// ---------------- common helpers ----------------
__device__ __forceinline__ unsigned f2tf32(float x) {
    unsigned r;
    asm("cvt.rna.tf32.f32 %0, %1;" : "=r"(r) : "f"(x));
    return r;
}

__device__ __forceinline__ void mma_tf32(float* c, const unsigned* a, const unsigned* b) {
    asm volatile(
        "mma.sync.aligned.m16n8k8.row.col.f32.tf32.tf32.f32 "
        "{%0,%1,%2,%3}, {%4,%5,%6,%7}, {%8,%9}, {%0,%1,%2,%3};"
        : "+f"(c[0]), "+f"(c[1]), "+f"(c[2]), "+f"(c[3])
        : "r"(a[0]), "r"(a[1]), "r"(a[2]), "r"(a[3]), "r"(b[0]), "r"(b[1]));
}

__device__ __forceinline__ void mma_bf16(float* c, const unsigned* a, const unsigned* b) {
    asm volatile(
        "mma.sync.aligned.m16n8k16.row.col.f32.bf16.bf16.f32 "
        "{%0,%1,%2,%3}, {%4,%5,%6,%7}, {%8,%9}, {%0,%1,%2,%3};"
        : "+f"(c[0]), "+f"(c[1]), "+f"(c[2]), "+f"(c[3])
        : "r"(a[0]), "r"(a[1]), "r"(a[2]), "r"(a[3]), "r"(b[0]), "r"(b[1]));
}

__device__ __forceinline__ void mma_f16(float* c, const unsigned* a, const unsigned* b) {
    asm volatile(
        "mma.sync.aligned.m16n8k16.row.col.f32.f16.f16.f32 "
        "{%0,%1,%2,%3}, {%4,%5,%6,%7}, {%8,%9}, {%0,%1,%2,%3};"
        : "+f"(c[0]), "+f"(c[1]), "+f"(c[2]), "+f"(c[3])
        : "r"(a[0]), "r"(a[1]), "r"(a[2]), "r"(a[3]), "r"(b[0]), "r"(b[1]));
}

// Split (a0,a1) into packed bf16x2 hi and lo: hi ~ bf16(a), lo ~ bf16(a-hi).
__device__ __forceinline__ void split2(float a0, float a1, unsigned& hi, unsigned& lo) {
    unsigned h;
    asm("cvt.rn.bf16x2.f32 %0, %1, %2;" : "=r"(h) : "f"(a1), "f"(a0));
    float h0 = __uint_as_float(h << 16);
    float h1 = __uint_as_float(h & 0xffff0000u);
    unsigned l;
    float r0 = a0 - h0, r1 = a1 - h1;
    asm("cvt.rn.bf16x2.f32 %0, %1, %2;" : "=r"(l) : "f"(r1), "f"(r0));
    hi = h; lo = l;
}

// fp16 variant: hi ~ fp16(a), lo ~ fp16(a-hi). Packed low16=a0, high16=a1.
__device__ __forceinline__ void split2h(float a0, float a1, unsigned& hi, unsigned& lo) {
    unsigned h;
    asm("cvt.rn.f16x2.f32 %0, %1, %2;" : "=r"(h) : "f"(a1), "f"(a0));
    __half2 hh = *reinterpret_cast<__half2*>(&h);
    float h0 = __low2float(hh), h1 = __high2float(hh);
    unsigned l;
    float r0 = a0 - h0, r1 = a1 - h1;
    asm("cvt.rn.f16x2.f32 %0, %1, %2;" : "=r"(l) : "f"(r1), "f"(r0));
    hi = h; lo = l;
}

__device__ __forceinline__ unsigned packh2(float a0, float a1) {
    unsigned r;
    asm("cvt.rn.f16x2.f32 %0, %1, %2;" : "=r"(r) : "f"(a1), "f"(a0));
    return r;
}

__device__ __forceinline__ unsigned saddr(const void* p) {
    return (unsigned)__cvta_generic_to_shared(p);
}

__device__ __forceinline__ void ldsm4(unsigned& r0, unsigned& r1, unsigned& r2,
                                      unsigned& r3, unsigned a) {
    asm volatile("ldmatrix.sync.aligned.m8n8.x4.shared.b16 {%0,%1,%2,%3}, [%4];"
                 : "=r"(r0), "=r"(r1), "=r"(r2), "=r"(r3) : "r"(a));
}

__device__ __forceinline__ float ex2(float x) {
    float r;
    asm("ex2.approx.f32 %0, %1;" : "=f"(r) : "f"(x));
    return r;
}

__device__ __forceinline__ void cp16(unsigned dst, const void* src) {
    asm volatile("cp.async.cg.shared.global [%0], [%1], 16;"
                 :: "r"(dst), "l"(src) : "memory");
}

// ---------------- tf32 tensor-core GEMM, software-pipelined (R5) ----------------
#define GBM 128
#define GBN 128
#define GBK 16
#define AS_STRIDE 20
#define BS_STRIDE 136
#define ASZ (GBM * AS_STRIDE)
#define BSZ (GBK * BS_STRIDE)
#define NSTG (CC / GBK)

__device__ __forceinline__ void gemm_sts(unsigned* Asu, unsigned* Bsu, int buf,
                                         const float4* pa, const float4* pb,
                                         const int* m_, const int* c4_,
                                         const int* kk_, const int* n4_) {
#pragma unroll
    for (int it = 0; it < 2; it++) {
        uint4 at;
        at.x = f2tf32(pa[it].x); at.y = f2tf32(pa[it].y);
        at.z = f2tf32(pa[it].z); at.w = f2tf32(pa[it].w);
        *(uint4*)&Asu[buf * ASZ + m_[it] * AS_STRIDE + c4_[it]] = at;
        uint4 bt;
        bt.x = f2tf32(pb[it].x); bt.y = f2tf32(pb[it].y);
        bt.z = f2tf32(pb[it].z); bt.w = f2tf32(pb[it].w);
        *(uint4*)&Bsu[buf * BSZ + kk_[it] * BS_STRIDE + n4_[it]] = bt;
    }
}

__device__ __forceinline__ void gemm_tile_tf32(
    const float* __restrict__ A, int lda,
    const float* __restrict__ W, int ldw,
    int bm0, int bn0,
    unsigned* Asu, unsigned* Bsu,
    float acc[2][8][4])
{
    int tid = threadIdx.x;
    int wid = tid >> 5, lane = tid & 31;
    int wm = wid & 3, wn = wid >> 2;
    int g = lane >> 2, tig = lane & 3;

    int m_[2], c4_[2], kk_[2], n4_[2];
#pragma unroll
    for (int it = 0; it < 2; it++) {
        int fi = it * 256 + tid;
        m_[it] = fi >> 2;
        c4_[it] = (fi & 3) * 4;
        kk_[it] = fi >> 5;
        n4_[it] = (fi & 31) * 4;
    }

    float4 pa[2], pb[2];
#pragma unroll
    for (int it = 0; it < 2; it++) {
        pa[it] = *(const float4*)&A[(size_t)(bm0 + m_[it]) * lda + c4_[it]];
        pb[it] = *(const float4*)&W[(size_t)kk_[it] * ldw + bn0 + n4_[it]];
    }
    gemm_sts(Asu, Bsu, 0, pa, pb, m_, c4_, kk_, n4_);
    __syncthreads();

#pragma unroll 2
    for (int s = 0; s < NSTG; s++) {
        int cur = s & 1;
        if (s + 1 < NSTG) {
            int k0 = (s + 1) * GBK;
#pragma unroll
            for (int it = 0; it < 2; it++) {
                pa[it] = *(const float4*)&A[(size_t)(bm0 + m_[it]) * lda + k0 + c4_[it]];
                pb[it] = *(const float4*)&W[(size_t)(k0 + kk_[it]) * ldw + bn0 + n4_[it]];
            }
        }
        const unsigned* Ac = Asu + cur * ASZ;
        const unsigned* Bc = Bsu + cur * BSZ;
#pragma unroll
        for (int kc = 0; kc < GBK; kc += 8) {
            unsigned a_frag[2][4];
#pragma unroll
            for (int im = 0; im < 2; im++) {
                int rm = wm * 32 + im * 16 + g;
                a_frag[im][0] = Ac[rm * AS_STRIDE + kc + tig];
                a_frag[im][1] = Ac[(rm + 8) * AS_STRIDE + kc + tig];
                a_frag[im][2] = Ac[rm * AS_STRIDE + kc + tig + 4];
                a_frag[im][3] = Ac[(rm + 8) * AS_STRIDE + kc + tig + 4];
            }
            unsigned b_frag[8][2];
#pragma unroll
            for (int jn = 0; jn < 8; jn++) {
                int n = wn * 64 + jn * 8 + g;
                b_frag[jn][0] = Bc[(kc + tig) * BS_STRIDE + n];
                b_frag[jn][1] = Bc[(kc + tig + 4) * BS_STRIDE + n];
            }
#pragma unroll
            for (int im = 0; im < 2; im++)
#pragma unroll
                for (int jn = 0; jn < 8; jn++)
                    mma_tf32(acc[im][jn], a_frag[im], b_frag[jn]);
        }
        if (s + 1 < NSTG)
            gemm_sts(Asu, Bsu, cur ^ 1, pa, pb, m_, c4_, kk_, n4_);
        __syncthreads();
    }
}

// QKV: seq @ w_attn + bias -> pre-split planes (q/k bf16 d-pair; v fp16 tile-transposed)
__global__ __launch_bounds__(256, 2) void qkv_kernel(const float* __restrict__ A,
                                                     const float* __restrict__ W,
                                                     const float* __restrict__ bias) {
    __shared__ unsigned Asu[2 * ASZ];
    __shared__ unsigned Bsu[2 * BSZ];
    int bn0 = blockIdx.x * GBN;
    int bm0 = blockIdx.y * GBM;
    float acc[2][8][4] = {};
    gemm_tile_tf32(A, CC, W, C3, bm0, bn0, Asu, Bsu, acc);

    int tid = threadIdx.x;
    int wid = tid >> 5, lane = tid & 31;
    int wm = wid & 3, wn = wid >> 2;
    int g = lane >> 2, tig = lane & 3;
#pragma unroll
    for (int jn = 0; jn < 8; jn++) {
        int n0 = bn0 + wn * 64 + jn * 8 + 2 * tig;    // even -> d-pair aligned
        int which = n0 / CC;
        int nl = n0 % CC;
        int h = nl / HD;
        int word = (nl % HD) >> 1;
        float b0v = bias[n0], b1v = bias[n0 + 1];
#pragma unroll
        for (int im = 0; im < 2; im++) {
            int r0 = bm0 + wm * 32 + im * 16 + g;
#pragma unroll
            for (int half = 0; half < 2; half++) {
                int r = r0 + half * 8;
                int b_ = r / TT, t = r % TT;
                int bhh = b_ * HH + h;
                float v0 = acc[im][jn][half * 2 + 0] + b0v;
                float v1 = acc[im][jn][half * 2 + 1] + b1v;
                if (which == 2) {
                    // v: fp16 hi/lo u16 scatter into tile-transposed layout
                    unsigned hi, lo;
                    split2h(v0, v1, hi, lo);
                    int tile = t >> 6, kq = (t & 63) >> 1, hk = t & 1;
                    size_t base = ((size_t)bhh * 32 + tile) * 64;
                    int d0v = word * 2;
#pragma unroll
                    for (int e = 0; e < 2; e++) {
                        int d = d0v + e;
                        int col = kq ^ (4 * ((d >> 2) & 7));
                        size_t w = (base + d) * 32 + col;
                        unsigned short hv = e ? (unsigned short)(hi >> 16)
                                              : (unsigned short)(hi & 0xffffu);
                        unsigned short lv = e ? (unsigned short)(lo >> 16)
                                              : (unsigned short)(lo & 0xffffu);
                        ((unsigned short*)g_vhi)[w * 2 + hk] = hv;
                        ((unsigned short*)g_vlo)[w * 2 + hk] = lv;
                    }
                } else {
                    if (which == 0) { v0 *= QSCALE; v1 *= QSCALE; }
                    unsigned hi, lo;
                    split2(v0, v1, hi, lo);
                    unsigned* dsthi = (which == 0) ? g_qhi : g_khi;
                    unsigned* dstlo = (which == 0) ? g_qlo : g_klo;
                    size_t idx = ((size_t)bhh * TT + t) * 32 + word;
                    dsthi[idx] = hi;
                    dstlo[idx] = lo;
                }
            }
        }
    }
}

// Proj: g_y[BT,CC] @ w_proj[CC,CC] + bias -> out (unchanged)
__global__ __launch_bounds__(256, 2) void proj_kernel(const float* __restrict__ W,
                                                      const float* __restrict__ bias,
                                                      float* __restrict__ out) {
    __shared__ unsigned Asu[2 * ASZ];
    __shared__ unsigned Bsu[2 * BSZ];
    int bn0 = blockIdx.x * GBN;
    int bm0 = blockIdx.y * GBM;
    float acc[2][8][4] = {};
    gemm_tile_tf32(g_y, CC, W, CC, bm0, bn0, Asu, Bsu, acc);

    int tid = threadIdx.x;
    int wid = tid >> 5, lane = tid & 31;
    int wm = wid & 3, wn = wid >> 2;
    int g = lane >> 2, tig = lane & 3;
#pragma unroll
    for (int jn = 0; jn < 8; jn++) {
        int n0 = bn0 + wn * 64 + jn * 8 + 2 * tig;
        float b0v = bias[n0], b1v = bias[n0 + 1];
#pragma unroll
        for (int im = 0; im < 2; im++) {
            int r0 = bm0 + wm * 32 + im * 16 + g;
#pragma unroll
            for (int half = 0; half < 2; half++) {
                int r = r0 + half * 8;
                float2 v2 = make_float2(acc[im][jn][half * 2 + 0] + b0v,
                                        acc[im][jn][half * 2 + 1] + b1v);
                *(float2*)&out[(size_t)r * CC + n0] = v2;
            }
        }
    }
}

// ---------------- tensor-core flash attention, cp.async double-buffered ----------------
// QK: bf16 3-pass. PV: fp16 2-pass. Softmax log2 domain, ex2.approx.
// Tiles (K hi/lo + Vt hi/lo) stream through a 2-stage dynamic-smem ring via cp.async.
#define AKT 64
#define NT (TT / AKT)          // 32 tiles
#define ARR_B 9216             // bytes per array per stage (64 rows x 36 words)
#define STAGE_B (4 * ARR_B)    // 36864
#define ATTN_SMEM (2 * STAGE_B)

// Issue one tile's 8 cp.async per thread (2048 x 16B total).
__device__ __forceinline__ void issue_tile(unsigned sbs,
                                           const unsigned* khg, const unsigned* klg,
                                           const unsigned* vhg, const unsigned* vlg,
                                           int kt, int tid) {
    int row0 = tid >> 3;
    int ch4 = (tid & 7) * 4;
    const unsigned* vht = vhg + (size_t)(kt >> 6) * 2048;
    const unsigned* vlt = vlg + (size_t)(kt >> 6) * 2048;
#pragma unroll
    for (int hf = 0; hf < 2; hf++) {
        int row = hf * 32 + row0;
        unsigned d = sbs + (unsigned)(row * 36 + ch4) * 4u;
        cp16(d,              khg + (size_t)(kt + row) * 32 + ch4);
        cp16(d + ARR_B,      klg + (size_t)(kt + row) * 32 + ch4);
        cp16(d + 2 * ARR_B,  vht + row * 32 + ch4);
        cp16(d + 3 * ARR_B,  vlt + row * 32 + ch4);
    }
}

__global__ __launch_bounds__(256, 2) void attn_kernel() {
    extern __shared__ __align__(128) char asmem[];
    const unsigned sb = saddr(asmem);

    const int tid = threadIdx.x;
    const int warp = tid >> 5, lane = tid & 31;
    const int g = lane >> 2, tig = lane & 3;
    const int l7 = lane & 7, l3h = lane >> 3;
    const int bh = blockIdx.y;
    const int q0 = blockIdx.x * 128;
    const unsigned* qhg = g_qhi + (size_t)bh * TT * 32;
    const unsigned* qlg = g_qlo + (size_t)bh * TT * 32;
    const unsigned* khg = g_khi + (size_t)bh * TT * 32;
    const unsigned* klg = g_klo + (size_t)bh * TT * 32;
    const unsigned* vhg = g_vhi + (size_t)bh * TT * 32;
    const unsigned* vlg = g_vlo + (size_t)bh * TT * 32;
    const int qrow = q0 + warp * 16 + g;

    // Q fragments: direct word loads (pre-scaled, pre-split)
    unsigned aqh[4][4], aql[4][4];
#pragma unroll
    for (int kc = 0; kc < 4; kc++) {
        int w = kc * 8 + tig;
        aqh[kc][0] = qhg[(size_t)qrow * 32 + w];
        aqh[kc][1] = qhg[(size_t)(qrow + 8) * 32 + w];
        aqh[kc][2] = qhg[(size_t)qrow * 32 + w + 4];
        aqh[kc][3] = qhg[(size_t)(qrow + 8) * 32 + w + 4];
        aql[kc][0] = qlg[(size_t)qrow * 32 + w];
        aql[kc][1] = qlg[(size_t)(qrow + 8) * 32 + w];
        aql[kc][2] = qlg[(size_t)qrow * 32 + w + 4];
        aql[kc][3] = qlg[(size_t)(qrow + 8) * 32 + w + 4];
    }

    float o[8][4];
#pragma unroll
    for (int j = 0; j < 8; j++)
#pragma unroll
        for (int i = 0; i < 4; i++) o[j][i] = 0.f;
    float m0 = -1e30f, m1 = -1e30f, l0 = 0.f, l1 = 0.f;

    // Prologue: tile 0 in flight
    issue_tile(sb, khg, klg, vhg, vlg, 0, tid);
    asm volatile("cp.async.commit_group;" ::: "memory");

    for (int ti = 0; ti < NT; ti++) {
        const int buf = ti & 1;
        if (ti + 1 < NT) {
            issue_tile(sb + (buf ^ 1) * STAGE_B, khg, klg, vhg, vlg,
                       (ti + 1) * AKT, tid);
            asm volatile("cp.async.commit_group;" ::: "memory");
            asm volatile("cp.async.wait_group 1;" ::: "memory");
        } else {
            asm volatile("cp.async.wait_group 0;" ::: "memory");
        }
        __syncthreads();

        const unsigned sbK_hi = sb + buf * STAGE_B;
        const unsigned sbK_lo = sbK_hi + ARR_B;
        const unsigned sbV_hi = sbK_hi + 2 * ARR_B;
        const unsigned sbV_lo = sbK_hi + 3 * ARR_B;

        // ---- S = Q K^T (3-pass bf16), in log2 units ----
        float sacc[8][4];
#pragma unroll
        for (int j = 0; j < 8; j++) {
#pragma unroll
            for (int i = 0; i < 4; i++) sacc[j][i] = 0.f;
            unsigned rwb = (unsigned)((8 * j + l7) * 36 + 4 * l3h) * 4u;
            unsigned kh[4][2], kl[4][2];
            ldsm4(kh[0][0], kh[0][1], kh[1][0], kh[1][1], sbK_hi + rwb);
            ldsm4(kh[2][0], kh[2][1], kh[3][0], kh[3][1], sbK_hi + rwb + 64);
            ldsm4(kl[0][0], kl[0][1], kl[1][0], kl[1][1], sbK_lo + rwb);
            ldsm4(kl[2][0], kl[2][1], kl[3][0], kl[3][1], sbK_lo + rwb + 64);
#pragma unroll
            for (int kc = 0; kc < 4; kc++) {
                mma_bf16(sacc[j], aqh[kc], kh[kc]);
                mma_bf16(sacc[j], aqh[kc], kl[kc]);
                mma_bf16(sacc[j], aql[kc], kh[kc]);
            }
        }

        // ---- online softmax (log2 domain) ----
        float rm0 = -1e30f, rm1 = -1e30f;
#pragma unroll
        for (int j = 0; j < 8; j++) {
            rm0 = fmaxf(rm0, fmaxf(sacc[j][0], sacc[j][1]));
            rm1 = fmaxf(rm1, fmaxf(sacc[j][2], sacc[j][3]));
        }
        rm0 = fmaxf(rm0, __shfl_xor_sync(0xffffffffu, rm0, 1));
        rm0 = fmaxf(rm0, __shfl_xor_sync(0xffffffffu, rm0, 2));
        rm1 = fmaxf(rm1, __shfl_xor_sync(0xffffffffu, rm1, 1));
        rm1 = fmaxf(rm1, __shfl_xor_sync(0xffffffffu, rm1, 2));
        float nm0 = fmaxf(m0, rm0), nm1 = fmaxf(m1, rm1);
        float cr0 = ex2(m0 - nm0), cr1 = ex2(m1 - nm1);
        m0 = nm0; m1 = nm1;

        unsigned p[4][4];
        float sum0 = 0.f, sum1 = 0.f;
#pragma unroll
        for (int u = 0; u < 4; u++) {
            float p00 = ex2(sacc[2 * u][0] - m0);
            float p01 = ex2(sacc[2 * u][1] - m0);
            float p10 = ex2(sacc[2 * u][2] - m1);
            float p11 = ex2(sacc[2 * u][3] - m1);
            float p20 = ex2(sacc[2 * u + 1][0] - m0);
            float p21 = ex2(sacc[2 * u + 1][1] - m0);
            float p30 = ex2(sacc[2 * u + 1][2] - m1);
            float p31 = ex2(sacc[2 * u + 1][3] - m1);
            sum0 += p00 + p01 + p20 + p21;
            sum1 += p10 + p11 + p30 + p31;
            p[u][0] = packh2(p00, p01);
            p[u][1] = packh2(p10, p11);
            p[u][2] = packh2(p20, p21);
            p[u][3] = packh2(p30, p31);
        }
        sum0 += __shfl_xor_sync(0xffffffffu, sum0, 1);
        sum0 += __shfl_xor_sync(0xffffffffu, sum0, 2);
        sum1 += __shfl_xor_sync(0xffffffffu, sum1, 1);
        sum1 += __shfl_xor_sync(0xffffffffu, sum1, 2);
        l0 = l0 * cr0 + sum0;
        l1 = l1 * cr1 + sum1;
#pragma unroll
        for (int j = 0; j < 8; j++) {
            o[j][0] *= cr0; o[j][1] *= cr0;
            o[j][2] *= cr1; o[j][3] *= cr1;
        }

        // ---- O += P V (2-pass fp16: P*(vh + vl)) ----
#pragma unroll
        for (int j = 0; j < 8; j++) {
            int drow = 8 * j + l7;
            int f = 4 * ((drow >> 2) & 7);
            unsigned rbb = (unsigned)(drow * 36) * 4u;
            unsigned c0 = (unsigned)((4 * l3h) ^ f) * 4u;
            unsigned c1 = (unsigned)((16 + 4 * l3h) ^ f) * 4u;
            unsigned vh[4][2], vl[4][2];
            ldsm4(vh[0][0], vh[0][1], vh[1][0], vh[1][1], sbV_hi + rbb + c0);
            ldsm4(vh[2][0], vh[2][1], vh[3][0], vh[3][1], sbV_hi + rbb + c1);
            ldsm4(vl[0][0], vl[0][1], vl[1][0], vl[1][1], sbV_lo + rbb + c0);
            ldsm4(vl[2][0], vl[2][1], vl[3][0], vl[3][1], sbV_lo + rbb + c1);
#pragma unroll
            for (int u = 0; u < 4; u++) {
                mma_f16(o[j], p[u], vh[u]);
                mma_f16(o[j], p[u], vl[u]);
            }
        }
        __syncthreads();
    }

    // ---- epilogue ----
    float inv0 = 1.f / l0, inv1 = 1.f / l1;
    int b_ = bh >> 4, h = bh & 15;
    float* y0 = g_y + ((size_t)(b_ * TT + qrow)) * CC + h * HD;
    float* y1 = g_y + ((size_t)(b_ * TT + qrow + 8)) * CC + h * HD;
#pragma unroll
    for (int j = 0; j < 8; j++) {
        *(float2*)&y0[8 * j + 2 * tig] = make_float2(o[j][0] * inv0, o[j][1] * inv0);
        *(float2*)&y1[8 * j + 2 * tig] = make_float2(o[j][2] * inv1, o[j][3] * inv1);
    }
}

extern "C" void kernel_launch(void* const* d_in, const int* in_sizes, int n_in,
                              void* d_out, int out_size) {
    const float* seq    = (const float*)d_in[0];
    const float* w_attn = (const float*)d_in[1];
    const float* b_attn = (const float*)d_in[2];
    const float* w_proj = (const float*)d_in[3];
    const float* b_proj = (const float*)d_in[4];
    float* out = (float*)d_out;

    static int attr_set = 0;
    if (!attr_set) {
        cudaFuncSetAttribute(attn_kernel,
                             cudaFuncAttributeMaxDynamicSharedMemorySize, ATTN_SMEM);
        attr_set = 1;
    }

    dim3 g1(C3 / GBN, BT / GBM);        // 24 x 64
    qkv_kernel<<<g1, 256>>>(seq, w_attn, b_attn);

    dim3 g2(TT / 128, BB * HH);         // 16 x 64
    attn_kernel<<<g2, 256, ATTN_SMEM>>>();

    dim3 g3(CC / GBN, BT / GBM);        // 8 x 64
    proj_kernel<<<g3, 256>>>(w_proj, b_proj, out);
}

// round 13
// speedup vs baseline: 4.4178x; 1.1595x over previous
#include <cuda_runtime.h>
#include <cuda_bf16.h>
#include <cuda_fp16.h>
#include <math.h>

#define BB 4
#define TT 2048
#define CC 1024
#define HH 16
#define HD 64
#define BT (BB*TT)
#define C3 (3*CC)

// q pre-scale: (1/sqrt(64)) * log2(e), folded in at qkv epilogue
#define QSCALE 0.18033688011112042f

// Scratch (device globals: allocation-guard safe).
// q/k: single fp16 planes, packed d-pairs [bh][t][32 words].
// v:   pre-split fp16 hi/lo planes in per-64-key-tile TRANSPOSED layout
//      [bh][tile][d(64)][colkey(32)] where colkey = kp ^ (4*((d>>2)&7)),
//      word = (key 2kp low16, key 2kp+1 high16) for dim d.
__device__ unsigned g_qh[BB*HH*TT*32];
__device__ unsigned g_kh[BB*HH*TT*32];
__device__ unsigned g_vhi[BB*HH*TT*32];   // fp16, tile-transposed
__device__ unsigned g_vlo[BB*HH*TT*32];   // fp16, tile-transposed
__device__ float g_y[BT*CC];

// ---------------- common helpers ----------------
__device__ __forceinline__ unsigned f2tf32(float x) {
    unsigned r;
    asm("cvt.rna.tf32.f32 %0, %1;" : "=r"(r) : "f"(x));
    return r;
}

__device__ __forceinline__ void mma_tf32(float* c, const unsigned* a, const unsigned* b) {
    asm volatile(
        "mma.sync.aligned.m16n8k8.row.col.f32.tf32.tf32.f32 "
        "{%0,%1,%2,%3}, {%4,%5,%6,%7}, {%8,%9}, {%0,%1,%2,%3};"
        : "+f"(c[0]), "+f"(c[1]), "+f"(c[2]), "+f"(c[3])
        : "r"(a[0]), "r"(a[1]), "r"(a[2]), "r"(a[3]), "r"(b[0]), "r"(b[1]));
}

__device__ __forceinline__ void mma_f16(float* c, const unsigned* a, const unsigned* b) {
    asm volatile(
        "mma.sync.aligned.m16n8k16.row.col.f32.f16.f16.f32 "
        "{%0,%1,%2,%3}, {%4,%5,%6,%7}, {%8,%9}, {%0,%1,%2,%3};"
        : "+f"(c[0]), "+f"(c[1]), "+f"(c[2]), "+f"(c[3])
        : "r"(a[0]), "r"(a[1]), "r"(a[2]), "r"(a[3]), "r"(b[0]), "r"(b[1]));
}

// fp16 split: hi ~ fp16(a), lo ~ fp16(a-hi). Packed low16=a0, high16=a1.
__device__ __forceinline__ void split2h(float a0, float a1, unsigned& hi, unsigned& lo) {
    unsigned h;
    asm("cvt.rn.f16x2.f32 %0, %1, %2;" : "=r"(h) : "f"(a1), "f"(a0));
    __half2 hh = *reinterpret_cast<__half2*>(&h);
    float h0 = __low2float(hh), h1 = __high2float(hh);
    unsigned l;
    float r0 = a0 - h0, r1 = a1 - h1;
    asm("cvt.rn.f16x2.f32 %0, %1, %2;" : "=r"(l) : "f"(r1), "f"(r0));
    hi = h; lo = l;
}

__device__ __forceinline__ unsigned packh2(float a0, float a1) {
    unsigned r;
    asm("cvt.rn.f16x2.f32 %0, %1, %2;" : "=r"(r) : "f"(a1), "f"(a0));
    return r;
}

__device__ __forceinline__ unsigned saddr(const void* p) {
    return (unsigned)__cvta_generic_to_shared(p);
}

__device__ __forceinline__ void ldsm4(unsigned& r0, unsigned& r1, unsigned& r2,
                                      unsigned& r3, unsigned a) {
    asm volatile("ldmatrix.sync.aligned.m8n8.x4.shared.b16 {%0,%1,%2,%3}, [%4];"
                 : "=r"(r0), "=r"(r1), "=r"(r2), "=r"(r3) : "r"(a));
}

__device__ __forceinline__ float ex2(float x) {
    float r;
    asm("ex2.approx.f32 %0, %1;" : "=f"(r) : "f"(x));
    return r;
}

__device__ __forceinline__ void cp16(unsigned dst, const void* src) {
    asm volatile("cp.async.cg.shared.global [%0], [%1], 16;"
                 :: "r"(dst), "l"(src) : "memory");
}

// ---------------- tf32 tensor-core GEMM, software-pipelined (R5) ----------------
#define GBM 128
#define GBN 128
#define GBK 16
#define AS_STRIDE 20
#define BS_STRIDE 136
#define ASZ (GBM * AS_STRIDE)
#define BSZ (GBK * BS_STRIDE)
#define NSTG (CC / GBK)

__device__ __forceinline__ void gemm_sts(unsigned* Asu, unsigned* Bsu, int buf,
                                         const float4* pa, const float4* pb,
                                         const int* m_, const int* c4_,
                                         const int* kk_, const int* n4_) {
#pragma unroll
    for (int it = 0; it < 2; it++) {
        uint4 at;
        at.x = f2tf32(pa[it].x); at.y = f2tf32(pa[it].y);
        at.z = f2tf32(pa[it].z); at.w = f2tf32(pa[it].w);
        *(uint4*)&Asu[buf * ASZ + m_[it] * AS_STRIDE + c4_[it]] = at;
        uint4 bt;
        bt.x = f2tf32(pb[it].x); bt.y = f2tf32(pb[it].y);
        bt.z = f2tf32(pb[it].z); bt.w = f2tf32(pb[it].w);
        *(uint4*)&Bsu[buf * BSZ + kk_[it] * BS_STRIDE + n4_[it]] = bt;
    }
}

__device__ __forceinline__ void gemm_tile_tf32(
    const float* __restrict__ A, int lda,
    const float* __restrict__ W, int ldw,
    int bm0, int bn0,
    unsigned* Asu, unsigned* Bsu,
    float acc[2][8][4])
{
    int tid = threadIdx.x;
    int wid = tid >> 5, lane = tid & 31;
    int wm = wid & 3, wn = wid >> 2;
    int g = lane >> 2, tig = lane & 3;

    int m_[2], c4_[2], kk_[2], n4_[2];
#pragma unroll
    for (int it = 0; it < 2; it++) {
        int fi = it * 256 + tid;
        m_[it] = fi >> 2;
        c4_[it] = (fi & 3) * 4;
        kk_[it] = fi >> 5;
        n4_[it] = (fi & 31) * 4;
    }

    float4 pa[2], pb[2];
#pragma unroll
    for (int it = 0; it < 2; it++) {
        pa[it] = *(const float4*)&A[(size_t)(bm0 + m_[it]) * lda + c4_[it]];
        pb[it] = *(const float4*)&W[(size_t)kk_[it] * ldw + bn0 + n4_[it]];
    }
    gemm_sts(Asu, Bsu, 0, pa, pb, m_, c4_, kk_, n4_);
    __syncthreads();

#pragma unroll 2
    for (int s = 0; s < NSTG; s++) {
        int cur = s & 1;
        if (s + 1 < NSTG) {
            int k0 = (s + 1) * GBK;
#pragma unroll
            for (int it = 0; it < 2; it++) {
                pa[it] = *(const float4*)&A[(size_t)(bm0 + m_[it]) * lda + k0 + c4_[it]];
                pb[it] = *(const float4*)&W[(size_t)(k0 + kk_[it]) * ldw + bn0 + n4_[it]];
            }
        }
        const unsigned* Ac = Asu + cur * ASZ;
        const unsigned* Bc = Bsu + cur * BSZ;
#pragma unroll
        for (int kc = 0; kc < GBK; kc += 8) {
            unsigned a_frag[2][4];
#pragma unroll
            for (int im = 0; im < 2; im++) {
                int rm = wm * 32 + im * 16 + g;
                a_frag[im][0] = Ac[rm * AS_STRIDE + kc + tig];
                a_frag[im][1] = Ac[(rm + 8) * AS_STRIDE + kc + tig];
                a_frag[im][2] = Ac[rm * AS_STRIDE + kc + tig + 4];
                a_frag[im][3] = Ac[(rm + 8) * AS_STRIDE + kc + tig + 4];
            }
            unsigned b_frag[8][2];
#pragma unroll
            for (int jn = 0; jn < 8; jn++) {
                int n = wn * 64 + jn * 8 + g;
                b_frag[jn][0] = Bc[(kc + tig) * BS_STRIDE + n];
                b_frag[jn][1] = Bc[(kc + tig + 4) * BS_STRIDE + n];
            }
#pragma unroll
            for (int im = 0; im < 2; im++)
#pragma unroll
                for (int jn = 0; jn < 8; jn++)
                    mma_tf32(acc[im][jn], a_frag[im], b_frag[jn]);
        }
        if (s + 1 < NSTG)
            gemm_sts(Asu, Bsu, cur ^ 1, pa, pb, m_, c4_, kk_, n4_);
        __syncthreads();
    }
}

// QKV: seq @ w_attn + bias -> q/k single fp16 planes (q pre-scaled); v fp16 hi/lo tile-transposed
__global__ __launch_bounds__(256, 2) void qkv_kernel(const float* __restrict__ A,
                                                     const float* __restrict__ W,
                                                     const float* __restrict__ bias) {
    __shared__ unsigned Asu[2 * ASZ];
    __shared__ unsigned Bsu[2 * BSZ];
    int bn0 = blockIdx.x * GBN;
    int bm0 = blockIdx.y * GBM;
    float acc[2][8][4] = {};
    gemm_tile_tf32(A, CC, W, C3, bm0, bn0, Asu, Bsu, acc);

    int tid = threadIdx.x;
    int wid = tid >> 5, lane = tid & 31;
    int wm = wid & 3, wn = wid >> 2;
    int g = lane >> 2, tig = lane & 3;
#pragma unroll
    for (int jn = 0; jn < 8; jn++) {
        int n0 = bn0 + wn * 64 + jn * 8 + 2 * tig;    // even -> d-pair aligned
        int which = n0 / CC;
        int nl = n0 % CC;
        int h = nl / HD;
        int word = (nl % HD) >> 1;
        float b0v = bias[n0], b1v = bias[n0 + 1];
#pragma unroll
        for (int im = 0; im < 2; im++) {
            int r0 = bm0 + wm * 32 + im * 16 + g;
#pragma unroll
            for (int half = 0; half < 2; half++) {
                int r = r0 + half * 8;
                int b_ = r / TT, t = r % TT;
                int bhh = b_ * HH + h;
                float v0 = acc[im][jn][half * 2 + 0] + b0v;
                float v1 = acc[im][jn][half * 2 + 1] + b1v;
                if (which == 2) {
                    // v: fp16 hi/lo u16 scatter into tile-transposed layout
                    unsigned hi, lo;
                    split2h(v0, v1, hi, lo);
                    int tile = t >> 6, kq = (t & 63) >> 1, hk = t & 1;
                    size_t base = ((size_t)bhh * 32 + tile) * 64;
                    int d0v = word * 2;
#pragma unroll
                    for (int e = 0; e < 2; e++) {
                        int d = d0v + e;
                        int col = kq ^ (4 * ((d >> 2) & 7));
                        size_t w = (base + d) * 32 + col;
                        unsigned short hv = e ? (unsigned short)(hi >> 16)
                                              : (unsigned short)(hi & 0xffffu);
                        unsigned short lv = e ? (unsigned short)(lo >> 16)
                                              : (unsigned short)(lo & 0xffffu);
                        ((unsigned short*)g_vhi)[w * 2 + hk] = hv;
                        ((unsigned short*)g_vlo)[w * 2 + hk] = lv;
                    }
                } else {
                    // q/k: single fp16 plane (q pre-scaled)
                    if (which == 0) { v0 *= QSCALE; v1 *= QSCALE; }
                    unsigned* dst = (which == 0) ? g_qh : g_kh;
                    size_t idx = ((size_t)bhh * TT + t) * 32 + word;
                    dst[idx] = packh2(v0, v1);
                }
            }
        }
    }
}

// Proj: g_y[BT,CC] @ w_proj[CC,CC] + bias -> out (unchanged)
__global__ __launch_bounds__(256, 2) void proj_kernel(const float* __restrict__ W,
                                                      const float* __restrict__ bias,
                                                      float* __restrict__ out) {
    __shared__ unsigned Asu[2 * ASZ];
    __shared__ unsigned Bsu[2 * BSZ];
    int bn0 = blockIdx.x * GBN;
    int bm0 = blockIdx.y * GBM;
    float acc[2][8][4] = {};
    gemm_tile_tf32(g_y, CC, W, CC, bm0, bn0, Asu, Bsu, acc);

    int tid = threadIdx.x;
    int wid = tid >> 5, lane = tid & 31;
    int wm = wid & 3, wn = wid >> 2;
    int g = lane >> 2, tig = lane & 3;
#pragma unroll
    for (int jn = 0; jn < 8; jn++) {
        int n0 = bn0 + wn * 64 + jn * 8 + 2 * tig;
        float b0v = bias[n0], b1v = bias[n0 + 1];
#pragma unroll
        for (int im = 0; im < 2; im++) {
            int r0 = bm0 + wm * 32 + im * 16 + g;
#pragma unroll
            for (int half = 0; half < 2; half++) {
                int r = r0 + half * 8;
                float2 v2 = make_float2(acc[im][jn][half * 2 + 0] + b0v,
                                        acc[im][jn][half * 2 + 1] + b1v);
                *(float2*)&out[(size_t)r * CC + n0] = v2;
            }
        }
    }
}

// ---------------- tensor-core flash attention, cp.async double-buffered ----------------
// QK: fp16 single-pass. PV: fp16 2-pass. Softmax log2 domain, ex2.approx.
// Tiles (K + Vt hi/lo) stream through a 2-stage dynamic-smem ring via cp.async.
#define AKT 64
#define NT (TT / AKT)          // 32 tiles
#define ARR_B 9216             // bytes per array per stage (64 rows x 36 words)
#define STAGE_B (3 * ARR_B)    // 27648
#define ATTN_SMEM (2 * STAGE_B)

// Issue one tile's 6 cp.async per thread (1536 x 16B total).
__device__ __forceinline__ void issue_tile(unsigned sbs,
                                           const unsigned* khg,
                                           const unsigned* vhg, const unsigned* vlg,
                                           int kt, int tid) {
    int row0 = tid >> 3;
    int ch4 = (tid & 7) * 4;
    const unsigned* vht = vhg + (size_t)(kt >> 6) * 2048;
    const unsigned* vlt = vlg + (size_t)(kt >> 6) * 2048;
#pragma unroll
    for (int hf = 0; hf < 2; hf++) {
        int row = hf * 32 + row0;
        unsigned d = sbs + (unsigned)(row * 36 + ch4) * 4u;
        cp16(d,              khg + (size_t)(kt + row) * 32 + ch4);
        cp16(d + ARR_B,      vht + row * 32 + ch4);
        cp16(d + 2 * ARR_B,  vlt + row * 32 + ch4);
    }
}

__global__ __launch_bounds__(256, 2) void attn_kernel() {
    extern __shared__ __align__(128) char asmem[];
    const unsigned sb = saddr(asmem);

    const int tid = threadIdx.x;
    const int warp = tid >> 5, lane = tid & 31;
    const int g = lane >> 2, tig = lane & 3;
    const int l7 = lane & 7, l3h = lane >> 3;
    const int bh = blockIdx.y;
    const int q0 = blockIdx.x * 128;
    const unsigned* qhg = g_qh + (size_t)bh * TT * 32;
    const unsigned* khg = g_kh + (size_t)bh * TT * 32;
    const unsigned* vhg = g_vhi + (size_t)bh * TT * 32;
    const unsigned* vlg = g_vlo + (size_t)bh * TT * 32;
    const int qrow = q0 + warp * 16 + g;

    // Q fragments: direct word loads (pre-scaled fp16)
    unsigned aq[4][4];
#pragma unroll
    for (int kc = 0; kc < 4; kc++) {
        int w = kc * 8 + tig;
        aq[kc][0] = qhg[(size_t)qrow * 32 + w];
        aq[kc][1] = qhg[(size_t)(qrow + 8) * 32 + w];
        aq[kc][2] = qhg[(size_t)qrow * 32 + w + 4];
        aq[kc][3] = qhg[(size_t)(qrow + 8) * 32 + w + 4];
    }

    float o[8][4];
#pragma unroll
    for (int j = 0; j < 8; j++)
#pragma unroll
        for (int i = 0; i < 4; i++) o[j][i] = 0.f;
    float m0 = -1e30f, m1 = -1e30f, l0 = 0.f, l1 = 0.f;

    // Prologue: tile 0 in flight
    issue_tile(sb, khg, vhg, vlg, 0, tid);
    asm volatile("cp.async.commit_group;" ::: "memory");

    for (int ti = 0; ti < NT; ti++) {
        const int buf = ti & 1;
        if (ti + 1 < NT) {
            issue_tile(sb + (buf ^ 1) * STAGE_B, khg, vhg, vlg,
                       (ti + 1) * AKT, tid);
            asm volatile("cp.async.commit_group;" ::: "memory");
            asm volatile("cp.async.wait_group 1;" ::: "memory");
        } else {
            asm volatile("cp.async.wait_group 0;" ::: "memory");
        }
        __syncthreads();

        const unsigned sbK    = sb + buf * STAGE_B;
        const unsigned sbV_hi = sbK + ARR_B;
        const unsigned sbV_lo = sbK + 2 * ARR_B;

        // ---- S = Q K^T (single-pass fp16), in log2 units ----
        float sacc[8][4];
#pragma unroll
        for (int j = 0; j < 8; j++) {
#pragma unroll
            for (int i = 0; i < 4; i++) sacc[j][i] = 0.f;
            unsigned rwb = (unsigned)((8 * j + l7) * 36 + 4 * l3h) * 4u;
            unsigned kh[4][2];
            ldsm4(kh[0][0], kh[0][1], kh[1][0], kh[1][1], sbK + rwb);
            ldsm4(kh[2][0], kh[2][1], kh[3][0], kh[3][1], sbK + rwb + 64);
#pragma unroll
            for (int kc = 0; kc < 4; kc++)
                mma_f16(sacc[j], aq[kc], kh[kc]);
        }

        // ---- online softmax (log2 domain) ----
        float rm0 = -1e30f, rm1 = -1e30f;
#pragma unroll
        for (int j = 0; j < 8; j++) {
            rm0 = fmaxf(rm0, fmaxf(sacc[j][0], sacc[j][1]));
            rm1 = fmaxf(rm1, fmaxf(sacc[j][2], sacc[j][3]));
        }
        rm0 = fmaxf(rm0, __shfl_xor_sync(0xffffffffu, rm0, 1));
        rm0 = fmaxf(rm0, __shfl_xor_sync(0xffffffffu, rm0, 2));
        rm1 = fmaxf(rm1, __shfl_xor_sync(0xffffffffu, rm1, 1));
        rm1 = fmaxf(rm1, __shfl_xor_sync(0xffffffffu, rm1, 2));
        float nm0 = fmaxf(m0, rm0), nm1 = fmaxf(m1, rm1);
        float cr0 = ex2(m0 - nm0), cr1 = ex2(m1 - nm1);
        m0 = nm0; m1 = nm1;

        unsigned p[4][4];
        float sum0 = 0.f, sum1 = 0.f;
#pragma unroll
        for (int u = 0; u < 4; u++) {
            float p00 = ex2(sacc[2 * u][0] - m0);
            float p01 = ex2(sacc[2 * u][1] - m0);
            float p10 = ex2(sacc[2 * u][2] - m1);
            float p11 = ex2(sacc[2 * u][3] - m1);
            float p20 = ex2(sacc[2 * u + 1][0] - m0);
            float p21 = ex2(sacc[2 * u + 1][1] - m0);
            float p30 = ex2(sacc[2 * u + 1][2] - m1);
            float p31 = ex2(sacc[2 * u + 1][3] - m1);
            sum0 += p00 + p01 + p20 + p21;
            sum1 += p10 + p11 + p30 + p31;
            p[u][0] = packh2(p00, p01);
            p[u][1] = packh2(p10, p11);
            p[u][2] = packh2(p20, p21);
            p[u][3] = packh2(p30, p31);
        }
        sum0 += __shfl_xor_sync(0xffffffffu, sum0, 1);
        sum0 += __shfl_xor_sync(0xffffffffu, sum0, 2);
        sum1 += __shfl_xor_sync(0xffffffffu, sum1, 1);
        sum1 += __shfl_xor_sync(0xffffffffu, sum1, 2);
        l0 = l0 * cr0 + sum0;
        l1 = l1 * cr1 + sum1;
#pragma unroll
        for (int j = 0; j < 8; j++) {
            o[j][0] *= cr0; o[j][1] *= cr0;
            o[j][2] *= cr1; o[j][3] *= cr1;
        }

        // ---- O += P V (2-pass fp16: P*(vh + vl)) ----
#pragma unroll
        for (int j = 0; j < 8; j++) {
            int drow = 8 * j + l7;
            int f = 4 * ((drow >> 2) & 7);
            unsigned rbb = (unsigned)(drow * 36) * 4u;
            unsigned c0 = (unsigned)((4 * l3h) ^ f) * 4u;
            unsigned c1 = (unsigned)((16 + 4 * l3h) ^ f) * 4u;
            unsigned vh[4][2], vl[4][2];
            ldsm4(vh[0][0], vh[0][1], vh[1][0], vh[1][1], sbV_hi + rbb + c0);
            ldsm4(vh[2][0], vh[2][1], vh[3][0], vh[3][1], sbV_hi + rbb + c1);
            ldsm4(vl[0][0], vl[0][1], vl[1][0], vl[1][1], sbV_lo + rbb + c0);
            ldsm4(vl[2][0], vl[2][1], vl[3][0], vl[3][1], sbV_lo + rbb + c1);
#pragma unroll
            for (int u = 0; u < 4; u++) {
                mma_f16(o[j], p[u], vh[u]);
                mma_f16(o[j], p[u], vl[u]);
            }
        }
        __syncthreads();
    }

    // ---- epilogue ----
    float inv0 = 1.f / l0, inv1 = 1.f / l1;
    int b_ = bh >> 4, h = bh & 15;
    float* y0 = g_y + ((size_t)(b_ * TT + qrow)) * CC + h * HD;
    float* y1 = g_y + ((size_t)(b_ * TT + qrow + 8)) * CC + h * HD;
#pragma unroll
    for (int j = 0; j < 8; j++) {
        *(float2*)&y0[8 * j + 2 * tig] = make_float2(o[j][0] * inv0, o[j][1] * inv0);
        *(float2*)&y1[8 * j + 2 * tig] = make_float2(o[j][2] * inv1, o[j][3] * inv1);
    }
}

extern "C" void kernel_launch(void* const* d_in, const int* in_sizes, int n_in,
                              void* d_out, int out_size) {
    const float* seq    = (const float*)d_in[0];
    const float* w_attn = (const float*)d_in[1];
    const float* b_attn = (const float*)d_in[2];
    const float* w_proj = (const float*)d_in[3];
    const float* b_proj = (const float*)d_in[4];
    float* out = (float*)d_out;

    static int attr_set = 0;
    if (!attr_set) {
        cudaFuncSetAttribute(attn_kernel,
                             cudaFuncAttributeMaxDynamicSharedMemorySize, ATTN_SMEM);
        attr_set = 1;
    }

    dim3 g1(C3 / GBN, BT / GBM);        // 24 x 64
    qkv_kernel<<<g1, 256>>>(seq, w_attn, b_attn);

    dim3 g2(TT / 128, BB * HH);         // 16 x 64
    attn_kernel<<<g2, 256, ATTN_SMEM>>>();

    dim3 g3(CC / GBN, BT / GBM);        // 8 x 64
    proj_kernel<<<g3, 256>>>(w_proj, b_proj, out);
}

// round 14
// speedup vs baseline: 5.2051x; 1.1782x over previous
#include <cuda_runtime.h>
#include <cuda_bf16.h>
#include <cuda_fp16.h>
#include <math.h>

#define BB 4
#define TT 2048
#define CC 1024
#define HH 16
#define HD 64
#define BT (BB*TT)
#define C3 (3*CC)

// q pre-scale: (1/sqrt(64)) * log2(e), folded in at qkv epilogue
#define QSCALE 0.18033688011112042f

// Scratch (device globals: allocation-guard safe).
// q/k: single fp16 planes, packed d-pairs [bh][t][32 words].
// v:   single fp16 plane in per-64-key-tile TRANSPOSED layout
//      [bh][tile][d(64)][colkey(32)] where colkey = kp ^ (4*((d>>2)&7)),
//      word = (key 2kp low16, key 2kp+1 high16) for dim d.
__device__ unsigned g_qh[BB*HH*TT*32];
__device__ unsigned g_kh[BB*HH*TT*32];
__device__ unsigned g_vh[BB*HH*TT*32];    // fp16, tile-transposed
__device__ float g_y[BT*CC];

// ---------------- common helpers ----------------
__device__ __forceinline__ unsigned f2tf32(float x) {
    unsigned r;
    asm("cvt.rna.tf32.f32 %0, %1;" : "=r"(r) : "f"(x));
    return r;
}

__device__ __forceinline__ void mma_tf32(float* c, const unsigned* a, const unsigned* b) {
    asm volatile(
        "mma.sync.aligned.m16n8k8.row.col.f32.tf32.tf32.f32 "
        "{%0,%1,%2,%3}, {%4,%5,%6,%7}, {%8,%9}, {%0,%1,%2,%3};"
        : "+f"(c[0]), "+f"(c[1]), "+f"(c[2]), "+f"(c[3])
        : "r"(a[0]), "r"(a[1]), "r"(a[2]), "r"(a[3]), "r"(b[0]), "r"(b[1]));
}

__device__ __forceinline__ void mma_f16(float* c, const unsigned* a, const unsigned* b) {
    asm volatile(
        "mma.sync.aligned.m16n8k16.row.col.f32.f16.f16.f32 "
        "{%0,%1,%2,%3}, {%4,%5,%6,%7}, {%8,%9}, {%0,%1,%2,%3};"
        : "+f"(c[0]), "+f"(c[1]), "+f"(c[2]), "+f"(c[3])
        : "r"(a[0]), "r"(a[1]), "r"(a[2]), "r"(a[3]), "r"(b[0]), "r"(b[1]));
}

__device__ __forceinline__ unsigned packh2(float a0, float a1) {
    unsigned r;
    asm("cvt.rn.f16x2.f32 %0, %1, %2;" : "=r"(r) : "f"(a1), "f"(a0));
    return r;
}

__device__ __forceinline__ unsigned saddr(const void* p) {
    return (unsigned)__cvta_generic_to_shared(p);
}

__device__ __forceinline__ void ldsm4(unsigned& r0, unsigned& r1, unsigned& r2,
                                      unsigned& r3, unsigned a) {
    asm volatile("ldmatrix.sync.aligned.m8n8.x4.shared.b16 {%0,%1,%2,%3}, [%4];"
                 : "=r"(r0), "=r"(r1), "=r"(r2), "=r"(r3) : "r"(a));
}

__device__ __forceinline__ float ex2(float x) {
    float r;
    asm("ex2.approx.f32 %0, %1;" : "=f"(r) : "f"(x));
    return r;
}

__device__ __forceinline__ void cp16(unsigned dst, const void* src) {
    asm volatile("cp.async.cg.shared.global [%0], [%1], 16;"
                 :: "r"(dst), "l"(src) : "memory");
}

// ---------------- tf32 tensor-core GEMM, software-pipelined (R5) ----------------
#define GBM 128
#define GBN 128
#define GBK 16
#define AS_STRIDE 20
#define BS_STRIDE 136
#define ASZ (GBM * AS_STRIDE)
#define BSZ (GBK * BS_STRIDE)
#define NSTG (CC / GBK)

__device__ __forceinline__ void gemm_sts(unsigned* Asu, unsigned* Bsu, int buf,
                                         const float4* pa, const float4* pb,
                                         const int* m_, const int* c4_,
                                         const int* kk_, const int* n4_) {
#pragma unroll
    for (int it = 0; it < 2; it++) {
        uint4 at;
        at.x = f2tf32(pa[it].x); at.y = f2tf32(pa[it].y);
        at.z = f2tf32(pa[it].z); at.w = f2tf32(pa[it].w);
        *(uint4*)&Asu[buf * ASZ + m_[it] * AS_STRIDE + c4_[it]] = at;
        uint4 bt;
        bt.x = f2tf32(pb[it].x); bt.y = f2tf32(pb[it].y);
        bt.z = f2tf32(pb[it].z); bt.w = f2tf32(pb[it].w);
        *(uint4*)&Bsu[buf * BSZ + kk_[it] * BS_STRIDE + n4_[it]] = bt;
    }
}

__device__ __forceinline__ void gemm_tile_tf32(
    const float* __restrict__ A, int lda,
    const float* __restrict__ W, int ldw,
    int bm0, int bn0,
    unsigned* Asu, unsigned* Bsu,
    float acc[2][8][4])
{
    int tid = threadIdx.x;
    int wid = tid >> 5, lane = tid & 31;
    int wm = wid & 3, wn = wid >> 2;
    int g = lane >> 2, tig = lane & 3;

    int m_[2], c4_[2], kk_[2], n4_[2];
#pragma unroll
    for (int it = 0; it < 2; it++) {
        int fi = it * 256 + tid;
        m_[it] = fi >> 2;
        c4_[it] = (fi & 3) * 4;
        kk_[it] = fi >> 5;
        n4_[it] = (fi & 31) * 4;
    }

    float4 pa[2], pb[2];
#pragma unroll
    for (int it = 0; it < 2; it++) {
        pa[it] = *(const float4*)&A[(size_t)(bm0 + m_[it]) * lda + c4_[it]];
        pb[it] = *(const float4*)&W[(size_t)kk_[it] * ldw + bn0 + n4_[it]];
    }
    gemm_sts(Asu, Bsu, 0, pa, pb, m_, c4_, kk_, n4_);
    __syncthreads();

#pragma unroll 2
    for (int s = 0; s < NSTG; s++) {
        int cur = s & 1;
        if (s + 1 < NSTG) {
            int k0 = (s + 1) * GBK;
#pragma unroll
            for (int it = 0; it < 2; it++) {
                pa[it] = *(const float4*)&A[(size_t)(bm0 + m_[it]) * lda + k0 + c4_[it]];
                pb[it] = *(const float4*)&W[(size_t)(k0 + kk_[it]) * ldw + bn0 + n4_[it]];
            }
        }
        const unsigned* Ac = Asu + cur * ASZ;
        const unsigned* Bc = Bsu + cur * BSZ;
#pragma unroll
        for (int kc = 0; kc < GBK; kc += 8) {
            unsigned a_frag[2][4];
#pragma unroll
            for (int im = 0; im < 2; im++) {
                int rm = wm * 32 + im * 16 + g;
                a_frag[im][0] = Ac[rm * AS_STRIDE + kc + tig];
                a_frag[im][1] = Ac[(rm + 8) * AS_STRIDE + kc + tig];
                a_frag[im][2] = Ac[rm * AS_STRIDE + kc + tig + 4];
                a_frag[im][3] = Ac[(rm + 8) * AS_STRIDE + kc + tig + 4];
            }
            unsigned b_frag[8][2];
#pragma unroll
            for (int jn = 0; jn < 8; jn++) {
                int n = wn * 64 + jn * 8 + g;
                b_frag[jn][0] = Bc[(kc + tig) * BS_STRIDE + n];
                b_frag[jn][1] = Bc[(kc + tig + 4) * BS_STRIDE + n];
            }
#pragma unroll
            for (int im = 0; im < 2; im++)
#pragma unroll
                for (int jn = 0; jn < 8; jn++)
                    mma_tf32(acc[im][jn], a_frag[im], b_frag[jn]);
        }
        if (s + 1 < NSTG)
            gemm_sts(Asu, Bsu, cur ^ 1, pa, pb, m_, c4_, kk_, n4_);
        __syncthreads();
    }
}

// QKV: seq @ w_attn + bias -> q/k single fp16 planes (q pre-scaled); v single fp16 tile-transposed
__global__ __launch_bounds__(256, 2) void qkv_kernel(const float* __restrict__ A,
                                                     const float* __restrict__ W,
                                                     const float* __restrict__ bias) {
    __shared__ unsigned Asu[2 * ASZ];
    __shared__ unsigned Bsu[2 * BSZ];
    int bn0 = blockIdx.x * GBN;
    int bm0 = blockIdx.y * GBM;
    float acc[2][8][4] = {};
    gemm_tile_tf32(A, CC, W, C3, bm0, bn0, Asu, Bsu, acc);

    int tid = threadIdx.x;
    int wid = tid >> 5, lane = tid & 31;
    int wm = wid & 3, wn = wid >> 2;
    int g = lane >> 2, tig = lane & 3;
#pragma unroll
    for (int jn = 0; jn < 8; jn++) {
        int n0 = bn0 + wn * 64 + jn * 8 + 2 * tig;    // even -> d-pair aligned
        int which = n0 / CC;
        int nl = n0 % CC;
        int h = nl / HD;
        int word = (nl % HD) >> 1;
        float b0v = bias[n0], b1v = bias[n0 + 1];
#pragma unroll
        for (int im = 0; im < 2; im++) {
            int r0 = bm0 + wm * 32 + im * 16 + g;
#pragma unroll
            for (int half = 0; half < 2; half++) {
                int r = r0 + half * 8;
                int b_ = r / TT, t = r % TT;
                int bhh = b_ * HH + h;
                float v0 = acc[im][jn][half * 2 + 0] + b0v;
                float v1 = acc[im][jn][half * 2 + 1] + b1v;
                if (which == 2) {
                    // v: single fp16, u16 scatter into tile-transposed layout
                    unsigned hi = packh2(v0, v1);
                    int tile = t >> 6, kq = (t & 63) >> 1, hk = t & 1;
                    size_t base = ((size_t)bhh * 32 + tile) * 64;
                    int d0v = word * 2;
#pragma unroll
                    for (int e = 0; e < 2; e++) {
                        int d = d0v + e;
                        int col = kq ^ (4 * ((d >> 2) & 7));
                        size_t w = (base + d) * 32 + col;
                        unsigned short hv = e ? (unsigned short)(hi >> 16)
                                              : (unsigned short)(hi & 0xffffu);
                        ((unsigned short*)g_vh)[w * 2 + hk] = hv;
                    }
                } else {
                    // q/k: single fp16 plane (q pre-scaled)
                    if (which == 0) { v0 *= QSCALE; v1 *= QSCALE; }
                    unsigned* dst = (which == 0) ? g_qh : g_kh;
                    size_t idx = ((size_t)bhh * TT + t) * 32 + word;
                    dst[idx] = packh2(v0, v1);
                }
            }
        }
    }
}

// Proj: g_y[BT,CC] @ w_proj[CC,CC] + bias -> out (unchanged)
__global__ __launch_bounds__(256, 2) void proj_kernel(const float* __restrict__ W,
                                                      const float* __restrict__ bias,
                                                      float* __restrict__ out) {
    __shared__ unsigned Asu[2 * ASZ];
    __shared__ unsigned Bsu[2 * BSZ];
    int bn0 = blockIdx.x * GBN;
    int bm0 = blockIdx.y * GBM;
    float acc[2][8][4] = {};
    gemm_tile_tf32(g_y, CC, W, CC, bm0, bn0, Asu, Bsu, acc);

    int tid = threadIdx.x;
    int wid = tid >> 5, lane = tid & 31;
    int wm = wid & 3, wn = wid >> 2;
    int g = lane >> 2, tig = lane & 3;
#pragma unroll
    for (int jn = 0; jn < 8; jn++) {
        int n0 = bn0 + wn * 64 + jn * 8 + 2 * tig;
        float b0v = bias[n0], b1v = bias[n0 + 1];
#pragma unroll
        for (int im = 0; im < 2; im++) {
            int r0 = bm0 + wm * 32 + im * 16 + g;
#pragma unroll
            for (int half = 0; half < 2; half++) {
                int r = r0 + half * 8;
                float2 v2 = make_float2(acc[im][jn][half * 2 + 0] + b0v,
                                        acc[im][jn][half * 2 + 1] + b1v);
                *(float2*)&out[(size_t)r * CC + n0] = v2;
            }
        }
    }
}

// ---------------- tensor-core flash attention, cp.async double-buffered ----------------
// QK: fp16 single-pass. PV: fp16 single-pass. Softmax log2 domain, ex2.approx.
// Tiles (K + Vt) stream through a 2-stage dynamic-smem ring via cp.async.
#define AKT 64
#define NT (TT / AKT)          // 32 tiles
#define ARR_B 9216             // bytes per array per stage (64 rows x 36 words)
#define STAGE_B (2 * ARR_B)    // 18432
#define ATTN_SMEM (2 * STAGE_B)

// Issue one tile's 4 cp.async per thread (1024 x 16B total).
__device__ __forceinline__ void issue_tile(unsigned sbs,
                                           const unsigned* khg,
                                           const unsigned* vhg,
                                           int kt, int tid) {
    int row0 = tid >> 3;
    int ch4 = (tid & 7) * 4;
    const unsigned* vht = vhg + (size_t)(kt >> 6) * 2048;
#pragma unroll
    for (int hf = 0; hf < 2; hf++) {
        int row = hf * 32 + row0;
        unsigned d = sbs + (unsigned)(row * 36 + ch4) * 4u;
        cp16(d,          khg + (size_t)(kt + row) * 32 + ch4);
        cp16(d + ARR_B,  vht + row * 32 + ch4);
    }
}

__global__ __launch_bounds__(256, 2) void attn_kernel() {
    extern __shared__ __align__(128) char asmem[];
    const unsigned sb = saddr(asmem);

    const int tid = threadIdx.x;
    const int warp = tid >> 5, lane = tid & 31;
    const int g = lane >> 2, tig = lane & 3;
    const int l7 = lane & 7, l3h = lane >> 3;
    const int bh = blockIdx.y;
    const int q0 = blockIdx.x * 128;
    const unsigned* qhg = g_qh + (size_t)bh * TT * 32;
    const unsigned* khg = g_kh + (size_t)bh * TT * 32;
    const unsigned* vhg = g_vh + (size_t)bh * TT * 32;
    const int qrow = q0 + warp * 16 + g;

    // Q fragments: direct word loads (pre-scaled fp16)
    unsigned aq[4][4];
#pragma unroll
    for (int kc = 0; kc < 4; kc++) {
        int w = kc * 8 + tig;
        aq[kc][0] = qhg[(size_t)qrow * 32 + w];
        aq[kc][1] = qhg[(size_t)(qrow + 8) * 32 + w];
        aq[kc][2] = qhg[(size_t)qrow * 32 + w + 4];
        aq[kc][3] = qhg[(size_t)(qrow + 8) * 32 + w + 4];
    }

    float o[8][4];
#pragma unroll
    for (int j = 0; j < 8; j++)
#pragma unroll
        for (int i = 0; i < 4; i++) o[j][i] = 0.f;
    float m0 = -1e30f, m1 = -1e30f, l0 = 0.f, l1 = 0.f;

    // Prologue: tile 0 in flight
    issue_tile(sb, khg, vhg, 0, tid);
    asm volatile("cp.async.commit_group;" ::: "memory");

    for (int ti = 0; ti < NT; ti++) {
        const int buf = ti & 1;
        if (ti + 1 < NT) {
            issue_tile(sb + (buf ^ 1) * STAGE_B, khg, vhg, (ti + 1) * AKT, tid);
            asm volatile("cp.async.commit_group;" ::: "memory");
            asm volatile("cp.async.wait_group 1;" ::: "memory");
        } else {
            asm volatile("cp.async.wait_group 0;" ::: "memory");
        }
        __syncthreads();

        const unsigned sbK = sb + buf * STAGE_B;
        const unsigned sbV = sbK + ARR_B;

        // ---- S = Q K^T (single-pass fp16), in log2 units ----
        float sacc[8][4];
#pragma unroll
        for (int j = 0; j < 8; j++) {
#pragma unroll
            for (int i = 0; i < 4; i++) sacc[j][i] = 0.f;
            unsigned rwb = (unsigned)((8 * j + l7) * 36 + 4 * l3h) * 4u;
            unsigned kh[4][2];
            ldsm4(kh[0][0], kh[0][1], kh[1][0], kh[1][1], sbK + rwb);
            ldsm4(kh[2][0], kh[2][1], kh[3][0], kh[3][1], sbK + rwb + 64);
#pragma unroll
            for (int kc = 0; kc < 4; kc++)
                mma_f16(sacc[j], aq[kc], kh[kc]);
        }

        // ---- online softmax (log2 domain) ----
        float rm0 = -1e30f, rm1 = -1e30f;
#pragma unroll
        for (int j = 0; j < 8; j++) {
            rm0 = fmaxf(rm0, fmaxf(sacc[j][0], sacc[j][1]));
            rm1 = fmaxf(rm1, fmaxf(sacc[j][2], sacc[j][3]));
        }
        rm0 = fmaxf(rm0, __shfl_xor_sync(0xffffffffu, rm0, 1));
        rm0 = fmaxf(rm0, __shfl_xor_sync(0xffffffffu, rm0, 2));
        rm1 = fmaxf(rm1, __shfl_xor_sync(0xffffffffu, rm1, 1));
        rm1 = fmaxf(rm1, __shfl_xor_sync(0xffffffffu, rm1, 2));
        float nm0 = fmaxf(m0, rm0), nm1 = fmaxf(m1, rm1);
        float cr0 = ex2(m0 - nm0), cr1 = ex2(m1 - nm1);
        m0 = nm0; m1 = nm1;

        unsigned p[4][4];
        float sum0 = 0.f, sum1 = 0.f;
#pragma unroll
        for (int u = 0; u < 4; u++) {
            float p00 = ex2(sacc[2 * u][0] - m0);
            float p01 = ex2(sacc[2 * u][1] - m0);
            float p10 = ex2(sacc[2 * u][2] - m1);
            float p11 = ex2(sacc[2 * u][3] - m1);
            float p20 = ex2(sacc[2 * u + 1][0] - m0);
            float p21 = ex2(sacc[2 * u + 1][1] - m0);
            float p30 = ex2(sacc[2 * u + 1][2] - m1);
            float p31 = ex2(sacc[2 * u + 1][3] - m1);
            sum0 += p00 + p01 + p20 + p21;
            sum1 += p10 + p11 + p30 + p31;
            p[u][0] = packh2(p00, p01);
            p[u][1] = packh2(p10, p11);
            p[u][2] = packh2(p20, p21);
            p[u][3] = packh2(p30, p31);
        }
        sum0 += __shfl_xor_sync(0xffffffffu, sum0, 1);
        sum0 += __shfl_xor_sync(0xffffffffu, sum0, 2);
        sum1 += __shfl_xor_sync(0xffffffffu, sum1, 1);
        sum1 += __shfl_xor_sync(0xffffffffu, sum1, 2);
        l0 = l0 * cr0 + sum0;
        l1 = l1 * cr1 + sum1;
#pragma unroll
        for (int j = 0; j < 8; j++) {
            o[j][0] *= cr0; o[j][1] *= cr0;
            o[j][2] *= cr1; o[j][3] *= cr1;
        }

        // ---- O += P V (single-pass fp16) ----
#pragma unroll
        for (int j = 0; j < 8; j++) {
            int drow = 8 * j + l7;
            int f = 4 * ((drow >> 2) & 7);
            unsigned rbb = (unsigned)(drow * 36) * 4u;
            unsigned c0 = (unsigned)((4 * l3h) ^ f) * 4u;
            unsigned c1 = (unsigned)((16 + 4 * l3h) ^ f) * 4u;
            unsigned vh[4][2];
            ldsm4(vh[0][0], vh[0][1], vh[1][0], vh[1][1], sbV + rbb + c0);
            ldsm4(vh[2][0], vh[2][1], vh[3][0], vh[3][1], sbV + rbb + c1);
#pragma unroll
            for (int u = 0; u < 4; u++)
                mma_f16(o[j], p[u], vh[u]);
        }
        __syncthreads();
    }

    // ---- epilogue ----
    float inv0 = 1.f / l0, inv1 = 1.f / l1;
    int b_ = bh >> 4, h = bh & 15;
    float* y0 = g_y + ((size_t)(b_ * TT + qrow)) * CC + h * HD;
    float* y1 = g_y + ((size_t)(b_ * TT + qrow + 8)) * CC + h * HD;
#pragma unroll
    for (int j = 0; j < 8; j++) {
        *(float2*)&y0[8 * j + 2 * tig] = make_float2(o[j][0] * inv0, o[j][1] * inv0);
        *(float2*)&y1[8 * j + 2 * tig] = make_float2(o[j][2] * inv1, o[j][3] * inv1);
    }
}

extern "C" void kernel_launch(void* const* d_in, const int* in_sizes, int n_in,
                              void* d_out, int out_size) {
    const float* seq    = (const float*)d_in[0];
    const float* w_attn = (const float*)d_in[1];
    const float* b_attn = (const float*)d_in[2];
    const float* w_proj = (const float*)d_in[3];
    const float* b_proj = (const float*)d_in[4];
    float* out = (float*)d_out;

    static int attr_set = 0;
    if (!attr_set) {
        cudaFuncSetAttribute(attn_kernel,
                             cudaFuncAttributeMaxDynamicSharedMemorySize, ATTN_SMEM);
        attr_set = 1;
    }

    dim3 g1(C3 / GBN, BT / GBM);        // 24 x 64
    qkv_kernel<<<g1, 256>>>(seq, w_attn, b_attn);

    dim3 g2(TT / 128, BB * HH);         // 16 x 64
    attn_kernel<<<g2, 256, ATTN_SMEM>>>();

    dim3 g3(CC / GBN, BT / GBM);        // 8 x 64
    proj_kernel<<<g3, 256>>>(w_proj, b_proj, out);
}

// round 15
// speedup vs baseline: 6.4121x; 1.2319x over previous
#include <cuda_runtime.h>
#include <cuda_bf16.h>
#include <cuda_fp16.h>
#include <math.h>

#define BB 4
#define TT 2048
#define CC 1024
#define HH 16
#define HD 64
#define BT (BB*TT)
#define C3 (3*CC)

// q pre-scale: (1/sqrt(64)) * log2(e), folded in at qkv epilogue
#define QSCALE 0.18033688011112042f

// Scratch (device globals: allocation-guard safe).
__device__ unsigned g_qh[BB*HH*TT*32];
__device__ unsigned g_kh[BB*HH*TT*32];
__device__ unsigned g_vh[BB*HH*TT*32];    // fp16, tile-transposed
__device__ float g_y[BT*CC];

// ---------------- common helpers ----------------
__device__ __forceinline__ void mma_f16(float* c, const unsigned* a, const unsigned* b) {
    asm volatile(
        "mma.sync.aligned.m16n8k16.row.col.f32.f16.f16.f32 "
        "{%0,%1,%2,%3}, {%4,%5,%6,%7}, {%8,%9}, {%0,%1,%2,%3};"
        : "+f"(c[0]), "+f"(c[1]), "+f"(c[2]), "+f"(c[3])
        : "r"(a[0]), "r"(a[1]), "r"(a[2]), "r"(a[3]), "r"(b[0]), "r"(b[1]));
}

__device__ __forceinline__ unsigned packh2(float a0, float a1) {
    unsigned r;
    asm("cvt.rn.f16x2.f32 %0, %1, %2;" : "=r"(r) : "f"(a1), "f"(a0));
    return r;
}

__device__ __forceinline__ unsigned saddr(const void* p) {
    return (unsigned)__cvta_generic_to_shared(p);
}

__device__ __forceinline__ void ldsm4(unsigned& r0, unsigned& r1, unsigned& r2,
                                      unsigned& r3, unsigned a) {
    asm volatile("ldmatrix.sync.aligned.m8n8.x4.shared.b16 {%0,%1,%2,%3}, [%4];"
                 : "=r"(r0), "=r"(r1), "=r"(r2), "=r"(r3) : "r"(a));
}

__device__ __forceinline__ float ex2(float x) {
    float r;
    asm("ex2.approx.f32 %0, %1;" : "=f"(r) : "f"(x));
    return r;
}

__device__ __forceinline__ void cp16(unsigned dst, const void* src) {
    asm volatile("cp.async.cg.shared.global [%0], [%1], 16;"
                 :: "r"(dst), "l"(src) : "memory");
}

// ---------------- fp16 tensor-core GEMM, software-pipelined ----------------
// Block 128x128, k-stage 16. A[m][k-pair] stride-12 words (all-bank scalar frags).
// B[n][k-pair] stride-12 words (K-style rows -> ldmatrix.x4, rows 12w apart =
// distinct banks). fp32 accum; fp16 mantissa == tf32 mantissa -> same error.
#define GBM 128
#define GBN 128
#define ST 12                    // row stride in words
#define TSZ (128 * ST)           // words per tile per stage
#define NSTG (CC / 16)           // 64 stages

__device__ __forceinline__ void gemm_sts_f16(unsigned* Asu, unsigned* Bsu, int buf,
                                             const float4* pa, const float* pbv,
                                             const int* m_, const int* c4_,
                                             int bn_, int bkh_) {
#pragma unroll
    for (int it = 0; it < 2; it++) {
        uint2 aw;
        aw.x = packh2(pa[it].x, pa[it].y);
        aw.y = packh2(pa[it].z, pa[it].w);
        *(uint2*)&Asu[buf * TSZ + m_[it] * ST + (c4_[it] >> 1)] = aw;
    }
    uint4 bw;
    bw.x = packh2(pbv[0], pbv[1]);
    bw.y = packh2(pbv[2], pbv[3]);
    bw.z = packh2(pbv[4], pbv[5]);
    bw.w = packh2(pbv[6], pbv[7]);
    *(uint4*)&Bsu[buf * TSZ + bn_ * ST + bkh_ * 4] = bw;
}

__device__ __forceinline__ void gemm_tile_f16(
    const float* __restrict__ A, int lda,
    const float* __restrict__ W, int ldw,
    int bm0, int bn0,
    unsigned* Asu, unsigned* Bsu,
    float acc[2][8][4])
{
    int tid = threadIdx.x;
    int wid = tid >> 5, lane = tid & 31;
    int wm = wid & 3, wn = wid >> 2;
    int g = lane >> 2, tig = lane & 3;

    // A fill coords (2 float4 per thread)
    int m_[2], c4_[2];
#pragma unroll
    for (int it = 0; it < 2; it++) {
        int fi = it * 256 + tid;
        m_[it] = fi >> 2;
        c4_[it] = (fi & 3) * 4;
    }
    // B fill coords: thread owns n-row bn_, k-half bkh_ (8 k values)
    int bn_ = tid >> 1;
    int bkh_ = tid & 1;

    // ldmatrix lane address offset (words) within B tile:
    // matrices: 0=(nb,kh0) 1=(nb,kh1) 2=(nb+8,kh0) 3=(nb+8,kh1)
    int mi = lane >> 3, r8 = lane & 7;
    int ldsm_off = (r8 + 8 * (mi >> 1)) * ST + (mi & 1) * 4;

    float4 pa[2];
    float pbv[8];
#pragma unroll
    for (int it = 0; it < 2; it++)
        pa[it] = *(const float4*)&A[(size_t)(bm0 + m_[it]) * lda + c4_[it]];
#pragma unroll
    for (int j = 0; j < 8; j++)
        pbv[j] = W[(size_t)(bkh_ * 8 + j) * ldw + bn0 + bn_];
    gemm_sts_f16(Asu, Bsu, 0, pa, pbv, m_, c4_, bn_, bkh_);
    __syncthreads();

#pragma unroll 2
    for (int s = 0; s < NSTG; s++) {
        int cur = s & 1;
        if (s + 1 < NSTG) {
            int k0 = (s + 1) * 16;
#pragma unroll
            for (int it = 0; it < 2; it++)
                pa[it] = *(const float4*)&A[(size_t)(bm0 + m_[it]) * lda + k0 + c4_[it]];
#pragma unroll
            for (int j = 0; j < 8; j++)
                pbv[j] = W[(size_t)(k0 + bkh_ * 8 + j) * ldw + bn0 + bn_];
        }
        const unsigned* Ac = Asu + cur * TSZ;
        unsigned bbase = saddr(Bsu) + (unsigned)(cur * TSZ) * 4u;

        unsigned a_frag[2][4];
#pragma unroll
        for (int im = 0; im < 2; im++) {
            int rm = wm * 32 + im * 16 + g;
            a_frag[im][0] = Ac[rm * ST + tig];
            a_frag[im][1] = Ac[(rm + 8) * ST + tig];
            a_frag[im][2] = Ac[rm * ST + tig + 4];
            a_frag[im][3] = Ac[(rm + 8) * ST + tig + 4];
        }
        unsigned b_frag[8][2];
#pragma unroll
        for (int jp = 0; jp < 4; jp++) {
            int nb = wn * 64 + jp * 16;
            unsigned addr = bbase + (unsigned)(nb * ST + ldsm_off) * 4u;
            ldsm4(b_frag[2 * jp][0], b_frag[2 * jp][1],
                  b_frag[2 * jp + 1][0], b_frag[2 * jp + 1][1], addr);
        }
#pragma unroll
        for (int im = 0; im < 2; im++)
#pragma unroll
            for (int jn = 0; jn < 8; jn++)
                mma_f16(acc[im][jn], a_frag[im], b_frag[jn]);

        if (s + 1 < NSTG)
            gemm_sts_f16(Asu, Bsu, cur ^ 1, pa, pbv, m_, c4_, bn_, bkh_);
        __syncthreads();
    }
}

// QKV: seq @ w_attn + bias -> q/k single fp16 planes (q pre-scaled); v fp16 tile-transposed
__global__ __launch_bounds__(256, 2) void qkv_kernel(const float* __restrict__ A,
                                                     const float* __restrict__ W,
                                                     const float* __restrict__ bias) {
    __shared__ __align__(16) unsigned Asu[2 * TSZ];
    __shared__ __align__(16) unsigned Bsu[2 * TSZ];
    int bn0 = blockIdx.x * GBN;
    int bm0 = blockIdx.y * GBM;
    float acc[2][8][4] = {};
    gemm_tile_f16(A, CC, W, C3, bm0, bn0, Asu, Bsu, acc);

    int tid = threadIdx.x;
    int wid = tid >> 5, lane = tid & 31;
    int wm = wid & 3, wn = wid >> 2;
    int g = lane >> 2, tig = lane & 3;
#pragma unroll
    for (int jn = 0; jn < 8; jn++) {
        int n0 = bn0 + wn * 64 + jn * 8 + 2 * tig;    // even -> d-pair aligned
        int which = n0 / CC;
        int nl = n0 % CC;
        int h = nl / HD;
        int word = (nl % HD) >> 1;
        float b0v = bias[n0], b1v = bias[n0 + 1];
#pragma unroll
        for (int im = 0; im < 2; im++) {
            int r0 = bm0 + wm * 32 + im * 16 + g;
#pragma unroll
            for (int half = 0; half < 2; half++) {
                int r = r0 + half * 8;
                int b_ = r / TT, t = r % TT;
                int bhh = b_ * HH + h;
                float v0 = acc[im][jn][half * 2 + 0] + b0v;
                float v1 = acc[im][jn][half * 2 + 1] + b1v;
                if (which == 2) {
                    // v: single fp16, u16 scatter into tile-transposed layout
                    unsigned hi = packh2(v0, v1);
                    int tile = t >> 6, kq = (t & 63) >> 1, hk = t & 1;
                    size_t base = ((size_t)bhh * 32 + tile) * 64;
                    int d0v = word * 2;
#pragma unroll
                    for (int e = 0; e < 2; e++) {
                        int d = d0v + e;
                        int col = kq ^ (4 * ((d >> 2) & 7));
                        size_t w = (base + d) * 32 + col;
                        unsigned short hv = e ? (unsigned short)(hi >> 16)
                                              : (unsigned short)(hi & 0xffffu);
                        ((unsigned short*)g_vh)[w * 2 + hk] = hv;
                    }
                } else {
                    // q/k: single fp16 plane (q pre-scaled)
                    if (which == 0) { v0 *= QSCALE; v1 *= QSCALE; }
                    unsigned* dst = (which == 0) ? g_qh : g_kh;
                    size_t idx = ((size_t)bhh * TT + t) * 32 + word;
                    dst[idx] = packh2(v0, v1);
                }
            }
        }
    }
}

// Proj: g_y[BT,CC] @ w_proj[CC,CC] + bias -> out
__global__ __launch_bounds__(256, 2) void proj_kernel(const float* __restrict__ W,
                                                      const float* __restrict__ bias,
                                                      float* __restrict__ out) {
    __shared__ __align__(16) unsigned Asu[2 * TSZ];
    __shared__ __align__(16) unsigned Bsu[2 * TSZ];
    int bn0 = blockIdx.x * GBN;
    int bm0 = blockIdx.y * GBM;
    float acc[2][8][4] = {};
    gemm_tile_f16(g_y, CC, W, CC, bm0, bn0, Asu, Bsu, acc);

    int tid = threadIdx.x;
    int wid = tid >> 5, lane = tid & 31;
    int wm = wid & 3, wn = wid >> 2;
    int g = lane >> 2, tig = lane & 3;
#pragma unroll
    for (int jn = 0; jn < 8; jn++) {
        int n0 = bn0 + wn * 64 + jn * 8 + 2 * tig;
        float b0v = bias[n0], b1v = bias[n0 + 1];
#pragma unroll
        for (int im = 0; im < 2; im++) {
            int r0 = bm0 + wm * 32 + im * 16 + g;
#pragma unroll
            for (int half = 0; half < 2; half++) {
                int r = r0 + half * 8;
                float2 v2 = make_float2(acc[im][jn][half * 2 + 0] + b0v,
                                        acc[im][jn][half * 2 + 1] + b1v);
                *(float2*)&out[(size_t)r * CC + n0] = v2;
            }
        }
    }
}

// ---------------- tensor-core flash attention (unchanged from R14) ----------------
#define AKT 64
#define NT (TT / AKT)
#define ARR_B 9216
#define STAGE_B (2 * ARR_B)
#define ATTN_SMEM (2 * STAGE_B)

__device__ __forceinline__ void issue_tile(unsigned sbs,
                                           const unsigned* khg,
                                           const unsigned* vhg,
                                           int kt, int tid) {
    int row0 = tid >> 3;
    int ch4 = (tid & 7) * 4;
    const unsigned* vht = vhg + (size_t)(kt >> 6) * 2048;
#pragma unroll
    for (int hf = 0; hf < 2; hf++) {
        int row = hf * 32 + row0;
        unsigned d = sbs + (unsigned)(row * 36 + ch4) * 4u;
        cp16(d,          khg + (size_t)(kt + row) * 32 + ch4);
        cp16(d + ARR_B,  vht + row * 32 + ch4);
    }
}

__global__ __launch_bounds__(256, 2) void attn_kernel() {
    extern __shared__ __align__(128) char asmem[];
    const unsigned sb = saddr(asmem);

    const int tid = threadIdx.x;
    const int warp = tid >> 5, lane = tid & 31;
    const int g = lane >> 2, tig = lane & 3;
    const int l7 = lane & 7, l3h = lane >> 3;
    const int bh = blockIdx.y;
    const int q0 = blockIdx.x * 128;
    const unsigned* qhg = g_qh + (size_t)bh * TT * 32;
    const unsigned* khg = g_kh + (size_t)bh * TT * 32;
    const unsigned* vhg = g_vh + (size_t)bh * TT * 32;
    const int qrow = q0 + warp * 16 + g;

    unsigned aq[4][4];
#pragma unroll
    for (int kc = 0; kc < 4; kc++) {
        int w = kc * 8 + tig;
        aq[kc][0] = qhg[(size_t)qrow * 32 + w];
        aq[kc][1] = qhg[(size_t)(qrow + 8) * 32 + w];
        aq[kc][2] = qhg[(size_t)qrow * 32 + w + 4];
        aq[kc][3] = qhg[(size_t)(qrow + 8) * 32 + w + 4];
    }

    float o[8][4];
#pragma unroll
    for (int j = 0; j < 8; j++)
#pragma unroll
        for (int i = 0; i < 4; i++) o[j][i] = 0.f;
    float m0 = -1e30f, m1 = -1e30f, l0 = 0.f, l1 = 0.f;

    issue_tile(sb, khg, vhg, 0, tid);
    asm volatile("cp.async.commit_group;" ::: "memory");

    for (int ti = 0; ti < NT; ti++) {
        const int buf = ti & 1;
        if (ti + 1 < NT) {
            issue_tile(sb + (buf ^ 1) * STAGE_B, khg, vhg, (ti + 1) * AKT, tid);
            asm volatile("cp.async.commit_group;" ::: "memory");
            asm volatile("cp.async.wait_group 1;" ::: "memory");
        } else {
            asm volatile("cp.async.wait_group 0;" ::: "memory");
        }
        __syncthreads();

        const unsigned sbK = sb + buf * STAGE_B;
        const unsigned sbV = sbK + ARR_B;

        float sacc[8][4];
#pragma unroll
        for (int j = 0; j < 8; j++) {
#pragma unroll
            for (int i = 0; i < 4; i++) sacc[j][i] = 0.f;
            unsigned rwb = (unsigned)((8 * j + l7) * 36 + 4 * l3h) * 4u;
            unsigned kh[4][2];
            ldsm4(kh[0][0], kh[0][1], kh[1][0], kh[1][1], sbK + rwb);
            ldsm4(kh[2][0], kh[2][1], kh[3][0], kh[3][1], sbK + rwb + 64);
#pragma unroll
            for (int kc = 0; kc < 4; kc++)
                mma_f16(sacc[j], aq[kc], kh[kc]);
        }

        float rm0 = -1e30f, rm1 = -1e30f;
#pragma unroll
        for (int j = 0; j < 8; j++) {
            rm0 = fmaxf(rm0, fmaxf(sacc[j][0], sacc[j][1]));
            rm1 = fmaxf(rm1, fmaxf(sacc[j][2], sacc[j][3]));
        }
        rm0 = fmaxf(rm0, __shfl_xor_sync(0xffffffffu, rm0, 1));
        rm0 = fmaxf(rm0, __shfl_xor_sync(0xffffffffu, rm0, 2));
        rm1 = fmaxf(rm1, __shfl_xor_sync(0xffffffffu, rm1, 1));
        rm1 = fmaxf(rm1, __shfl_xor_sync(0xffffffffu, rm1, 2));
        float nm0 = fmaxf(m0, rm0), nm1 = fmaxf(m1, rm1);
        float cr0 = ex2(m0 - nm0), cr1 = ex2(m1 - nm1);
        m0 = nm0; m1 = nm1;

        unsigned p[4][4];
        float sum0 = 0.f, sum1 = 0.f;
#pragma unroll
        for (int u = 0; u < 4; u++) {
            float p00 = ex2(sacc[2 * u][0] - m0);
            float p01 = ex2(sacc[2 * u][1] - m0);
            float p10 = ex2(sacc[2 * u][2] - m1);
            float p11 = ex2(sacc[2 * u][3] - m1);
            float p20 = ex2(sacc[2 * u + 1][0] - m0);
            float p21 = ex2(sacc[2 * u + 1][1] - m0);
            float p30 = ex2(sacc[2 * u + 1][2] - m1);
            float p31 = ex2(sacc[2 * u + 1][3] - m1);
            sum0 += p00 + p01 + p20 + p21;
            sum1 += p10 + p11 + p30 + p31;
            p[u][0] = packh2(p00, p01);
            p[u][1] = packh2(p10, p11);
            p[u][2] = packh2(p20, p21);
            p[u][3] = packh2(p30, p31);
        }
        sum0 += __shfl_xor_sync(0xffffffffu, sum0, 1);
        sum0 += __shfl_xor_sync(0xffffffffu, sum0, 2);
        sum1 += __shfl_xor_sync(0xffffffffu, sum1, 1);
        sum1 += __shfl_xor_sync(0xffffffffu, sum1, 2);
        l0 = l0 * cr0 + sum0;
        l1 = l1 * cr1 + sum1;
#pragma unroll
        for (int j = 0; j < 8; j++) {
            o[j][0] *= cr0; o[j][1] *= cr0;
            o[j][2] *= cr1; o[j][3] *= cr1;
        }

#pragma unroll
        for (int j = 0; j < 8; j++) {
            int drow = 8 * j + l7;
            int f = 4 * ((drow >> 2) & 7);
            unsigned rbb = (unsigned)(drow * 36) * 4u;
            unsigned c0 = (unsigned)((4 * l3h) ^ f) * 4u;
            unsigned c1 = (unsigned)((16 + 4 * l3h) ^ f) * 4u;
            unsigned vh[4][2];
            ldsm4(vh[0][0], vh[0][1], vh[1][0], vh[1][1], sbV + rbb + c0);
            ldsm4(vh[2][0], vh[2][1], vh[3][0], vh[3][1], sbV + rbb + c1);
#pragma unroll
            for (int u = 0; u < 4; u++)
                mma_f16(o[j], p[u], vh[u]);
        }
        __syncthreads();
    }

    float inv0 = 1.f / l0, inv1 = 1.f / l1;
    int b_ = bh >> 4, h = bh & 15;
    float* y0 = g_y + ((size_t)(b_ * TT + qrow)) * CC + h * HD;
    float* y1 = g_y + ((size_t)(b_ * TT + qrow + 8)) * CC + h * HD;
#pragma unroll
    for (int j = 0; j < 8; j++) {
        *(float2*)&y0[8 * j + 2 * tig] = make_float2(o[j][0] * inv0, o[j][1] * inv0);
        *(float2*)&y1[8 * j + 2 * tig] = make_float2(o[j][2] * inv1, o[j][3] * inv1);
    }
}

extern "C" void kernel_launch(void* const* d_in, const int* in_sizes, int n_in,
                              void* d_out, int out_size) {
    const float* seq    = (const float*)d_in[0];
    const float* w_attn = (const float*)d_in[1];
    const float* b_attn = (const float*)d_in[2];
    const float* w_proj = (const float*)d_in[3];
    const float* b_proj = (const float*)d_in[4];
    float* out = (float*)d_out;

    static int attr_set = 0;
    if (!attr_set) {
        cudaFuncSetAttribute(attn_kernel,
                             cudaFuncAttributeMaxDynamicSharedMemorySize, ATTN_SMEM);
        attr_set = 1;
    }

    dim3 g1(C3 / GBN, BT / GBM);        // 24 x 64
    qkv_kernel<<<g1, 256>>>(seq, w_attn, b_attn);

    dim3 g2(TT / 128, BB * HH);         // 16 x 64
    attn_kernel<<<g2, 256, ATTN_SMEM>>>();

    dim3 g3(CC / GBN, BT / GBM);        // 8 x 64
    proj_kernel<<<g3, 256>>>(w_proj, b_proj, out);
}

// round 17
// speedup vs baseline: 6.6124x; 1.0312x over previous
#include <cuda_runtime.h>
#include <cuda_bf16.h>
#include <cuda_fp16.h>
#include <math.h>

#define BB 4
#define TT 2048
#define CC 1024
#define HH 16
#define HD 64
#define BT (BB*TT)
#define C3 (3*CC)
#define CW (CC/2)        // fp16 words per length-CC row

// q pre-scale: (1/sqrt(64)) * log2(e), folded in at qkv epilogue
#define QSCALE 0.18033688011112042f

// Scratch (device globals: allocation-guard safe)
__device__ unsigned g_x16[BT*CW];    // seq as fp16, [m][k]
__device__ unsigned g_wat[C3*CW];    // w_attn^T fp16, [n][k]
__device__ unsigned g_wpt[CC*CW];    // w_proj^T fp16, [n][k]
__device__ unsigned g_y16[BT*CW];    // attention output fp16, [m][c]
__device__ unsigned g_qh[BB*HH*TT*32];
__device__ unsigned g_kh[BB*HH*TT*32];
__device__ unsigned g_vh[BB*HH*TT*32];   // fp16, tile-transposed

// ---------------- common helpers ----------------
__device__ __forceinline__ void mma_f16(float* c, const unsigned* a, const unsigned* b) {
    asm volatile(
        "mma.sync.aligned.m16n8k16.row.col.f32.f16.f16.f32 "
        "{%0,%1,%2,%3}, {%4,%5,%6,%7}, {%8,%9}, {%0,%1,%2,%3};"
        : "+f"(c[0]), "+f"(c[1]), "+f"(c[2]), "+f"(c[3])
        : "r"(a[0]), "r"(a[1]), "r"(a[2]), "r"(a[3]), "r"(b[0]), "r"(b[1]));
}

__device__ __forceinline__ unsigned packh2(float a0, float a1) {
    unsigned r;
    asm("cvt.rn.f16x2.f32 %0, %1, %2;" : "=r"(r) : "f"(a1), "f"(a0));
    return r;
}

__device__ __forceinline__ unsigned saddr(const void* p) {
    return (unsigned)__cvta_generic_to_shared(p);
}

__device__ __forceinline__ void ldsm4(unsigned& r0, unsigned& r1, unsigned& r2,
                                      unsigned& r3, unsigned a) {
    asm volatile("ldmatrix.sync.aligned.m8n8.x4.shared.b16 {%0,%1,%2,%3}, [%4];"
                 : "=r"(r0), "=r"(r1), "=r"(r2), "=r"(r3) : "r"(a));
}

__device__ __forceinline__ float ex2(float x) {
    float r;
    asm("ex2.approx.f32 %0, %1;" : "=f"(r) : "f"(x));
    return r;
}

__device__ __forceinline__ void cp16(unsigned dst, const void* src) {
    asm volatile("cp.async.cg.shared.global [%0], [%1], 16;"
                 :: "r"(dst), "l"(src) : "memory");
}

// ---------------- prep kernels (run once per call; bit-identical values) ----------------
// seq fp32 -> fp16 words
__global__ __launch_bounds__(256) void cvt_seq_kernel(const float4* __restrict__ in) {
    size_t i = (size_t)blockIdx.x * 256 + threadIdx.x;
    float4 v = in[i];
    uint2 w;
    w.x = packh2(v.x, v.y);
    w.y = packh2(v.z, v.w);
    *(uint2*)&g_x16[2 * i] = w;
}

// W[K][N] fp32 -> Wt[N][K] fp16 words (tiled transpose)
__global__ __launch_bounds__(256) void cvt_wT_kernel(const float* __restrict__ W,
                                                     unsigned* __restrict__ Wt,
                                                     int K, int N) {
    __shared__ float s[32][33];
    int n0 = blockIdx.x * 32, k0 = blockIdx.y * 32;
    int tid = threadIdx.x;
#pragma unroll
    for (int it = 0; it < 4; it++) {
        int idx = it * 256 + tid;
        int kk = idx >> 5, nn = idx & 31;
        s[kk][nn] = W[(size_t)(k0 + kk) * N + n0 + nn];
    }
    __syncthreads();
#pragma unroll
    for (int it = 0; it < 2; it++) {
        int idx = it * 256 + tid;
        int nn = idx >> 4, kw = idx & 15;
        Wt[(size_t)(n0 + nn) * (K >> 1) + (k0 >> 1) + kw] =
            packh2(s[2 * kw][nn], s[2 * kw + 1][nn]);
    }
}

// ---------------- fp16 GEMM: cp.async 3-stage ring ----------------
// Both operands pre-converted fp16, [row][k] with k contiguous (CW words/row).
// Smem tiles stride-12 words (R15-verified conflict-free fragment layout).
#define ST 12
#define TSZ (128 * ST)           // words per tile per stage
#define NSTG (CC / 16)           // 64 k-stages

__device__ __forceinline__ void g_issue(unsigned sbs,
                                        const unsigned* Ag, const unsigned* Bg,
                                        int bm0, int bn0, int kw0, int tid) {
    int m = tid >> 1, hf = tid & 1;
    unsigned d = sbs + (unsigned)(m * ST + hf * 4) * 4u;
    cp16(d,            Ag + (size_t)(bm0 + m) * CW + kw0 + hf * 4);
    cp16(d + TSZ * 4,  Bg + (size_t)(bn0 + m) * CW + kw0 + hf * 4);
}

__device__ __forceinline__ void gemm_tile_f16(const unsigned* Ag, const unsigned* Bg,
                                              int bm0, int bn0, unsigned* Ssu,
                                              float acc[2][8][4]) {
    int tid = threadIdx.x;
    int wid = tid >> 5, lane = tid & 31;
    int wm = wid & 3, wn = wid >> 2;
    int g = lane >> 2, tig = lane & 3;
    int mi = lane >> 3, r8 = lane & 7;
    int ldsm_off = (r8 + 8 * (mi >> 1)) * ST + (mi & 1) * 4;
    unsigned sb = saddr(Ssu);

    g_issue(sb, Ag, Bg, bm0, bn0, 0, tid);
    asm volatile("cp.async.commit_group;" ::: "memory");
    g_issue(sb + 2 * TSZ * 4, Ag, Bg, bm0, bn0, 8, tid);
    asm volatile("cp.async.commit_group;" ::: "memory");

    int buf = 0;
    for (int s = 0; s < NSTG; s++) {
        if (s + 2 < NSTG) asm volatile("cp.async.wait_group 1;" ::: "memory");
        else              asm volatile("cp.async.wait_group 0;" ::: "memory");
        __syncthreads();
        if (s + 2 < NSTG) {
            int nb = buf + 2; if (nb >= 3) nb -= 3;
            g_issue(sb + (unsigned)(nb * 2 * TSZ) * 4u, Ag, Bg, bm0, bn0,
                    (s + 2) * 8, tid);
            asm volatile("cp.async.commit_group;" ::: "memory");
        }
        const unsigned* Ac = Ssu + buf * 2 * TSZ;
        unsigned bb = sb + (unsigned)(buf * 2 * TSZ + TSZ) * 4u;

        unsigned a_frag[2][4];
#pragma unroll
        for (int im = 0; im < 2; im++) {
            int rm = wm * 32 + im * 16 + g;
            a_frag[im][0] = Ac[rm * ST + tig];
            a_frag[im][1] = Ac[(rm + 8) * ST + tig];
            a_frag[im][2] = Ac[rm * ST + tig + 4];
            a_frag[im][3] = Ac[(rm + 8) * ST + tig + 4];
        }
        unsigned b_frag[8][2];
#pragma unroll
        for (int jp = 0; jp < 4; jp++) {
            int nb = wn * 64 + jp * 16;
            unsigned addr = bb + (unsigned)(nb * ST + ldsm_off) * 4u;
            ldsm4(b_frag[2 * jp][0], b_frag[2 * jp][1],
                  b_frag[2 * jp + 1][0], b_frag[2 * jp + 1][1], addr);
        }
#pragma unroll
        for (int im = 0; im < 2; im++)
#pragma unroll
            for (int jn = 0; jn < 8; jn++)
                mma_f16(acc[im][jn], a_frag[im], b_frag[jn]);

        buf++; if (buf == 3) buf = 0;
    }
}

// QKV: g_x16 @ g_wat^T + bias -> q/k fp16 planes (q pre-scaled); v fp16 tile-transposed
__global__ __launch_bounds__(256, 2) void qkv_kernel(const float* __restrict__ bias) {
    __shared__ __align__(16) unsigned Ssu[3 * 2 * TSZ];
    int bn0 = blockIdx.x * 128;
    int bm0 = blockIdx.y * 128;
    float acc[2][8][4] = {};
    gemm_tile_f16(g_x16, g_wat, bm0, bn0, Ssu, acc);

    int tid = threadIdx.x;
    int wid = tid >> 5, lane = tid & 31;
    int wm = wid & 3, wn = wid >> 2;
    int g = lane >> 2, tig = lane & 3;
#pragma unroll
    for (int jn = 0; jn < 8; jn++) {
        int n0 = bn0 + wn * 64 + jn * 8 + 2 * tig;    // even -> d-pair aligned
        int which = n0 / CC;
        int nl = n0 % CC;
        int h = nl / HD;
        int word = (nl % HD) >> 1;
        float b0v = bias[n0], b1v = bias[n0 + 1];
#pragma unroll
        for (int im = 0; im < 2; im++) {
            int r0 = bm0 + wm * 32 + im * 16 + g;
#pragma unroll
            for (int half = 0; half < 2; half++) {
                int r = r0 + half * 8;
                int b_ = r / TT, t = r % TT;
                int bhh = b_ * HH + h;
                float v0 = acc[im][jn][half * 2 + 0] + b0v;
                float v1 = acc[im][jn][half * 2 + 1] + b1v;
                if (which == 2) {
                    unsigned hi = packh2(v0, v1);
                    int tile = t >> 6, kq = (t & 63) >> 1, hk = t & 1;
                    size_t base = ((size_t)bhh * 32 + tile) * 64;
                    int d0v = word * 2;
#pragma unroll
                    for (int e = 0; e < 2; e++) {
                        int d = d0v + e;
                        int col = kq ^ (4 * ((d >> 2) & 7));
                        size_t w = (base + d) * 32 + col;
                        unsigned short hv = e ? (unsigned short)(hi >> 16)
                                              : (unsigned short)(hi & 0xffffu);
                        ((unsigned short*)g_vh)[w * 2 + hk] = hv;
                    }
                } else {
                    if (which == 0) { v0 *= QSCALE; v1 *= QSCALE; }
                    unsigned* dst = (which == 0) ? g_qh : g_kh;
                    size_t idx = ((size_t)bhh * TT + t) * 32 + word;
                    dst[idx] = packh2(v0, v1);
                }
            }
        }
    }
}

// Proj: g_y16 @ g_wpt^T + bias -> out (fp32)
__global__ __launch_bounds__(256, 2) void proj_kernel(const float* __restrict__ bias,
                                                      float* __restrict__ out) {
    __shared__ __align__(16) unsigned Ssu[3 * 2 * TSZ];
    int bn0 = blockIdx.x * 128;
    int bm0 = blockIdx.y * 128;
    float acc[2][8][4] = {};
    gemm_tile_f16(g_y16, g_wpt, bm0, bn0, Ssu, acc);

    int tid = threadIdx.x;
    int wid = tid >> 5, lane = tid & 31;
    int wm = wid & 3, wn = wid >> 2;
    int g = lane >> 2, tig = lane & 3;
#pragma unroll
    for (int jn = 0; jn < 8; jn++) {
        int n0 = bn0 + wn * 64 + jn * 8 + 2 * tig;
        float b0v = bias[n0], b1v = bias[n0 + 1];
#pragma unroll
        for (int im = 0; im < 2; im++) {
            int r0 = bm0 + wm * 32 + im * 16 + g;
#pragma unroll
            for (int half = 0; half < 2; half++) {
                int r = r0 + half * 8;
                float2 v2 = make_float2(acc[im][jn][half * 2 + 0] + b0v,
                                        acc[im][jn][half * 2 + 1] + b1v);
                *(float2*)&out[(size_t)r * CC + n0] = v2;
            }
        }
    }
}

// ---------------- tensor-core flash attention (R14/R15, epilogue -> fp16 y) ----------------
#define AKT 64
#define NT (TT / AKT)
#define ARR_B 9216
#define STAGE_B (2 * ARR_B)
#define ATTN_SMEM (2 * STAGE_B)

__device__ __forceinline__ void issue_tile(unsigned sbs,
                                           const unsigned* khg,
                                           const unsigned* vhg,
                                           int kt, int tid) {
    int row0 = tid >> 3;
    int ch4 = (tid & 7) * 4;
    const unsigned* vht = vhg + (size_t)(kt >> 6) * 2048;
#pragma unroll
    for (int hf = 0; hf < 2; hf++) {
        int row = hf * 32 + row0;
        unsigned d = sbs + (unsigned)(row * 36 + ch4) * 4u;
        cp16(d,          khg + (size_t)(kt + row) * 32 + ch4);
        cp16(d + ARR_B,  vht + row * 32 + ch4);
    }
}

__global__ __launch_bounds__(256, 2) void attn_kernel() {
    extern __shared__ __align__(128) char asmem[];
    const unsigned sb = saddr(asmem);

    const int tid = threadIdx.x;
    const int warp = tid >> 5, lane = tid & 31;
    const int g = lane >> 2, tig = lane & 3;
    const int l7 = lane & 7, l3h = lane >> 3;
    const int bh = blockIdx.y;
    const int q0 = blockIdx.x * 128;
    const unsigned* qhg = g_qh + (size_t)bh * TT * 32;
    const unsigned* khg = g_kh + (size_t)bh * TT * 32;
    const unsigned* vhg = g_vh + (size_t)bh * TT * 32;
    const int qrow = q0 + warp * 16 + g;

    unsigned aq[4][4];
#pragma unroll
    for (int kc = 0; kc < 4; kc++) {
        int w = kc * 8 + tig;
        aq[kc][0] = qhg[(size_t)qrow * 32 + w];
        aq[kc][1] = qhg[(size_t)(qrow + 8) * 32 + w];
        aq[kc][2] = qhg[(size_t)qrow * 32 + w + 4];
        aq[kc][3] = qhg[(size_t)(qrow + 8) * 32 + w + 4];
    }

    float o[8][4];
#pragma unroll
    for (int j = 0; j < 8; j++)
#pragma unroll
        for (int i = 0; i < 4; i++) o[j][i] = 0.f;
    float m0 = -1e30f, m1 = -1e30f, l0 = 0.f, l1 = 0.f;

    issue_tile(sb, khg, vhg, 0, tid);
    asm volatile("cp.async.commit_group;" ::: "memory");

    for (int ti = 0; ti < NT; ti++) {
        const int buf = ti & 1;
        if (ti + 1 < NT) {
            issue_tile(sb + (buf ^ 1) * STAGE_B, khg, vhg, (ti + 1) * AKT, tid);
            asm volatile("cp.async.commit_group;" ::: "memory");
            asm volatile("cp.async.wait_group 1;" ::: "memory");
        } else {
            asm volatile("cp.async.wait_group 0;" ::: "memory");
        }
        __syncthreads();

        const unsigned sbK = sb + buf * STAGE_B;
        const unsigned sbV = sbK + ARR_B;

        float sacc[8][4];
#pragma unroll
        for (int j = 0; j < 8; j++) {
#pragma unroll
            for (int i = 0; i < 4; i++) sacc[j][i] = 0.f;
            unsigned rwb = (unsigned)((8 * j + l7) * 36 + 4 * l3h) * 4u;
            unsigned kh[4][2];
            ldsm4(kh[0][0], kh[0][1], kh[1][0], kh[1][1], sbK + rwb);
            ldsm4(kh[2][0], kh[2][1], kh[3][0], kh[3][1], sbK + rwb + 64);
#pragma unroll
            for (int kc = 0; kc < 4; kc++)
                mma_f16(sacc[j], aq[kc], kh[kc]);
        }

        float rm0 = -1e30f, rm1 = -1e30f;
#pragma unroll
        for (int j = 0; j < 8; j++) {
            rm0 = fmaxf(rm0, fmaxf(sacc[j][0], sacc[j][1]));
            rm1 = fmaxf(rm1, fmaxf(sacc[j][2], sacc[j][3]));
        }
        rm0 = fmaxf(rm0, __shfl_xor_sync(0xffffffffu, rm0, 1));
        rm0 = fmaxf(rm0, __shfl_xor_sync(0xffffffffu, rm0, 2));
        rm1 = fmaxf(rm1, __shfl_xor_sync(0xffffffffu, rm1, 1));
        rm1 = fmaxf(rm1, __shfl_xor_sync(0xffffffffu, rm1, 2));
        float nm0 = fmaxf(m0, rm0), nm1 = fmaxf(m1, rm1);
        float cr0 = ex2(m0 - nm0), cr1 = ex2(m1 - nm1);
        m0 = nm0; m1 = nm1;

        unsigned p[4][4];
        float sum0 = 0.f, sum1 = 0.f;
#pragma unroll
        for (int u = 0; u < 4; u++) {
            float p00 = ex2(sacc[2 * u][0] - m0);
            float p01 = ex2(sacc[2 * u][1] - m0);
            float p10 = ex2(sacc[2 * u][2] - m1);
            float p11 = ex2(sacc[2 * u][3] - m1);
            float p20 = ex2(sacc[2 * u + 1][0] - m0);
            float p21 = ex2(sacc[2 * u + 1][1] - m0);
            float p30 = ex2(sacc[2 * u + 1][2] - m1);
            float p31 = ex2(sacc[2 * u + 1][3] - m1);
            sum0 += p00 + p01 + p20 + p21;
            sum1 += p10 + p11 + p30 + p31;
            p[u][0] = packh2(p00, p01);
            p[u][1] = packh2(p10, p11);
            p[u][2] = packh2(p20, p21);
            p[u][3] = packh2(p30, p31);
        }
        sum0 += __shfl_xor_sync(0xffffffffu, sum0, 1);
        sum0 += __shfl_xor_sync(0xffffffffu, sum0, 2);
        sum1 += __shfl_xor_sync(0xffffffffu, sum1, 1);
        sum1 += __shfl_xor_sync(0xffffffffu, sum1, 2);
        l0 = l0 * cr0 + sum0;
        l1 = l1 * cr1 + sum1;
#pragma unroll
        for (int j = 0; j < 8; j++) {
            o[j][0] *= cr0; o[j][1] *= cr0;
            o[j][2] *= cr1; o[j][3] *= cr1;
        }

#pragma unroll
        for (int j = 0; j < 8; j++) {
            int drow = 8 * j + l7;
            int f = 4 * ((drow >> 2) & 7);
            unsigned rbb = (unsigned)(drow * 36) * 4u;
            unsigned c0 = (unsigned)((4 * l3h) ^ f) * 4u;
            unsigned c1 = (unsigned)((16 + 4 * l3h) ^ f) * 4u;
            unsigned vh[4][2];
            ldsm4(vh[0][0], vh[0][1], vh[1][0], vh[1][1], sbV + rbb + c0);
            ldsm4(vh[2][0], vh[2][1], vh[3][0], vh[3][1], sbV + rbb + c1);
#pragma unroll
            for (int u = 0; u < 4; u++)
                mma_f16(o[j], p[u], vh[u]);
        }
        __syncthreads();
    }

    // ---- epilogue: write y directly as fp16 words ----
    float inv0 = 1.f / l0, inv1 = 1.f / l1;
    int b_ = bh >> 4, h = bh & 15;
    unsigned* y0 = g_y16 + (size_t)(b_ * TT + qrow) * CW + (h * HD) / 2;
    unsigned* y1 = g_y16 + (size_t)(b_ * TT + qrow + 8) * CW + (h * HD) / 2;
#pragma unroll
    for (int j = 0; j < 8; j++) {
        y0[4 * j + tig] = packh2(o[j][0] * inv0, o[j][1] * inv0);
        y1[4 * j + tig] = packh2(o[j][2] * inv1, o[j][3] * inv1);
    }
}

extern "C" void kernel_launch(void* const* d_in, const int* in_sizes, int n_in,
                              void* d_out, int out_size) {
    const float* seq    = (const float*)d_in[0];
    const float* w_attn = (const float*)d_in[1];
    const float* b_attn = (const float*)d_in[2];
    const float* w_proj = (const float*)d_in[3];
    const float* b_proj = (const float*)d_in[4];
    float* out = (float*)d_out;

    static int attr_set = 0;
    if (!attr_set) {
        cudaFuncSetAttribute(attn_kernel,
                             cudaFuncAttributeMaxDynamicSharedMemorySize, ATTN_SMEM);
        attr_set = 1;
    }

    // prep: fp16 conversions + weight transposes (bit-identical to in-loop cvt)
    cvt_seq_kernel<<<BT * CC / 4 / 256, 256>>>((const float4*)seq);
    unsigned* d_wat; cudaGetSymbolAddress((void**)&d_wat, g_wat);
    unsigned* d_wpt; cudaGetSymbolAddress((void**)&d_wpt, g_wpt);
    cvt_wT_kernel<<<dim3(C3 / 32, CC / 32), 256>>>(w_attn, d_wat, CC, C3);
    cvt_wT_kernel<<<dim3(CC / 32, CC / 32), 256>>>(w_proj, d_wpt, CC, CC);

    dim3 g1(C3 / 128, BT / 128);        // 24 x 64
    qkv_kernel<<<g1, 256>>>(b_attn);

    dim3 g2(TT / 128, BB * HH);         // 16 x 64
    attn_kernel<<<g2, 256, ATTN_SMEM>>>();

    dim3 g3(CC / 128, BT / 128);        // 8 x 64
    proj_kernel<<<g3, 256>>>(b_proj, out);
}